// round 9
// baseline (speedup 1.0000x reference)
#include <cuda_runtime.h>
#include <math.h>
#include <cfloat>

#ifndef M_PI
#define M_PI 3.14159265358979323846
#endif

typedef unsigned long long u64;

#define NPIX 10000      // 100*100
#define SIDE 100
#define SS   200
#define KH   101        // rfft half-width
#define RR   360
#define NB   2
#define NIMG (NB*RR)    // 720
#define SPEC (SS*KH)    // 20200
#define EPSF 1e-12f
#define T1PITCH 201
#define SPITCH  105

// ---------------- static device scratch ----------------
__device__ float  d_h1[4*9*NPIX];
__device__ float  d_feat[4*2*NPIX];
__device__ float  d_rot[NIMG*2*NPIX];
__device__ float2 d_rf[4*SPEC];            // [q][k2*200 + k1]
__device__ float2 d_G[4*SPEC];             // [q][k2*200 + k1]
__device__ float2 d_SF[NIMG*SPEC];         // [img][k2*200 + k1]
__device__ float2 d_Binv[NIMG*SPEC];       // [img][k2*200 + y]
__device__ float  d_blockmax[NIMG];
__device__ float  d_pos[NB];
__device__ float2 d_rtrig[RR];
__device__ u64        d_tw1f[SS];          // (c, -s)         fwd stage1
__device__ u64        d_tw1i[SS];          // (c,  s)         ifft2
__device__ ulonglong2 d_tw2f[SS];          // ((c,-s),(-s,c)) fwd stage2
__device__ ulonglong2 d_tw2i[SS];          // ((c, s),( s,c)) ifft1

// ---------------- packed f32x2 helpers ----------------
__device__ __forceinline__ u64 pk2(float a, float b){
    u64 r; asm("mov.b64 %0, {%1, %2};" : "=l"(r) : "f"(a), "f"(b)); return r;
}
__device__ __forceinline__ float2 up2(u64 v){
    float2 r; asm("mov.b64 {%0, %1}, %2;" : "=f"(r.x), "=f"(r.y) : "l"(v)); return r;
}
__device__ __forceinline__ u64 ffma2(u64 a, u64 b, u64 c){
    u64 d; asm("fma.rn.f32x2 %0, %1, %2, %3;" : "=l"(d) : "l"(a), "l"(b), "l"(c)); return d;
}

// ---------------- init tables ----------------
__global__ void k_init(){
    int t = threadIdx.x;
    if (t < SS){
        double th = 2.0 * M_PI * (double)t / 200.0;
        float c = (float)cos(th), s = (float)sin(th);
        d_tw1f[t] = pk2(c, -s);
        d_tw1i[t] = pk2(c,  s);
        d_tw2f[t] = make_ulonglong2(pk2(c, -s), pk2(-s, c));
        d_tw2i[t] = make_ulonglong2(pk2(c,  s), pk2( s, c));
    }
    if (t < RR){
        double th = -M_PI + (double)t * (2.0 * M_PI / 360.0);
        d_rtrig[t] = make_float2((float)cos(th), (float)sin(th));
    }
}

// ---------------- conv1 + field norm ----------------
__global__ void k_conv1(const float* __restrict__ rec, const float* __restrict__ lig,
                        const float* __restrict__ w1){
    int idx = blockIdx.x*blockDim.x + threadIdx.x;
    if (idx >= 4*NPIX) return;
    int t = idx / NPIX, p = idx % NPIX;
    int y = p / SIDE, x = p % SIDE;
    const float* src = (t < 2) ? rec + t*NPIX : lig + (t-2)*NPIX;
    float acc[9];
#pragma unroll
    for (int o = 0; o < 9; o++) acc[o] = 0.f;
    for (int dy = 0; dy < 5; dy++){
        int yy = y + dy - 2; if (yy < 0 || yy >= SIDE) continue;
        for (int dx = 0; dx < 5; dx++){
            int xx = x + dx - 2; if (xx < 0 || xx >= SIDE) continue;
            float v = src[yy*SIDE + xx];
#pragma unroll
            for (int o = 0; o < 9; o++) acc[o] = fmaf(w1[o*25 + dy*5 + dx], v, acc[o]);
        }
    }
    float out[9];
    { float n = sqrtf(acc[0]*acc[0] + EPSF); out[0] = acc[0] * (n/(n+EPSF)); }
#pragma unroll
    for (int g = 0; g < 4; g++){
        int a = 1 + 2*g;
        float n = sqrtf(acc[a]*acc[a] + acc[a+1]*acc[a+1] + EPSF);
        float s = n/(n+EPSF);
        out[a] = acc[a]*s; out[a+1] = acc[a+1]*s;
    }
#pragma unroll
    for (int o = 0; o < 9; o++) d_h1[(t*9 + o)*NPIX + p] = out[o];
}

// ---------------- conv2 + field norm + features ----------------
__global__ void k_conv2(const float* __restrict__ w2){
    int idx = blockIdx.x*blockDim.x + threadIdx.x;
    if (idx >= 4*NPIX) return;
    int t = idx / NPIX, p = idx % NPIX;
    int y = p / SIDE, x = p % SIDE;
    float h[3] = {0.f, 0.f, 0.f};
    for (int ic = 0; ic < 9; ic++){
        const float* base = d_h1 + (t*9 + ic)*NPIX;
        for (int dy = 0; dy < 5; dy++){
            int yy = y + dy - 2; if (yy < 0 || yy >= SIDE) continue;
            for (int dx = 0; dx < 5; dx++){
                int xx = x + dx - 2; if (xx < 0 || xx >= SIDE) continue;
                float v = base[yy*SIDE + xx];
#pragma unroll
                for (int oc = 0; oc < 3; oc++)
                    h[oc] = fmaf(w2[(oc*9 + ic)*25 + dy*5 + dx], v, h[oc]);
            }
        }
    }
    float n0 = sqrtf(h[0]*h[0] + EPSF);
    float o0 = h[0] * (n0/(n0+EPSF));
    float n1 = sqrtf(h[1]*h[1] + h[2]*h[2] + EPSF);
    float s  = n1/(n1+EPSF);
    float o1 = h[1]*s, o2 = h[2]*s;
    d_feat[(t*2 + 0)*NPIX + p] = fabsf(o0);
    d_feat[(t*2 + 1)*NPIX + p] = sqrtf(o1*o1 + o2*o2 + EPSF);
}

// ---------------- bilinear rotation ----------------
__global__ void k_rot(){
    int idx = blockIdx.x*blockDim.x + threadIdx.x;
    if (idx >= NIMG*NPIX) return;
    int img = idx / NPIX, p = idx % NPIX;
    int b = img / RR, r = img % RR;
    int i = p / SIDE, j = p % SIDE;
    float2 cs = d_rtrig[r];
    float ct = cs.x, st = cs.y;
    const float c = 49.5f;
    float xs = (float)j - c, ys = (float)i - c;
    float xq =  ct*xs + st*ys + c;
    float yq = -st*xs + ct*ys + c;
    float x0f = floorf(xq), y0f = floorf(yq);
    float wx = xq - x0f, wy = yq - y0f;
    int x0 = (int)x0f, y0 = (int)y0f;
    float w00 = (1.f-wy)*(1.f-wx), w01 = (1.f-wy)*wx;
    float w10 = wy*(1.f-wx),       w11 = wy*wx;
    bool vx0 = (x0 >= 0 && x0 < SIDE), vx1 = (x0+1 >= 0 && x0+1 < SIDE);
    bool vy0 = (y0 >= 0 && y0 < SIDE), vy1 = (y0+1 >= 0 && y0+1 < SIDE);
    int cx0 = min(max(x0, 0), SIDE-1),   cx1 = min(max(x0+1, 0), SIDE-1);
    int cy0 = min(max(y0, 0), SIDE-1),   cy1 = min(max(y0+1, 0), SIDE-1);
#pragma unroll
    for (int ch = 0; ch < 2; ch++){
        const float* base = d_feat + ((2 + b)*2 + ch)*NPIX;
        float g00 = (vy0 && vx0) ? base[cy0*SIDE + cx0] : 0.f;
        float g01 = (vy0 && vx1) ? base[cy0*SIDE + cx1] : 0.f;
        float g10 = (vy1 && vx0) ? base[cy1*SIDE + cx0] : 0.f;
        float g11 = (vy1 && vx1) ? base[cy1*SIDE + cx1] : 0.f;
        d_rot[(img*2 + ch)*NPIX + p] = g00*w00 + g01*w01 + g10*w10 + g11*w11;
    }
}

// ---------------- forward rfft2 (packed FFMA2, twiddle-table broadcast) ----------------
// lig_mode=0: grid 2 blocks (b); writes d_rf[q = b*2+ch]
// lig_mode=1: grid 720 blocks (img); writes/accumulates d_SF via d_G
__global__ void __launch_bounds__(512, 1) k_fwd(int lig_mode){
    extern __shared__ char sm[];
    ulonglong2* s_tw2 = (ulonglong2*)sm;              // 3200 B
    u64*        s_tw1 = (u64*)(sm + 3200);            // 1600 B
    float*      s_img = (float*)(sm + 4800);          // 40000 B
    float2*     s_T1  = (float2*)(sm + 44800);        // 100*201*8 = 160800 B
    int tid = threadIdx.x, lane = tid & 31, warp = tid >> 5;
    int img = blockIdx.x;
    int b = lig_mode ? (img / RR) : img;

    for (int i = tid; i < SS; i += 512){ s_tw1[i] = d_tw1f[i]; s_tw2[i] = d_tw2f[i]; }

    for (int ch = 0; ch < 2; ch++){
        const float* src = lig_mode ? (d_rot + (img*2 + ch)*NPIX)
                                    : (d_feat + (img*2 + ch)*NPIX);
        for (int i = tid; i < NPIX; i += 512) s_img[i] = src[i];
        __syncthreads();

        // stage 1: T1[k1][x] = sum_y img[y][x] * e^{-2pi i k1 y /200}; stored [x][k1]
        for (int tile = warp; tile < 50; tile += 16){
            int k1b = tile * 4;
            u64 acc[4][4];
#pragma unroll
            for (int j = 0; j < 4; j++)
#pragma unroll
                for (int m = 0; m < 4; m++) acc[j][m] = 0ull;
            int idx[4] = {0, 0, 0, 0};
            for (int y = 0; y < 100; y++){
                const float* row = s_img + y*SIDE;
                float v0 = row[lane], v1 = row[lane+32], v2 = row[lane+64];
                float v3 = (lane < 4) ? row[lane+96] : 0.f;
                u64 V[4] = {pk2(v0,v0), pk2(v1,v1), pk2(v2,v2), pk2(v3,v3)};
#pragma unroll
                for (int j = 0; j < 4; j++){
                    u64 w = s_tw1[idx[j]];
#pragma unroll
                    for (int m = 0; m < 4; m++) acc[j][m] = ffma2(V[m], w, acc[j][m]);
                    idx[j] += k1b + j; if (idx[j] >= 200) idx[j] -= 200;
                }
            }
#pragma unroll
            for (int j = 0; j < 4; j++)
#pragma unroll
                for (int m = 0; m < 4; m++){
                    if (m < 3 || lane < 4){
                        int x = lane + 32*m;
                        s_T1[x*T1PITCH + k1b + j] = up2(acc[j][m]);
                    }
                }
        }
        __syncthreads();

        // stage 2: C[k1][k2] = sum_x T1[k1][x] * e^{-2pi i k2 x /200}
        float2* gout = lig_mode ? (d_SF + img*SPEC) : (d_rf + (img*2 + ch)*SPEC);
        const float2* gG = lig_mode ? (d_G + (b*2 + ch)*SPEC) : (const float2*)0;
        for (int u = warp; u < 104; u += 16){
            int k2t = u >> 2, pass = u & 3;
            int k2b = k2t * 4;
            int k1m0 = pass*64 + lane, k1m1 = k1m0 + 32;
            bool va0 = k1m0 < 200, va1 = k1m1 < 200;
            int k1c0 = min(k1m0, 199), k1c1 = min(k1m1, 199);
            u64 P1[4][2], P2[4][2];
#pragma unroll
            for (int j = 0; j < 4; j++){ P1[j][0]=0ull; P1[j][1]=0ull; P2[j][0]=0ull; P2[j][1]=0ull; }
            int idx[4] = {0, 0, 0, 0};
            for (int x = 0; x < 100; x++){
                float2 t0 = s_T1[x*T1PITCH + k1c0];
                float2 t1 = s_T1[x*T1PITCH + k1c1];
                u64 Tx0 = pk2(t0.x, t0.x), Ty0 = pk2(t0.y, t0.y);
                u64 Tx1 = pk2(t1.x, t1.x), Ty1 = pk2(t1.y, t1.y);
#pragma unroll
                for (int j = 0; j < 4; j++){
                    ulonglong2 wv = s_tw2[idx[j]];
                    P1[j][0] = ffma2(Tx0, wv.x, P1[j][0]);
                    P2[j][0] = ffma2(Ty0, wv.y, P2[j][0]);
                    P1[j][1] = ffma2(Tx1, wv.x, P1[j][1]);
                    P2[j][1] = ffma2(Ty1, wv.y, P2[j][1]);
                    idx[j] += k2b + j; if (idx[j] >= 200) idx[j] -= 200;
                }
            }
#pragma unroll
            for (int j = 0; j < 4; j++){
                int k2 = k2b + j;
                if (k2 >= KH) continue;
#pragma unroll
                for (int m = 0; m < 2; m++){
                    bool va = (m == 0) ? va0 : va1;
                    if (!va) continue;
                    int k1 = (m == 0) ? k1m0 : k1m1;
                    float2 p1 = up2(P1[j][m]), p2 = up2(P2[j][m]);
                    float2 C = make_float2(p1.x - p2.x, p1.y + p2.y);
                    int o = k2*200 + k1;
                    if (lig_mode){
                        float2 g = gG[o];
                        float2 v = make_float2(C.x*g.x - C.y*g.y, C.x*g.y + C.y*g.x);
                        if (ch == 0) gout[o] = v;
                        else { float2 pv = gout[o]; gout[o] = make_float2(pv.x + v.x, pv.y + v.y); }
                    } else {
                        gout[o] = C;
                    }
                }
            }
        }
        __threadfence_block();
        __syncthreads();
    }
}

// ---------------- combine coefficients ----------------
__global__ void k_gcoef(const float* __restrict__ bW, const float* __restrict__ c1,
                        const float* __restrict__ c2, const float* __restrict__ bu){
    int idx = blockIdx.x*blockDim.x + threadIdx.x;
    if (idx >= NB*SPEC) return;
    int b = idx / SPEC, i = idx % SPEC;
    float2 rb = d_rf[(b*2 + 0)*SPEC + i];
    float2 rB = d_rf[(b*2 + 1)*SPEC + i];
    float2 crb = make_float2(rb.x, -rb.y);
    float2 crB = make_float2(rB.x, -rB.y);
    float wb = bW[0], wc1 = c1[0], wc2 = c2[0], wk = bu[0];
    d_G[(b*2 + 0)*SPEC + i] = make_float2(wb*crb.x + wc2*crB.x,  wb*crb.y + wc2*crB.y);
    d_G[(b*2 + 1)*SPEC + i] = make_float2(wc1*crb.x - wk*crB.x,  wc1*crb.y - wk*crB.y);
}

// ---------------- inverse stage 1 over k1 (packed) ----------------
// Binv[k2][y] = scale(k2) * sum_k1 SF[k2][k1] * e^{+2pi i k1 y /200}
__global__ void __launch_bounds__(512, 1) k_ifft1(){
    extern __shared__ char sm[];
    ulonglong2* s_tw2 = (ulonglong2*)sm;            // 3200 B
    float2*     s_S   = (float2*)(sm + 3200);       // 200*105*8 = 168000 B, [k1][k2]
    int tid = threadIdx.x, lane = tid & 31, warp = tid >> 5;
    int img = blockIdx.x;
    const float2* src = d_SF + img*SPEC;
    for (int i = tid; i < SS; i += 512) s_tw2[i] = d_tw2i[i];
    for (int i = tid; i < SPEC; i += 512){
        int k2 = i / 200, k1 = i - k2*200;
        s_S[k1*SPITCH + k2] = src[i];
    }
    __syncthreads();

    for (int u = warp; u < 100; u += 16){
        int yt = u >> 1, pass = u & 1;
        int k2m0 = pass*64 + lane, k2m1 = k2m0 + 32;
        bool va0 = k2m0 <= 100, va1 = k2m1 <= 100;
        int k2c0 = min(k2m0, 100), k2c1 = min(k2m1, 100);
        u64 P1[4][2], P2[4][2];
#pragma unroll
        for (int j = 0; j < 4; j++){ P1[j][0]=0ull; P1[j][1]=0ull; P2[j][0]=0ull; P2[j][1]=0ull; }
        int idx[4] = {0, 0, 0, 0};
        for (int k1 = 0; k1 < 200; k1++){
            float2 t0 = s_S[k1*SPITCH + k2c0];
            float2 t1 = s_S[k1*SPITCH + k2c1];
            u64 Tx0 = pk2(t0.x, t0.x), Ty0 = pk2(t0.y, t0.y);
            u64 Tx1 = pk2(t1.x, t1.x), Ty1 = pk2(t1.y, t1.y);
#pragma unroll
            for (int j = 0; j < 4; j++){
                ulonglong2 wv = s_tw2[idx[j]];
                P1[j][0] = ffma2(Tx0, wv.x, P1[j][0]);
                P2[j][0] = ffma2(Ty0, wv.y, P2[j][0]);
                P1[j][1] = ffma2(Tx1, wv.x, P1[j][1]);
                P2[j][1] = ffma2(Ty1, wv.y, P2[j][1]);
                idx[j] += yt*4 + j; if (idx[j] >= 200) idx[j] -= 200;
            }
        }
#pragma unroll
        for (int j = 0; j < 4; j++){
            int y = yt*4 + j;
#pragma unroll
            for (int m = 0; m < 2; m++){
                bool va = (m == 0) ? va0 : va1;
                if (!va) continue;
                int k2 = (m == 0) ? k2m0 : k2m1;
                float2 p1 = up2(P1[j][m]), p2 = up2(P2[j][m]);
                float sc = (k2 == 0 || k2 == 100) ? 2.5e-5f : 5.0e-5f;
                d_Binv[img*SPEC + k2*200 + y] = make_float2((p1.x - p2.x)*sc, (p1.y + p2.y)*sc);
            }
        }
    }
}

// ---------------- inverse stage 2 over k2 (real, packed-term trick) + max + gather ----------------
// s[y][x] = sum_{k2} (B.x*c - B.y*s), (c,s)=e^{+2pi i k2 x /200}
__global__ void __launch_bounds__(512, 1) k_ifft2(const int* __restrict__ gt_rot,
                                                  const int* __restrict__ gt_txy){
    extern __shared__ char sm[];
    u64* s_tw = (u64*)sm;                 // 1600 B
    u64* s_B  = (u64*)(sm + 1600);        // SPEC*8 = 161600 B, [k2][y] as packed float2
    __shared__ float red[512];
    int tid = threadIdx.x, lane = tid & 31, warp = tid >> 5;
    int img = blockIdx.x;
    int b = img / RR, r = img % RR;
    const u64* src = (const u64*)(d_Binv + img*SPEC);
    for (int i = tid; i < SS; i += 512) s_tw[i] = d_tw1i[i];
    for (int i = tid; i < SPEC; i += 512) s_B[i] = src[i];
    __syncthreads();

    int gtr = gt_rot[b];
    int ty = gt_txy[2*b], tx = gt_txy[2*b + 1];
    float lm = -FLT_MAX;

    for (int u = warp; u < 50; u += 16){
        int xt = u >> 1, pass = u & 1;
        int xb = xt * 8;
        int ym[4]; bool vy[4]; int yc[4];
#pragma unroll
        for (int m = 0; m < 4; m++){
            ym[m] = pass*128 + lane + 32*m;
            vy[m] = ym[m] < 200;
            yc[m] = min(ym[m], 199);
        }
        u64 acc[8][4];
#pragma unroll
        for (int i = 0; i < 8; i++)
#pragma unroll
            for (int m = 0; m < 4; m++) acc[i][m] = 0ull;
        int idx[8] = {0,0,0,0,0,0,0,0};
        for (int k2 = 0; k2 <= 100; k2++){
            u64 B0 = s_B[k2*200 + yc[0]];
            u64 B1 = s_B[k2*200 + yc[1]];
            u64 B2 = s_B[k2*200 + yc[2]];
            u64 B3 = s_B[k2*200 + yc[3]];
#pragma unroll
            for (int i = 0; i < 8; i++){
                u64 w = s_tw[idx[i]];
                acc[i][0] = ffma2(B0, w, acc[i][0]);
                acc[i][1] = ffma2(B1, w, acc[i][1]);
                acc[i][2] = ffma2(B2, w, acc[i][2]);
                acc[i][3] = ffma2(B3, w, acc[i][3]);
                idx[i] += xb + i; if (idx[i] >= 200) idx[i] -= 200;
            }
        }
#pragma unroll
        for (int i = 0; i < 8; i++){
            int x = xb + i;
#pragma unroll
            for (int m = 0; m < 4; m++){
                if (!vy[m]) continue;
                float2 a = up2(acc[i][m]);
                float v = a.x - a.y;
                lm = fmaxf(lm, v);
                if (r == gtr && ym[m] == ty && x == tx) d_pos[b] = v;
            }
        }
    }
    red[tid] = lm;
    __syncthreads();
    for (int s = 256; s > 0; s >>= 1){
        if (tid < s) red[tid] = fmaxf(red[tid], red[tid + s]);
        __syncthreads();
    }
    if (tid == 0) d_blockmax[img] = red[0];
}

// ---------------- final reduction + loss ----------------
__global__ void k_final(float* __restrict__ out){
    __shared__ float r0[512], r1[512];
    int tid = threadIdx.x;
    float m0 = -FLT_MAX, m1 = -FLT_MAX;
    if (tid < RR){ m0 = d_blockmax[tid]; m1 = d_blockmax[RR + tid]; }
    r0[tid] = m0; r1[tid] = m1;
    __syncthreads();
    for (int s = 256; s > 0; s >>= 1){
        if (tid < s){ r0[tid] = fmaxf(r0[tid], r0[tid+s]); r1[tid] = fmaxf(r1[tid], r1[tid+s]); }
        __syncthreads();
    }
    if (tid == 0){
        float p0 = d_pos[0], p1 = d_pos[1];
        float b0 = r0[0], b1 = r1[0];
        out[0] = 0.5f * ((p0 + p0*p0) + (p1 + p1*p1));
        out[1] = 0.5f * ((-b0 + b0*b0) + (-b1 + b1*b1));
    }
}

// ---------------- launch ----------------
extern "C" void kernel_launch(void* const* d_in, const int* in_sizes, int n_in,
                              void* d_out, int out_size){
    const float* rec = (const float*)d_in[0];
    const float* lig = (const float*)d_in[1];
    const float* w1  = (const float*)d_in[2];
    const float* w2  = (const float*)d_in[3];
    const float* bW  = (const float*)d_in[4];
    const float* c1  = (const float*)d_in[5];
    const float* c2  = (const float*)d_in[6];
    const float* bu  = (const float*)d_in[7];
    const int*   gtr = (const int*)d_in[8];
    const int*   gtx = (const int*)d_in[9];
    float* out = (float*)d_out;

    const int FWD_SMEM  = 3200 + 1600 + NPIX*4 + SIDE*T1PITCH*8;   // 205600
    const int I1_SMEM   = 3200 + SS*SPITCH*8;                      // 171200
    const int I2_SMEM   = 1600 + SPEC*8;                           // 163200
    cudaFuncSetAttribute(k_fwd,   cudaFuncAttributeMaxDynamicSharedMemorySize, FWD_SMEM);
    cudaFuncSetAttribute(k_ifft1, cudaFuncAttributeMaxDynamicSharedMemorySize, I1_SMEM);
    cudaFuncSetAttribute(k_ifft2, cudaFuncAttributeMaxDynamicSharedMemorySize, I2_SMEM);

    k_init<<<1, 512>>>();
    k_conv1<<<(4*NPIX + 255)/256, 256>>>(rec, lig, w1);
    k_conv2<<<(4*NPIX + 255)/256, 256>>>(w2);
    k_rot<<<(NIMG*NPIX + 255)/256, 256>>>();
    k_fwd<<<NB, 512, FWD_SMEM>>>(0);
    k_gcoef<<<(NB*SPEC + 255)/256, 256>>>(bW, c1, c2, bu);
    k_fwd<<<NIMG, 512, FWD_SMEM>>>(1);
    k_ifft1<<<NIMG, 512, I1_SMEM>>>();
    k_ifft2<<<NIMG, 512, I2_SMEM>>>(gtr, gtx);
    k_final<<<1, 512>>>(out);
}

// round 11
// speedup vs baseline: 1.5256x; 1.5256x over previous
#include <cuda_runtime.h>
#include <math.h>
#include <cfloat>

#ifndef M_PI
#define M_PI 3.14159265358979323846
#endif

typedef unsigned long long u64;

#define NPIX 10000      // 100*100
#define SIDE 100
#define SS   200
#define KH   101        // rfft half-width
#define RR   360
#define NB   2
#define NIMG (NB*RR)    // 720
#define SPEC (SS*KH)    // 20200 (layout [k1*101 + k2] for SF/rf/G; [y*101 + k2] for Binv)
#define EPSF 1e-12f
#define THR  416
#define NW   13

// ---------------- static device scratch ----------------
__device__ float  d_h1[4*9*NPIX];
__device__ float  d_feat[4*2*NPIX];
__device__ float  d_rot[NIMG*2*NPIX];
__device__ float2 d_rf[4*SPEC];            // [q][k1*101 + k2]
__device__ float2 d_G[4*SPEC];             // [q][k1*101 + k2]
__device__ float2 d_SF[NIMG*SPEC];         // [img][k1*101 + k2]
__device__ float2 d_Binv[NIMG*SPEC];       // [img][y*101 + k2]
__device__ float  d_blockmax[NIMG];
__device__ float  d_pos[NB];
__device__ float2 d_rtrig[RR];
__device__ ulonglong2 d_twd[SS];           // ((c,c),(s,s)), c=cos(2pi t/200), s=sin
__device__ u64        d_twp[SS];           // (c, s)

// ---------------- packed f32x2 helpers ----------------
__device__ __forceinline__ u64 pk2(float a, float b){
    u64 r; asm("mov.b64 %0, {%1, %2};" : "=l"(r) : "f"(a), "f"(b)); return r;
}
__device__ __forceinline__ float2 up2(u64 v){
    float2 r; asm("mov.b64 {%0, %1}, %2;" : "=f"(r.x), "=f"(r.y) : "l"(v)); return r;
}
__device__ __forceinline__ u64 ffma2(u64 a, u64 b, u64 c){
    u64 d; asm("fma.rn.f32x2 %0, %1, %2, %3;" : "=l"(d) : "l"(a), "l"(b), "l"(c)); return d;
}

// ---------------- init tables ----------------
__global__ void k_init(){
    int t = threadIdx.x;
    if (t < SS){
        double th = 2.0 * M_PI * (double)t / 200.0;
        float c = (float)cos(th), s = (float)sin(th);
        d_twd[t] = make_ulonglong2(pk2(c, c), pk2(s, s));
        d_twp[t] = pk2(c, s);
    }
    if (t < RR){
        double th = -M_PI + (double)t * (2.0 * M_PI / 360.0);
        d_rtrig[t] = make_float2((float)cos(th), (float)sin(th));
    }
}

// ---------------- conv1 + field norm ----------------
__global__ void k_conv1(const float* __restrict__ rec, const float* __restrict__ lig,
                        const float* __restrict__ w1){
    int idx = blockIdx.x*blockDim.x + threadIdx.x;
    if (idx >= 4*NPIX) return;
    int t = idx / NPIX, p = idx % NPIX;
    int y = p / SIDE, x = p % SIDE;
    const float* src = (t < 2) ? rec + t*NPIX : lig + (t-2)*NPIX;
    float acc[9];
#pragma unroll
    for (int o = 0; o < 9; o++) acc[o] = 0.f;
    for (int dy = 0; dy < 5; dy++){
        int yy = y + dy - 2; if (yy < 0 || yy >= SIDE) continue;
        for (int dx = 0; dx < 5; dx++){
            int xx = x + dx - 2; if (xx < 0 || xx >= SIDE) continue;
            float v = src[yy*SIDE + xx];
#pragma unroll
            for (int o = 0; o < 9; o++) acc[o] = fmaf(w1[o*25 + dy*5 + dx], v, acc[o]);
        }
    }
    float out[9];
    { float n = sqrtf(acc[0]*acc[0] + EPSF); out[0] = acc[0] * (n/(n+EPSF)); }
#pragma unroll
    for (int g = 0; g < 4; g++){
        int a = 1 + 2*g;
        float n = sqrtf(acc[a]*acc[a] + acc[a+1]*acc[a+1] + EPSF);
        float s = n/(n+EPSF);
        out[a] = acc[a]*s; out[a+1] = acc[a+1]*s;
    }
#pragma unroll
    for (int o = 0; o < 9; o++) d_h1[(t*9 + o)*NPIX + p] = out[o];
}

// ---------------- conv2 + field norm + features ----------------
__global__ void k_conv2(const float* __restrict__ w2){
    int idx = blockIdx.x*blockDim.x + threadIdx.x;
    if (idx >= 4*NPIX) return;
    int t = idx / NPIX, p = idx % NPIX;
    int y = p / SIDE, x = p % SIDE;
    float h[3] = {0.f, 0.f, 0.f};
    for (int ic = 0; ic < 9; ic++){
        const float* base = d_h1 + (t*9 + ic)*NPIX;
        for (int dy = 0; dy < 5; dy++){
            int yy = y + dy - 2; if (yy < 0 || yy >= SIDE) continue;
            for (int dx = 0; dx < 5; dx++){
                int xx = x + dx - 2; if (xx < 0 || xx >= SIDE) continue;
                float v = base[yy*SIDE + xx];
#pragma unroll
                for (int oc = 0; oc < 3; oc++)
                    h[oc] = fmaf(w2[(oc*9 + ic)*25 + dy*5 + dx], v, h[oc]);
            }
        }
    }
    float n0 = sqrtf(h[0]*h[0] + EPSF);
    float o0 = h[0] * (n0/(n0+EPSF));
    float n1 = sqrtf(h[1]*h[1] + h[2]*h[2] + EPSF);
    float s  = n1/(n1+EPSF);
    float o1 = h[1]*s, o2 = h[2]*s;
    d_feat[(t*2 + 0)*NPIX + p] = fabsf(o0);
    d_feat[(t*2 + 1)*NPIX + p] = sqrtf(o1*o1 + o2*o2 + EPSF);
}

// ---------------- bilinear rotation ----------------
__global__ void k_rot(){
    int idx = blockIdx.x*blockDim.x + threadIdx.x;
    if (idx >= NIMG*NPIX) return;
    int img = idx / NPIX, p = idx % NPIX;
    int b = img / RR, r = img % RR;
    int i = p / SIDE, j = p % SIDE;
    float2 cs = d_rtrig[r];
    float ct = cs.x, st = cs.y;
    const float c = 49.5f;
    float xs = (float)j - c, ys = (float)i - c;
    float xq =  ct*xs + st*ys + c;
    float yq = -st*xs + ct*ys + c;
    float x0f = floorf(xq), y0f = floorf(yq);
    float wx = xq - x0f, wy = yq - y0f;
    int x0 = (int)x0f, y0 = (int)y0f;
    float w00 = (1.f-wy)*(1.f-wx), w01 = (1.f-wy)*wx;
    float w10 = wy*(1.f-wx),       w11 = wy*wx;
    bool vx0 = (x0 >= 0 && x0 < SIDE), vx1 = (x0+1 >= 0 && x0+1 < SIDE);
    bool vy0 = (y0 >= 0 && y0 < SIDE), vy1 = (y0+1 >= 0 && y0+1 < SIDE);
    int cx0 = min(max(x0, 0), SIDE-1),   cx1 = min(max(x0+1, 0), SIDE-1);
    int cy0 = min(max(y0, 0), SIDE-1),   cy1 = min(max(y0+1, 0), SIDE-1);
#pragma unroll
    for (int ch = 0; ch < 2; ch++){
        const float* base = d_feat + ((2 + b)*2 + ch)*NPIX;
        float g00 = (vy0 && vx0) ? base[cy0*SIDE + cx0] : 0.f;
        float g01 = (vy0 && vx1) ? base[cy0*SIDE + cx1] : 0.f;
        float g10 = (vy1 && vx0) ? base[cy1*SIDE + cx0] : 0.f;
        float g11 = (vy1 && vx1) ? base[cy1*SIDE + cx1] : 0.f;
        d_rot[(img*2 + ch)*NPIX + p] = g00*w00 + g01*w01 + g10*w10 + g11*w11;
    }
}

// ---------------- forward rfft2: x-axis half-DFT then y-axis full DFT w/ conjugate pairing ----
// lig_mode=0: grid NB; writes d_rf.  lig_mode=1: grid NIMG; combines with d_G into d_SF.
__global__ void __launch_bounds__(THR, 1) k_fwd(int lig_mode){
    extern __shared__ char sm[];
    ulonglong2* s_twd  = (ulonglong2*)sm;              // 3200 B
    float*      s_imgT = (float*)(sm + 3200);          // 100 x-rows * pitch102 * 4 = 40800 B
    u64*        s_U    = (u64*)(sm + 3200 + 40800);    // 100 y * pitch103 * 8 = 82400 B
    int tid = threadIdx.x, lane = tid & 31, warp = tid >> 5;
    int img = blockIdx.x;
    int b = lig_mode ? (img / RR) : img;

    for (int i = tid; i < SS; i += THR) s_twd[i] = d_twd[i];

    for (int ch = 0; ch < 2; ch++){
        const float* src = lig_mode ? (d_rot + (img*2 + ch)*NPIX)
                                    : (d_feat + (img*2 + ch)*NPIX);
        for (int i = tid; i < NPIX; i += THR){
            int y = i / 100, x = i - y*100;
            s_imgT[x*102 + y] = src[i];
        }
        __syncthreads();

        // ---- stage A: U[y][k2] = sum_x v[y][x] e^{-2pi i k2 x/200}, k2=0..100
        // lanes = y-pairs, regs j = k2. acc pairs: (U_y, U_{y+1}) for cos and sin sums.
        {
            int p0 = lane, p1 = lane + 32;
            int pc0 = min(p0, 49), pc1 = min(p1, 49);
            for (int u = warp; u < 26; u += NW){
                int k2b = u * 4;
                u64 aC[4][2], aS[4][2];
#pragma unroll
                for (int j = 0; j < 4; j++){ aC[j][0]=0; aC[j][1]=0; aS[j][0]=0; aS[j][1]=0; }
                int idx[4] = {0,0,0,0};
                for (int x = 0; x < 100; x++){
                    const u64* rp = (const u64*)(s_imgT + x*102);
                    u64 V0 = rp[pc0], V1 = rp[pc1];
#pragma unroll
                    for (int j = 0; j < 4; j++){
                        ulonglong2 w = s_twd[idx[j]];
                        aC[j][0] = ffma2(V0, w.x, aC[j][0]);
                        aS[j][0] = ffma2(V0, w.y, aS[j][0]);
                        aC[j][1] = ffma2(V1, w.x, aC[j][1]);
                        aS[j][1] = ffma2(V1, w.y, aS[j][1]);
                        idx[j] += k2b + j; if (idx[j] >= 200) idx[j] -= 200;
                    }
                }
#pragma unroll
                for (int j = 0; j < 4; j++){
                    int k2 = k2b + j;
                    if (k2 > 100) continue;
#pragma unroll
                    for (int m = 0; m < 2; m++){
                        int p = lane + 32*m;
                        if (p >= 50) continue;
                        float2 cv = up2(aC[j][m]), sv = up2(aS[j][m]);
                        s_U[(2*p    )*103 + k2] = pk2(cv.x, -sv.x);
                        s_U[(2*p + 1)*103 + k2] = pk2(cv.y, -sv.y);
                    }
                }
            }
        }
        __syncthreads();

        // ---- stage B: C[k1][k2] = sum_y U[y][k2] e^{-2pi i k1 y/200}, k1 paired with 200-k1
        // acc1 = (Pc,Qc) = sum (U.re*c, U.im*c); acc2 = (Ps,Qs) = sum (U.re*s, U.im*s)
        // C[k1] = (Pc+Qs, Qc-Ps);  C[200-k1] = (Pc-Qs, Qc+Ps)
        {
            float2* gout = lig_mode ? (d_SF + img*SPEC) : (d_rf + (img*2 + ch)*SPEC);
            const float2* Gt = lig_mode ? (d_G + (b*2 + ch)*SPEC) : (const float2*)0;
            int kc[4];
#pragma unroll
            for (int m = 0; m < 4; m++) kc[m] = min(lane + 32*m, 100);
            for (int u = warp; u < 26; u += NW){
                int k1b = u * 4;
                u64 a1[4][4], a2[4][4];
#pragma unroll
                for (int j = 0; j < 4; j++)
#pragma unroll
                    for (int m = 0; m < 4; m++){ a1[j][m] = 0; a2[j][m] = 0; }
                int idx[4] = {0,0,0,0};
                for (int y = 0; y < 100; y++){
                    const u64* rp = s_U + y*103;
                    u64 D0 = rp[kc[0]], D1 = rp[kc[1]], D2 = rp[kc[2]], D3 = rp[kc[3]];
#pragma unroll
                    for (int j = 0; j < 4; j++){
                        ulonglong2 w = s_twd[idx[j]];
                        a1[j][0] = ffma2(D0, w.x, a1[j][0]);
                        a2[j][0] = ffma2(D0, w.y, a2[j][0]);
                        a1[j][1] = ffma2(D1, w.x, a1[j][1]);
                        a2[j][1] = ffma2(D1, w.y, a2[j][1]);
                        a1[j][2] = ffma2(D2, w.x, a1[j][2]);
                        a2[j][2] = ffma2(D2, w.y, a2[j][2]);
                        a1[j][3] = ffma2(D3, w.x, a1[j][3]);
                        a2[j][3] = ffma2(D3, w.y, a2[j][3]);
                        idx[j] += k1b + j; if (idx[j] >= 200) idx[j] -= 200;
                    }
                }
#pragma unroll
                for (int j = 0; j < 4; j++){
                    int k1 = k1b + j;
                    if (k1 > 100) continue;
#pragma unroll
                    for (int m = 0; m < 4; m++){
                        int k2 = lane + 32*m;
                        if (k2 > 100) continue;
                        float2 p = up2(a1[j][m]);   // (Pc, Qc)
                        float2 q = up2(a2[j][m]);   // (Ps, Qs)
                        float2 C1 = make_float2(p.x + q.y, p.y - q.x);
                        int o1 = k1*101 + k2;
                        if (lig_mode){
                            float2 g = Gt[o1];
                            float2 v = make_float2(C1.x*g.x - C1.y*g.y, C1.x*g.y + C1.y*g.x);
                            if (ch == 0) gout[o1] = v;
                            else { float2 pv = gout[o1]; gout[o1] = make_float2(pv.x+v.x, pv.y+v.y); }
                        } else gout[o1] = C1;
                        if (k1 >= 1 && k1 <= 99){
                            float2 C2 = make_float2(p.x - q.y, p.y + q.x);
                            int o2 = (200 - k1)*101 + k2;
                            if (lig_mode){
                                float2 g = Gt[o2];
                                float2 v = make_float2(C2.x*g.x - C2.y*g.y, C2.x*g.y + C2.y*g.x);
                                if (ch == 0) gout[o2] = v;
                                else { float2 pv = gout[o2]; gout[o2] = make_float2(pv.x+v.x, pv.y+v.y); }
                            } else gout[o2] = C2;
                        }
                    }
                }
            }
        }
        __syncthreads();
    }
}

// ---------------- combine coefficients (layout-agnostic elementwise) ----------------
__global__ void k_gcoef(const float* __restrict__ bW, const float* __restrict__ c1,
                        const float* __restrict__ c2, const float* __restrict__ bu){
    int idx = blockIdx.x*blockDim.x + threadIdx.x;
    if (idx >= NB*SPEC) return;
    int b = idx / SPEC, i = idx % SPEC;
    float2 rb = d_rf[(b*2 + 0)*SPEC + i];
    float2 rB = d_rf[(b*2 + 1)*SPEC + i];
    float2 crb = make_float2(rb.x, -rb.y);
    float2 crB = make_float2(rB.x, -rB.y);
    float wb = bW[0], wc1 = c1[0], wc2 = c2[0], wk = bu[0];
    d_G[(b*2 + 0)*SPEC + i] = make_float2(wb*crb.x + wc2*crB.x,  wb*crb.y + wc2*crB.y);
    d_G[(b*2 + 1)*SPEC + i] = make_float2(wc1*crb.x - wk*crB.x,  wc1*crb.y - wk*crB.y);
}

// ---------------- inverse stage 1 over k1, conjugate-pairing y <-> 200-y ----------------
// B[k2][y] = sc(k2) * sum_k1 SF[k1][k2] e^{+2pi i k1 y/200}
// acc1=(Pc,Qc), acc2=(Ps,Qs); B[y]=(Pc-Qs, Ps+Qc); B[200-y]=(Pc+Qs, Qc-Ps)
__global__ void __launch_bounds__(THR, 1) k_ifft1(){
    extern __shared__ char sm[];
    ulonglong2* s_twd = (ulonglong2*)sm;            // 3200 B
    u64*        s_S   = (u64*)(sm + 3200);          // 20200*8 = 161600 B, [k1*101+k2]
    int tid = threadIdx.x, lane = tid & 31, warp = tid >> 5;
    int img = blockIdx.x;
    const u64* src = (const u64*)(d_SF + img*SPEC);
    for (int i = tid; i < SS; i += THR) s_twd[i] = d_twd[i];
    for (int i = tid; i < SPEC; i += THR) s_S[i] = src[i];
    __syncthreads();

    int kc[4];
#pragma unroll
    for (int m = 0; m < 4; m++) kc[m] = min(lane + 32*m, 100);

    for (int u = warp; u < 26; u += NW){
        int yb = u * 4;
        u64 a1[4][4], a2[4][4];
#pragma unroll
        for (int j = 0; j < 4; j++)
#pragma unroll
            for (int m = 0; m < 4; m++){ a1[j][m] = 0; a2[j][m] = 0; }
        int idx[4] = {0,0,0,0};
        for (int k1 = 0; k1 < 200; k1++){
            const u64* rp = s_S + k1*101;
            u64 D0 = rp[kc[0]], D1 = rp[kc[1]], D2 = rp[kc[2]], D3 = rp[kc[3]];
#pragma unroll
            for (int j = 0; j < 4; j++){
                ulonglong2 w = s_twd[idx[j]];
                a1[j][0] = ffma2(D0, w.x, a1[j][0]);
                a2[j][0] = ffma2(D0, w.y, a2[j][0]);
                a1[j][1] = ffma2(D1, w.x, a1[j][1]);
                a2[j][1] = ffma2(D1, w.y, a2[j][1]);
                a1[j][2] = ffma2(D2, w.x, a1[j][2]);
                a2[j][2] = ffma2(D2, w.y, a2[j][2]);
                a1[j][3] = ffma2(D3, w.x, a1[j][3]);
                a2[j][3] = ffma2(D3, w.y, a2[j][3]);
                idx[j] += yb + j; if (idx[j] >= 200) idx[j] -= 200;
            }
        }
#pragma unroll
        for (int j = 0; j < 4; j++){
            int y = yb + j;
            if (y > 100) continue;
#pragma unroll
            for (int m = 0; m < 4; m++){
                int k2 = lane + 32*m;
                if (k2 > 100) continue;
                float2 p = up2(a1[j][m]);   // (Pc, Qc)
                float2 q = up2(a2[j][m]);   // (Ps, Qs)
                float sc = (k2 == 0 || k2 == 100) ? 2.5e-5f : 5.0e-5f;
                d_Binv[img*SPEC + y*101 + k2] = make_float2((p.x - q.y)*sc, (q.x + p.y)*sc);
                if (y >= 1 && y <= 99)
                    d_Binv[img*SPEC + (200 - y)*101 + k2] = make_float2((p.x + q.y)*sc, (p.y - q.x)*sc);
            }
        }
    }
}

// ---------------- inverse stage 2 over k2 (real) with x <-> 200-x pairing + max + gather ----
template<int MCNT>
__device__ __forceinline__ void ifft2_tile(const u64* s_B, const u64* s_tw,
    int xt, int ybase, int lane, float& lm, int r, int gtr, int ty, int tx, int b){
    int xb = xt * 8;
    int ym[MCNT], yc[MCNT]; bool vy[MCNT];
#pragma unroll
    for (int m = 0; m < MCNT; m++){
        ym[m] = ybase + lane + 32*m;
        vy[m] = ym[m] < 200;
        yc[m] = min(ym[m], 199);
    }
    u64 acc[8][MCNT];
#pragma unroll
    for (int j = 0; j < 8; j++)
#pragma unroll
        for (int m = 0; m < MCNT; m++) acc[j][m] = 0;
    int idx[8] = {0,0,0,0,0,0,0,0};
    for (int k2 = 0; k2 <= 100; k2++){
        const u64* rp = s_B + k2*200;
        u64 D[MCNT];
#pragma unroll
        for (int m = 0; m < MCNT; m++) D[m] = rp[yc[m]];
#pragma unroll
        for (int j = 0; j < 8; j++){
            u64 w = s_tw[idx[j]];
#pragma unroll
            for (int m = 0; m < MCNT; m++) acc[j][m] = ffma2(D[m], w, acc[j][m]);
            idx[j] += xb + j; if (idx[j] >= 200) idx[j] -= 200;
        }
    }
#pragma unroll
    for (int j = 0; j < 8; j++){
        int x = xb + j;
        if (x > 100) continue;
#pragma unroll
        for (int m = 0; m < MCNT; m++){
            if (!vy[m]) continue;
            float2 a = up2(acc[j][m]);
            float v1 = a.x - a.y;
            lm = fmaxf(lm, v1);
            if (r == gtr && ym[m] == ty && x == tx) d_pos[b] = v1;
            if (x >= 1 && x <= 99){
                float v2 = a.x + a.y;
                lm = fmaxf(lm, v2);
                if (r == gtr && ym[m] == ty && (200 - x) == tx) d_pos[b] = v2;
            }
        }
    }
}

__global__ void __launch_bounds__(THR, 1) k_ifft2(const int* __restrict__ gt_rot,
                                                  const int* __restrict__ gt_txy){
    extern __shared__ char sm[];
    u64* s_tw = (u64*)sm;                 // 1600 B
    u64* s_B  = (u64*)(sm + 1600);        // 101*200*8 = 161600 B, [k2*200 + y]
    __shared__ float red[512];
    int tid = threadIdx.x, lane = tid & 31, warp = tid >> 5;
    int img = blockIdx.x;
    int b = img / RR, r = img % RR;
    const u64* src = (const u64*)(d_Binv + img*SPEC);   // [y*101 + k2]
    for (int i = tid; i < SS; i += THR) s_tw[i] = d_twp[i];
    for (int i = tid; i < SPEC; i += THR){
        int y = i / 101, k2 = i - y*101;
        s_B[k2*200 + y] = src[i];
    }
    __syncthreads();

    int gtr = gt_rot[b];
    int ty = gt_txy[2*b], tx = gt_txy[2*b + 1];
    float lm = -FLT_MAX;

    ifft2_tile<4>(s_B, s_tw, warp, 0,   lane, lm, r, gtr, ty, tx, b);
    ifft2_tile<3>(s_B, s_tw, warp, 128, lane, lm, r, gtr, ty, tx, b);

    red[tid] = lm;
    if (tid < 512 - THR) red[THR + tid] = -FLT_MAX;
    __syncthreads();
    for (int s = 256; s > 0; s >>= 1){
        if (tid < s) red[tid] = fmaxf(red[tid], red[tid + s]);
        __syncthreads();
    }
    if (tid == 0) d_blockmax[img] = red[0];
}

// ---------------- final reduction + loss ----------------
__global__ void k_final(float* __restrict__ out){
    __shared__ float r0[512], r1[512];
    int tid = threadIdx.x;
    float m0 = -FLT_MAX, m1 = -FLT_MAX;
    if (tid < RR){ m0 = d_blockmax[tid]; m1 = d_blockmax[RR + tid]; }
    r0[tid] = m0; r1[tid] = m1;
    __syncthreads();
    for (int s = 256; s > 0; s >>= 1){
        if (tid < s){ r0[tid] = fmaxf(r0[tid], r0[tid+s]); r1[tid] = fmaxf(r1[tid], r1[tid+s]); }
        __syncthreads();
    }
    if (tid == 0){
        float p0 = d_pos[0], p1 = d_pos[1];
        float b0 = r0[0], b1 = r1[0];
        out[0] = 0.5f * ((p0 + p0*p0) + (p1 + p1*p1));
        out[1] = 0.5f * ((-b0 + b0*b0) + (-b1 + b1*b1));
    }
}

// ---------------- launch ----------------
extern "C" void kernel_launch(void* const* d_in, const int* in_sizes, int n_in,
                              void* d_out, int out_size){
    const float* rec = (const float*)d_in[0];
    const float* lig = (const float*)d_in[1];
    const float* w1  = (const float*)d_in[2];
    const float* w2  = (const float*)d_in[3];
    const float* bW  = (const float*)d_in[4];
    const float* c1  = (const float*)d_in[5];
    const float* c2  = (const float*)d_in[6];
    const float* bu  = (const float*)d_in[7];
    const int*   gtr = (const int*)d_in[8];
    const int*   gtx = (const int*)d_in[9];
    float* out = (float*)d_out;

    const int FWD_SMEM = 3200 + 40800 + 82400;     // 126400
    const int I1_SMEM  = 3200 + SPEC*8;            // 164800
    const int I2_SMEM  = 1600 + SPEC*8;            // 163200
    cudaFuncSetAttribute(k_fwd,   cudaFuncAttributeMaxDynamicSharedMemorySize, FWD_SMEM);
    cudaFuncSetAttribute(k_ifft1, cudaFuncAttributeMaxDynamicSharedMemorySize, I1_SMEM);
    cudaFuncSetAttribute(k_ifft2, cudaFuncAttributeMaxDynamicSharedMemorySize, I2_SMEM);

    k_init<<<1, 512>>>();
    k_conv1<<<(4*NPIX + 255)/256, 256>>>(rec, lig, w1);
    k_conv2<<<(4*NPIX + 255)/256, 256>>>(w2);
    k_rot<<<(NIMG*NPIX + 255)/256, 256>>>();
    k_fwd<<<NB, THR, FWD_SMEM>>>(0);
    k_gcoef<<<(NB*SPEC + 255)/256, 256>>>(bW, c1, c2, bu);
    k_fwd<<<NIMG, THR, FWD_SMEM>>>(1);
    k_ifft1<<<NIMG, THR, I1_SMEM>>>();
    k_ifft2<<<NIMG, THR, I2_SMEM>>>(gtr, gtx);
    k_final<<<1, 512>>>(out);
}

// round 12
// speedup vs baseline: 1.7916x; 1.1744x over previous
#include <cuda_runtime.h>
#include <math.h>
#include <cfloat>

#ifndef M_PI
#define M_PI 3.14159265358979323846
#endif

typedef unsigned long long u64;

#define NPIX 10000      // 100*100
#define SIDE 100
#define SS   200
#define KH   101        // rfft half-width
#define RR   360
#define NB   2
#define NIMG (NB*RR)    // 720
#define SPEC (SS*KH)    // 20200
#define EPSF 1e-12f
#define THR  416
#define NW   13

// ---------------- static device scratch ----------------
__device__ float  d_h1[4*9*NPIX];
__device__ float  d_feat[4*2*NPIX];
__device__ float2 d_rf[4*SPEC];            // [q][k1*101 + k2]
__device__ float2 d_G[4*SPEC];             // [q][k1*101 + k2]
__device__ float2 d_SF[NIMG*SPEC];         // [img][k1*101 + k2]
__device__ float2 d_Binv[NIMG*SPEC];       // [img][y*101 + k2]
__device__ float  d_blockmax[NIMG];
__device__ float  d_pos[NB];
__device__ float2 d_rtrig[RR];
__device__ ulonglong2 d_twd[SS];           // ((c,c),(s,s)), c=cos(2pi t/200), s=sin
__device__ u64        d_twp[SS];           // (c, s)

// ---------------- packed f32x2 helpers ----------------
__device__ __forceinline__ u64 pk2(float a, float b){
    u64 r; asm("mov.b64 %0, {%1, %2};" : "=l"(r) : "f"(a), "f"(b)); return r;
}
__device__ __forceinline__ float2 up2(u64 v){
    float2 r; asm("mov.b64 {%0, %1}, %2;" : "=f"(r.x), "=f"(r.y) : "l"(v)); return r;
}
__device__ __forceinline__ u64 ffma2(u64 a, u64 b, u64 c){
    u64 d; asm("fma.rn.f32x2 %0, %1, %2, %3;" : "=l"(d) : "l"(a), "l"(b), "l"(c)); return d;
}

// ---------------- init tables ----------------
__global__ void k_init(){
    int t = threadIdx.x;
    if (t < SS){
        double th = 2.0 * M_PI * (double)t / 200.0;
        float c = (float)cos(th), s = (float)sin(th);
        d_twd[t] = make_ulonglong2(pk2(c, c), pk2(s, s));
        d_twp[t] = pk2(c, s);
    }
    if (t < RR){
        double th = -M_PI + (double)t * (2.0 * M_PI / 360.0);
        d_rtrig[t] = make_float2((float)cos(th), (float)sin(th));
    }
}

// ---------------- conv1 + field norm ----------------
__global__ void k_conv1(const float* __restrict__ rec, const float* __restrict__ lig,
                        const float* __restrict__ w1){
    int idx = blockIdx.x*blockDim.x + threadIdx.x;
    if (idx >= 4*NPIX) return;
    int t = idx / NPIX, p = idx % NPIX;
    int y = p / SIDE, x = p % SIDE;
    const float* src = (t < 2) ? rec + t*NPIX : lig + (t-2)*NPIX;
    float acc[9];
#pragma unroll
    for (int o = 0; o < 9; o++) acc[o] = 0.f;
    for (int dy = 0; dy < 5; dy++){
        int yy = y + dy - 2; if (yy < 0 || yy >= SIDE) continue;
        for (int dx = 0; dx < 5; dx++){
            int xx = x + dx - 2; if (xx < 0 || xx >= SIDE) continue;
            float v = src[yy*SIDE + xx];
#pragma unroll
            for (int o = 0; o < 9; o++) acc[o] = fmaf(w1[o*25 + dy*5 + dx], v, acc[o]);
        }
    }
    float out[9];
    { float n = sqrtf(acc[0]*acc[0] + EPSF); out[0] = acc[0] * (n/(n+EPSF)); }
#pragma unroll
    for (int g = 0; g < 4; g++){
        int a = 1 + 2*g;
        float n = sqrtf(acc[a]*acc[a] + acc[a+1]*acc[a+1] + EPSF);
        float s = n/(n+EPSF);
        out[a] = acc[a]*s; out[a+1] = acc[a+1]*s;
    }
#pragma unroll
    for (int o = 0; o < 9; o++) d_h1[(t*9 + o)*NPIX + p] = out[o];
}

// ---------------- conv2 + field norm + features ----------------
__global__ void k_conv2(const float* __restrict__ w2){
    int idx = blockIdx.x*blockDim.x + threadIdx.x;
    if (idx >= 4*NPIX) return;
    int t = idx / NPIX, p = idx % NPIX;
    int y = p / SIDE, x = p % SIDE;
    float h[3] = {0.f, 0.f, 0.f};
    for (int ic = 0; ic < 9; ic++){
        const float* base = d_h1 + (t*9 + ic)*NPIX;
        for (int dy = 0; dy < 5; dy++){
            int yy = y + dy - 2; if (yy < 0 || yy >= SIDE) continue;
            for (int dx = 0; dx < 5; dx++){
                int xx = x + dx - 2; if (xx < 0 || xx >= SIDE) continue;
                float v = base[yy*SIDE + xx];
#pragma unroll
                for (int oc = 0; oc < 3; oc++)
                    h[oc] = fmaf(w2[(oc*9 + ic)*25 + dy*5 + dx], v, h[oc]);
            }
        }
    }
    float n0 = sqrtf(h[0]*h[0] + EPSF);
    float o0 = h[0] * (n0/(n0+EPSF));
    float n1 = sqrtf(h[1]*h[1] + h[2]*h[2] + EPSF);
    float s  = n1/(n1+EPSF);
    float o1 = h[1]*s, o2 = h[2]*s;
    d_feat[(t*2 + 0)*NPIX + p] = fabsf(o0);
    d_feat[(t*2 + 1)*NPIX + p] = sqrtf(o1*o1 + o2*o2 + EPSF);
}

// ---------------- bilinear rotation of one pixel (device helper) ----------------
__device__ __forceinline__ float rot_pixel(const float* __restrict__ base,
                                           float ct, float st, int i, int j){
    const float c = 49.5f;
    float xs = (float)j - c, ys = (float)i - c;
    float xq =  ct*xs + st*ys + c;
    float yq = -st*xs + ct*ys + c;
    float x0f = floorf(xq), y0f = floorf(yq);
    float wx = xq - x0f, wy = yq - y0f;
    int x0 = (int)x0f, y0 = (int)y0f;
    float w00 = (1.f-wy)*(1.f-wx), w01 = (1.f-wy)*wx;
    float w10 = wy*(1.f-wx),       w11 = wy*wx;
    bool vx0 = (x0 >= 0 && x0 < SIDE), vx1 = (x0+1 >= 0 && x0+1 < SIDE);
    bool vy0 = (y0 >= 0 && y0 < SIDE), vy1 = (y0+1 >= 0 && y0+1 < SIDE);
    int cx0 = min(max(x0, 0), SIDE-1),   cx1 = min(max(x0+1, 0), SIDE-1);
    int cy0 = min(max(y0, 0), SIDE-1),   cy1 = min(max(y0+1, 0), SIDE-1);
    float g00 = (vy0 && vx0) ? base[cy0*SIDE + cx0] : 0.f;
    float g01 = (vy0 && vx1) ? base[cy0*SIDE + cx1] : 0.f;
    float g10 = (vy1 && vx0) ? base[cy1*SIDE + cx0] : 0.f;
    float g11 = (vy1 && vx1) ? base[cy1*SIDE + cx1] : 0.f;
    return g00*w00 + g01*w01 + g10*w10 + g11*w11;
}

// ---------------- forward rfft2 (fused rotation in lig mode) ----------------
__global__ void __launch_bounds__(THR, 1) k_fwd(int lig_mode){
    extern __shared__ char sm[];
    ulonglong2* s_twd  = (ulonglong2*)sm;              // 3200 B
    float*      s_imgT = (float*)(sm + 3200);          // 100 x-rows * pitch102 * 4 = 40800 B
    u64*        s_U    = (u64*)(sm + 3200 + 40800);    // 100 y * pitch103 * 8 = 82400 B
    int tid = threadIdx.x, lane = tid & 31, warp = tid >> 5;
    int img = blockIdx.x;
    int b = lig_mode ? (img / RR) : img;
    int r = lig_mode ? (img % RR) : 0;
    float2 cs = d_rtrig[r];

    for (int i = tid; i < SS; i += THR) s_twd[i] = d_twd[i];

    for (int ch = 0; ch < 2; ch++){
        if (lig_mode){
            const float* base = d_feat + ((2 + b)*2 + ch)*NPIX;
            for (int i = tid; i < NPIX; i += THR){
                int yy = i / 100, xx = i - yy*100;
                s_imgT[xx*102 + yy] = rot_pixel(base, cs.x, cs.y, yy, xx);
            }
        } else {
            const float* src = d_feat + (img*2 + ch)*NPIX;
            for (int i = tid; i < NPIX; i += THR){
                int yy = i / 100, xx = i - yy*100;
                s_imgT[xx*102 + yy] = src[i];
            }
        }
        __syncthreads();

        // ---- stage A: U[y][k2] = sum_x v[y][x] e^{-2pi i k2 x/200}, k2=0..100
        {
            int p0 = lane, p1 = lane + 32;
            int pc0 = min(p0, 49), pc1 = min(p1, 49);
            for (int u = warp; u < 26; u += NW){
                int k2b = u * 4;
                u64 aC[4][2], aS[4][2];
#pragma unroll
                for (int j = 0; j < 4; j++){ aC[j][0]=0; aC[j][1]=0; aS[j][0]=0; aS[j][1]=0; }
                int idx[4] = {0,0,0,0};
                for (int x = 0; x < 100; x++){
                    const u64* rp = (const u64*)(s_imgT + x*102);
                    u64 V0 = rp[pc0], V1 = rp[pc1];
#pragma unroll
                    for (int j = 0; j < 4; j++){
                        ulonglong2 w = s_twd[idx[j]];
                        aC[j][0] = ffma2(V0, w.x, aC[j][0]);
                        aS[j][0] = ffma2(V0, w.y, aS[j][0]);
                        aC[j][1] = ffma2(V1, w.x, aC[j][1]);
                        aS[j][1] = ffma2(V1, w.y, aS[j][1]);
                        idx[j] += k2b + j; if (idx[j] >= 200) idx[j] -= 200;
                    }
                }
#pragma unroll
                for (int j = 0; j < 4; j++){
                    int k2 = k2b + j;
                    if (k2 > 100) continue;
#pragma unroll
                    for (int m = 0; m < 2; m++){
                        int p = lane + 32*m;
                        if (p >= 50) continue;
                        float2 cv = up2(aC[j][m]), sv = up2(aS[j][m]);
                        s_U[(2*p    )*103 + k2] = pk2(cv.x, -sv.x);
                        s_U[(2*p + 1)*103 + k2] = pk2(cv.y, -sv.y);
                    }
                }
            }
        }
        __syncthreads();

        // ---- stage B: C[k1][k2] = sum_y U[y][k2] e^{-2pi i k1 y/200}, k1 paired with 200-k1
        {
            float2* gout = lig_mode ? (d_SF + img*SPEC) : (d_rf + (img*2 + ch)*SPEC);
            const float2* Gt = lig_mode ? (d_G + (b*2 + ch)*SPEC) : (const float2*)0;
            int kc[4];
#pragma unroll
            for (int m = 0; m < 4; m++) kc[m] = min(lane + 32*m, 100);
            for (int u = warp; u < 26; u += NW){
                int k1b = u * 4;
                u64 a1[4][4], a2[4][4];
#pragma unroll
                for (int j = 0; j < 4; j++)
#pragma unroll
                    for (int m = 0; m < 4; m++){ a1[j][m] = 0; a2[j][m] = 0; }
                int idx[4] = {0,0,0,0};
                for (int y = 0; y < 100; y++){
                    const u64* rp = s_U + y*103;
                    u64 D0 = rp[kc[0]], D1 = rp[kc[1]], D2 = rp[kc[2]], D3 = rp[kc[3]];
#pragma unroll
                    for (int j = 0; j < 4; j++){
                        ulonglong2 w = s_twd[idx[j]];
                        a1[j][0] = ffma2(D0, w.x, a1[j][0]);
                        a2[j][0] = ffma2(D0, w.y, a2[j][0]);
                        a1[j][1] = ffma2(D1, w.x, a1[j][1]);
                        a2[j][1] = ffma2(D1, w.y, a2[j][1]);
                        a1[j][2] = ffma2(D2, w.x, a1[j][2]);
                        a2[j][2] = ffma2(D2, w.y, a2[j][2]);
                        a1[j][3] = ffma2(D3, w.x, a1[j][3]);
                        a2[j][3] = ffma2(D3, w.y, a2[j][3]);
                        idx[j] += k1b + j; if (idx[j] >= 200) idx[j] -= 200;
                    }
                }
#pragma unroll
                for (int j = 0; j < 4; j++){
                    int k1 = k1b + j;
                    if (k1 > 100) continue;
#pragma unroll
                    for (int m = 0; m < 4; m++){
                        int k2 = lane + 32*m;
                        if (k2 > 100) continue;
                        float2 p = up2(a1[j][m]);   // (Pc, Qc)
                        float2 q = up2(a2[j][m]);   // (Ps, Qs)
                        float2 C1 = make_float2(p.x + q.y, p.y - q.x);
                        int o1 = k1*101 + k2;
                        if (lig_mode){
                            float2 g = Gt[o1];
                            float2 v = make_float2(C1.x*g.x - C1.y*g.y, C1.x*g.y + C1.y*g.x);
                            if (ch == 0) gout[o1] = v;
                            else { float2 pv = gout[o1]; gout[o1] = make_float2(pv.x+v.x, pv.y+v.y); }
                        } else gout[o1] = C1;
                        if (k1 >= 1 && k1 <= 99){
                            float2 C2 = make_float2(p.x - q.y, p.y + q.x);
                            int o2 = (200 - k1)*101 + k2;
                            if (lig_mode){
                                float2 g = Gt[o2];
                                float2 v = make_float2(C2.x*g.x - C2.y*g.y, C2.x*g.y + C2.y*g.x);
                                if (ch == 0) gout[o2] = v;
                                else { float2 pv = gout[o2]; gout[o2] = make_float2(pv.x+v.x, pv.y+v.y); }
                            } else gout[o2] = C2;
                        }
                    }
                }
            }
        }
        __syncthreads();
    }
}

// ---------------- combine coefficients ----------------
__global__ void k_gcoef(const float* __restrict__ bW, const float* __restrict__ c1,
                        const float* __restrict__ c2, const float* __restrict__ bu){
    int idx = blockIdx.x*blockDim.x + threadIdx.x;
    if (idx >= NB*SPEC) return;
    int b = idx / SPEC, i = idx % SPEC;
    float2 rb = d_rf[(b*2 + 0)*SPEC + i];
    float2 rB = d_rf[(b*2 + 1)*SPEC + i];
    float2 crb = make_float2(rb.x, -rb.y);
    float2 crB = make_float2(rB.x, -rB.y);
    float wb = bW[0], wc1 = c1[0], wc2 = c2[0], wk = bu[0];
    d_G[(b*2 + 0)*SPEC + i] = make_float2(wb*crb.x + wc2*crB.x,  wb*crb.y + wc2*crB.y);
    d_G[(b*2 + 1)*SPEC + i] = make_float2(wc1*crb.x - wk*crB.x,  wc1*crb.y - wk*crB.y);
}

// ---------------- inverse stage 1 over k1, radix-2 (even/odd k1) + y-pairing ----------------
// B[y][k2] = sc * sum_k1 SF[k1][k2] e^{+i 2pi k1 y/200}
// E(y') = sum_m SF[2m] e^{+i 2pi m y'/100}; O from odd rows; B[y] = E(y%100) + w200^y O(y%100)
__device__ __forceinline__ void ifft1_phase(const u64* __restrict__ s_S,
    const ulonglong2* __restrict__ s_twd, int img, int warp, int lane, int ph){
    int yb = warp * 4;
    int k2m[2], k2c[2];
#pragma unroll
    for (int m = 0; m < 2; m++){
        k2m[m] = ph*64 + lane + 32*m;
        k2c[m] = min(k2m[m], 100);
    }
    u64 aE1[4][2], aE2[4][2], aO1[4][2], aO2[4][2];
#pragma unroll
    for (int j = 0; j < 4; j++)
#pragma unroll
        for (int m = 0; m < 2; m++){ aE1[j][m]=0; aE2[j][m]=0; aO1[j][m]=0; aO2[j][m]=0; }
    int idx[4], step[4];
#pragma unroll
    for (int j = 0; j < 4; j++){ step[j] = (2*(yb + j)) % 200; idx[j] = 0; }
    for (int mm = 0; mm < 100; mm++){
        const u64* rE = s_S + (2*mm)*101;
        const u64* rO = s_S + (2*mm + 1)*101;
        u64 DE0 = rE[k2c[0]], DE1 = rE[k2c[1]];
        u64 DO0 = rO[k2c[0]], DO1 = rO[k2c[1]];
#pragma unroll
        for (int j = 0; j < 4; j++){
            ulonglong2 w = s_twd[idx[j]];
            aE1[j][0] = ffma2(DE0, w.x, aE1[j][0]);
            aE2[j][0] = ffma2(DE0, w.y, aE2[j][0]);
            aE1[j][1] = ffma2(DE1, w.x, aE1[j][1]);
            aE2[j][1] = ffma2(DE1, w.y, aE2[j][1]);
            aO1[j][0] = ffma2(DO0, w.x, aO1[j][0]);
            aO2[j][0] = ffma2(DO0, w.y, aO2[j][0]);
            aO1[j][1] = ffma2(DO1, w.x, aO1[j][1]);
            aO2[j][1] = ffma2(DO1, w.y, aO2[j][1]);
            idx[j] += step[j]; if (idx[j] >= 200) idx[j] -= 200;
        }
    }
    float2* base = d_Binv + img*SPEC;
#pragma unroll
    for (int j = 0; j < 4; j++){
        int yp = yb + j;
        if (yp > 50) continue;
        float c1 = up2(s_twd[yp].x).x;
        float s1 = up2(s_twd[yp].y).x;
#pragma unroll
        for (int m = 0; m < 2; m++){
            int k2 = k2m[m];
            if (k2 > 100) continue;
            float2 a1 = up2(aE1[j][m]), a2 = up2(aE2[j][m]);
            float2 E1 = make_float2(a1.x - a2.y, a2.x + a1.y);
            float2 E2 = make_float2(a1.x + a2.y, a1.y - a2.x);
            float2 o1 = up2(aO1[j][m]), o2 = up2(aO2[j][m]);
            float2 O1 = make_float2(o1.x - o2.y, o2.x + o1.y);
            float2 O2 = make_float2(o1.x + o2.y, o1.y - o2.x);
            float2 T1 = make_float2(c1*O1.x - s1*O1.y,  c1*O1.y + s1*O1.x);
            float2 T2 = make_float2(-c1*O2.x - s1*O2.y, -c1*O2.y + s1*O2.x);
            float sc = (k2 == 0 || k2 == 100) ? 2.5e-5f : 5.0e-5f;
            base[yp*101 + k2]        = make_float2((E1.x + T1.x)*sc, (E1.y + T1.y)*sc);
            base[(yp + 100)*101 + k2] = make_float2((E1.x - T1.x)*sc, (E1.y - T1.y)*sc);
            base[(100 - yp)*101 + k2] = make_float2((E2.x + T2.x)*sc, (E2.y + T2.y)*sc);
            if (yp >= 1)
                base[(200 - yp)*101 + k2] = make_float2((E2.x - T2.x)*sc, (E2.y - T2.y)*sc);
        }
    }
}

__global__ void __launch_bounds__(THR, 1) k_ifft1(){
    extern __shared__ char sm[];
    ulonglong2* s_twd = (ulonglong2*)sm;            // 3200 B
    u64*        s_S   = (u64*)(sm + 3200);          // 20200*8 B, [k1*101+k2]
    int tid = threadIdx.x, lane = tid & 31, warp = tid >> 5;
    int img = blockIdx.x;
    const u64* src = (const u64*)(d_SF + img*SPEC);
    for (int i = tid; i < SS; i += THR) s_twd[i] = d_twd[i];
    for (int i = tid; i < SPEC; i += THR) s_S[i] = src[i];
    __syncthreads();
    ifft1_phase(s_S, s_twd, img, warp, lane, 0);
    ifft1_phase(s_S, s_twd, img, warp, lane, 1);
}

// ---------------- inverse stage 2 over k2, radix-2 (even/odd k2) + x quad-pairing ----------------
template<int MCNT>
__device__ __forceinline__ void ifft2r_tile(const u64* __restrict__ s_B,
    const u64* __restrict__ s_twp, const ulonglong2* __restrict__ s_twd,
    int xt, int ybase, int lane, float& lm, int r, int gtr, int ty, int tx, int b){
    int xb = xt * 4;
    int ym[MCNT], yc[MCNT]; bool vy[MCNT];
#pragma unroll
    for (int m = 0; m < MCNT; m++){
        ym[m] = ybase + lane + 32*m;
        vy[m] = ym[m] < 200;
        yc[m] = min(ym[m], 199);
    }
    u64 aE[4][MCNT], aO1[4][MCNT], aO2[4][MCNT];
#pragma unroll
    for (int j = 0; j < 4; j++)
#pragma unroll
        for (int m = 0; m < MCNT; m++){ aE[j][m]=0; aO1[j][m]=0; aO2[j][m]=0; }
    int idx[4], step[4];
#pragma unroll
    for (int j = 0; j < 4; j++){ step[j] = (2*(xb + j)) % 200; idx[j] = 0; }
    for (int mm = 0; mm < 50; mm++){
        const u64* rE = s_B + (2*mm)*200;
        const u64* rO = s_B + (2*mm + 1)*200;
        u64 BE[MCNT], BO[MCNT];
#pragma unroll
        for (int m = 0; m < MCNT; m++){ BE[m] = rE[yc[m]]; BO[m] = rO[yc[m]]; }
#pragma unroll
        for (int j = 0; j < 4; j++){
            u64 wp = s_twp[idx[j]];
            ulonglong2 wd = s_twd[idx[j]];
#pragma unroll
            for (int m = 0; m < MCNT; m++){
                aE[j][m]  = ffma2(BE[m], wp,   aE[j][m]);
                aO1[j][m] = ffma2(BO[m], wd.x, aO1[j][m]);
                aO2[j][m] = ffma2(BO[m], wd.y, aO2[j][m]);
            }
            idx[j] += step[j]; if (idx[j] >= 200) idx[j] -= 200;
        }
    }
    // even tail: k2 = 100 (angle index = (2*x'*50) mod 200 = current idx)
    {
        const u64* rE = s_B + 100*200;
        u64 BE[MCNT];
#pragma unroll
        for (int m = 0; m < MCNT; m++) BE[m] = rE[yc[m]];
#pragma unroll
        for (int j = 0; j < 4; j++){
            u64 wp = s_twp[idx[j]];
#pragma unroll
            for (int m = 0; m < MCNT; m++) aE[j][m] = ffma2(BE[m], wp, aE[j][m]);
        }
    }
#pragma unroll
    for (int j = 0; j < 4; j++){
        int xp = xb + j;
        if (xp > 50) continue;
        float2 w1 = up2(s_twp[xp]);   // (c1, s1)
#pragma unroll
        for (int m = 0; m < MCNT; m++){
            if (!vy[m]) continue;
            float2 ae = up2(aE[j][m]);
            float vE1 = ae.x - ae.y;      // even contrib at x', x'+100
            float vE2 = ae.x + ae.y;      // even contrib at 100-x', 200-x'
            float2 a1 = up2(aO1[j][m]), a2 = up2(aO2[j][m]);
            float POr = a1.x - a2.y, POi = a2.x + a1.y;        // PO(x')
            float P2r = a1.x + a2.y, P2i = a1.y - a2.x;        // PO(100-x')
            float t1 =  w1.x*POr - w1.y*POi;
            float t2 = -w1.x*P2r - w1.y*P2i;
            float v1 = vE1 + t1;          // x = xp
            float v2 = vE1 - t1;          // x = xp + 100
            float v3 = vE2 + t2;          // x = 100 - xp
            float v4 = vE2 - t2;          // x = 200 - xp (xp >= 1)
            lm = fmaxf(lm, fmaxf(v1, v2));
            lm = fmaxf(lm, v3);
            if (xp >= 1) lm = fmaxf(lm, v4);
            if (r == gtr && ym[m] == ty){
                if (xp == tx)               d_pos[b] = v1;
                if (xp + 100 == tx)         d_pos[b] = v2;
                if (100 - xp == tx)         d_pos[b] = v3;
                if (xp >= 1 && 200 - xp == tx) d_pos[b] = v4;
            }
        }
    }
}

__global__ void __launch_bounds__(THR, 1) k_ifft2(const int* __restrict__ gt_rot,
                                                  const int* __restrict__ gt_txy){
    extern __shared__ char sm[];
    u64*        s_twp = (u64*)sm;                   // 1600 B
    ulonglong2* s_twd = (ulonglong2*)(sm + 1600);   // 3200 B
    u64*        s_B   = (u64*)(sm + 4800);          // 101*200*8 B, [k2*200 + y]
    __shared__ float red[512];
    int tid = threadIdx.x, lane = tid & 31, warp = tid >> 5;
    int img = blockIdx.x;
    int b = img / RR, r = img % RR;
    const u64* src = (const u64*)(d_Binv + img*SPEC);   // [y*101 + k2]
    for (int i = tid; i < SS; i += THR){ s_twp[i] = d_twp[i]; s_twd[i] = d_twd[i]; }
    for (int i = tid; i < SPEC; i += THR){
        int y = i / 101, k2 = i - y*101;
        s_B[k2*200 + y] = src[i];
    }
    __syncthreads();

    int gtr = gt_rot[b];
    int ty = gt_txy[2*b], tx = gt_txy[2*b + 1];
    float lm = -FLT_MAX;

    ifft2r_tile<4>(s_B, s_twp, s_twd, warp, 0,   lane, lm, r, gtr, ty, tx, b);
    ifft2r_tile<3>(s_B, s_twp, s_twd, warp, 128, lane, lm, r, gtr, ty, tx, b);

    red[tid] = lm;
    if (tid < 512 - THR) red[THR + tid] = -FLT_MAX;
    __syncthreads();
    for (int s = 256; s > 0; s >>= 1){
        if (tid < s) red[tid] = fmaxf(red[tid], red[tid + s]);
        __syncthreads();
    }
    if (tid == 0) d_blockmax[img] = red[0];
}

// ---------------- final reduction + loss ----------------
__global__ void k_final(float* __restrict__ out){
    __shared__ float r0[512], r1[512];
    int tid = threadIdx.x;
    float m0 = -FLT_MAX, m1 = -FLT_MAX;
    if (tid < RR){ m0 = d_blockmax[tid]; m1 = d_blockmax[RR + tid]; }
    r0[tid] = m0; r1[tid] = m1;
    __syncthreads();
    for (int s = 256; s > 0; s >>= 1){
        if (tid < s){ r0[tid] = fmaxf(r0[tid], r0[tid+s]); r1[tid] = fmaxf(r1[tid], r1[tid+s]); }
        __syncthreads();
    }
    if (tid == 0){
        float p0 = d_pos[0], p1 = d_pos[1];
        float b0 = r0[0], b1 = r1[0];
        out[0] = 0.5f * ((p0 + p0*p0) + (p1 + p1*p1));
        out[1] = 0.5f * ((-b0 + b0*b0) + (-b1 + b1*b1));
    }
}

// ---------------- launch ----------------
extern "C" void kernel_launch(void* const* d_in, const int* in_sizes, int n_in,
                              void* d_out, int out_size){
    const float* rec = (const float*)d_in[0];
    const float* lig = (const float*)d_in[1];
    const float* w1  = (const float*)d_in[2];
    const float* w2  = (const float*)d_in[3];
    const float* bW  = (const float*)d_in[4];
    const float* c1  = (const float*)d_in[5];
    const float* c2  = (const float*)d_in[6];
    const float* bu  = (const float*)d_in[7];
    const int*   gtr = (const int*)d_in[8];
    const int*   gtx = (const int*)d_in[9];
    float* out = (float*)d_out;

    const int FWD_SMEM = 3200 + 40800 + 82400;     // 126400
    const int I1_SMEM  = 3200 + SPEC*8;            // 164800
    const int I2_SMEM  = 4800 + SPEC*8;            // 166400
    cudaFuncSetAttribute(k_fwd,   cudaFuncAttributeMaxDynamicSharedMemorySize, FWD_SMEM);
    cudaFuncSetAttribute(k_ifft1, cudaFuncAttributeMaxDynamicSharedMemorySize, I1_SMEM);
    cudaFuncSetAttribute(k_ifft2, cudaFuncAttributeMaxDynamicSharedMemorySize, I2_SMEM);

    k_init<<<1, 512>>>();
    k_conv1<<<(4*NPIX + 255)/256, 256>>>(rec, lig, w1);
    k_conv2<<<(4*NPIX + 255)/256, 256>>>(w2);
    k_fwd<<<NB, THR, FWD_SMEM>>>(0);
    k_gcoef<<<(NB*SPEC + 255)/256, 256>>>(bW, c1, c2, bu);
    k_fwd<<<NIMG, THR, FWD_SMEM>>>(1);
    k_ifft1<<<NIMG, THR, I1_SMEM>>>();
    k_ifft2<<<NIMG, THR, I2_SMEM>>>(gtr, gtx);
    k_final<<<1, 512>>>(out);
}

// round 13
// speedup vs baseline: 2.7149x; 1.5153x over previous
#include <cuda_runtime.h>
#include <math.h>
#include <cfloat>

#ifndef M_PI
#define M_PI 3.14159265358979323846
#endif

typedef unsigned long long u64;

#define NPIX 10000      // 100*100
#define SIDE 100
#define SS   200
#define KH   101        // rfft half-width
#define RR   360
#define NB   2
#define NIMG (NB*RR)    // 720
#define SPEC (SS*KH)    // 20200
#define EPSF 1e-12f
#define THR  416
#define NW   13

// ---------------- static device scratch ----------------
__device__ float  d_h1[4*9*NPIX];
__device__ float  d_feat[4*2*NPIX];
__device__ float2 d_rf[4*SPEC];            // [q][k1*101 + k2]
__device__ float2 d_G[4*SPEC];             // [q][k1*101 + k2]
__device__ float2 d_SF[NIMG*SPEC];         // [img][k1*101 + k2]
__device__ float2 d_Binv[NIMG*SPEC];       // [img][y*101 + k2]
__device__ float  d_blockmax[NIMG];
__device__ float  d_pos[NB];
__device__ float2 d_rtrig[RR];
__device__ ulonglong2 d_twd[SS];           // ((c,c),(s,s)), c=cos(2pi t/200), s=sin
__device__ u64        d_twp[SS];           // (c, s)

// ---------------- packed f32x2 helpers ----------------
__device__ __forceinline__ u64 pk2(float a, float b){
    u64 r; asm("mov.b64 %0, {%1, %2};" : "=l"(r) : "f"(a), "f"(b)); return r;
}
__device__ __forceinline__ float2 up2(u64 v){
    float2 r; asm("mov.b64 {%0, %1}, %2;" : "=f"(r.x), "=f"(r.y) : "l"(v)); return r;
}
__device__ __forceinline__ u64 ffma2(u64 a, u64 b, u64 c){
    u64 d; asm("fma.rn.f32x2 %0, %1, %2, %3;" : "=l"(d) : "l"(a), "l"(b), "l"(c)); return d;
}

// ---------------- init tables ----------------
__global__ void k_init(){
    int t = threadIdx.x;
    if (t < SS){
        double th = 2.0 * M_PI * (double)t / 200.0;
        float c = (float)cos(th), s = (float)sin(th);
        d_twd[t] = make_ulonglong2(pk2(c, c), pk2(s, s));
        d_twp[t] = pk2(c, s);
    }
    if (t < RR){
        double th = -M_PI + (double)t * (2.0 * M_PI / 360.0);
        d_rtrig[t] = make_float2((float)cos(th), (float)sin(th));
    }
}

// ---------------- conv1 + field norm ----------------
__global__ void k_conv1(const float* __restrict__ rec, const float* __restrict__ lig,
                        const float* __restrict__ w1){
    int idx = blockIdx.x*blockDim.x + threadIdx.x;
    if (idx >= 4*NPIX) return;
    int t = idx / NPIX, p = idx % NPIX;
    int y = p / SIDE, x = p % SIDE;
    const float* src = (t < 2) ? rec + t*NPIX : lig + (t-2)*NPIX;
    float acc[9];
#pragma unroll
    for (int o = 0; o < 9; o++) acc[o] = 0.f;
    for (int dy = 0; dy < 5; dy++){
        int yy = y + dy - 2; if (yy < 0 || yy >= SIDE) continue;
        for (int dx = 0; dx < 5; dx++){
            int xx = x + dx - 2; if (xx < 0 || xx >= SIDE) continue;
            float v = src[yy*SIDE + xx];
#pragma unroll
            for (int o = 0; o < 9; o++) acc[o] = fmaf(w1[o*25 + dy*5 + dx], v, acc[o]);
        }
    }
    float out[9];
    { float n = sqrtf(acc[0]*acc[0] + EPSF); out[0] = acc[0] * (n/(n+EPSF)); }
#pragma unroll
    for (int g = 0; g < 4; g++){
        int a = 1 + 2*g;
        float n = sqrtf(acc[a]*acc[a] + acc[a+1]*acc[a+1] + EPSF);
        float s = n/(n+EPSF);
        out[a] = acc[a]*s; out[a+1] = acc[a+1]*s;
    }
#pragma unroll
    for (int o = 0; o < 9; o++) d_h1[(t*9 + o)*NPIX + p] = out[o];
}

// ---------------- conv2 + field norm + features ----------------
__global__ void k_conv2(const float* __restrict__ w2){
    int idx = blockIdx.x*blockDim.x + threadIdx.x;
    if (idx >= 4*NPIX) return;
    int t = idx / NPIX, p = idx % NPIX;
    int y = p / SIDE, x = p % SIDE;
    float h[3] = {0.f, 0.f, 0.f};
    for (int ic = 0; ic < 9; ic++){
        const float* base = d_h1 + (t*9 + ic)*NPIX;
        for (int dy = 0; dy < 5; dy++){
            int yy = y + dy - 2; if (yy < 0 || yy >= SIDE) continue;
            for (int dx = 0; dx < 5; dx++){
                int xx = x + dx - 2; if (xx < 0 || xx >= SIDE) continue;
                float v = base[yy*SIDE + xx];
#pragma unroll
                for (int oc = 0; oc < 3; oc++)
                    h[oc] = fmaf(w2[(oc*9 + ic)*25 + dy*5 + dx], v, h[oc]);
            }
        }
    }
    float n0 = sqrtf(h[0]*h[0] + EPSF);
    float o0 = h[0] * (n0/(n0+EPSF));
    float n1 = sqrtf(h[1]*h[1] + h[2]*h[2] + EPSF);
    float s  = n1/(n1+EPSF);
    float o1 = h[1]*s, o2 = h[2]*s;
    d_feat[(t*2 + 0)*NPIX + p] = fabsf(o0);
    d_feat[(t*2 + 1)*NPIX + p] = sqrtf(o1*o1 + o2*o2 + EPSF);
}

// ---------------- bilinear rotation of one pixel ----------------
__device__ __forceinline__ float rot_pixel(const float* __restrict__ base,
                                           float ct, float st, int i, int j){
    const float c = 49.5f;
    float xs = (float)j - c, ys = (float)i - c;
    float xq =  ct*xs + st*ys + c;
    float yq = -st*xs + ct*ys + c;
    float x0f = floorf(xq), y0f = floorf(yq);
    float wx = xq - x0f, wy = yq - y0f;
    int x0 = (int)x0f, y0 = (int)y0f;
    float w00 = (1.f-wy)*(1.f-wx), w01 = (1.f-wy)*wx;
    float w10 = wy*(1.f-wx),       w11 = wy*wx;
    bool vx0 = (x0 >= 0 && x0 < SIDE), vx1 = (x0+1 >= 0 && x0+1 < SIDE);
    bool vy0 = (y0 >= 0 && y0 < SIDE), vy1 = (y0+1 >= 0 && y0+1 < SIDE);
    int cx0 = min(max(x0, 0), SIDE-1),   cx1 = min(max(x0+1, 0), SIDE-1);
    int cy0 = min(max(y0, 0), SIDE-1),   cy1 = min(max(y0+1, 0), SIDE-1);
    float g00 = (vy0 && vx0) ? base[cy0*SIDE + cx0] : 0.f;
    float g01 = (vy0 && vx1) ? base[cy0*SIDE + cx1] : 0.f;
    float g10 = (vy1 && vx0) ? base[cy1*SIDE + cx0] : 0.f;
    float g11 = (vy1 && vx1) ? base[cy1*SIDE + cx1] : 0.f;
    return g00*w00 + g01*w01 + g10*w10 + g11*w11;
}

// ---------------- forward rfft2, radix-2 in both stages ----------------
// One image pass: s_imgT [x][y] pitch 102 -> s_U [y][k2] pitch 103 -> spectrum out.
__device__ __forceinline__ void fwd_pass(const ulonglong2* __restrict__ s_twd,
                                         const float* __restrict__ s_imgT,
                                         u64* __restrict__ s_U,
                                         float2* __restrict__ gout,
                                         const float2* __restrict__ Gt,   // null: raw store
                                         int accum_ch,                    // 0: store, 1: accumulate
                                         int lane, int warp){
    // ---- stage A: U[y][k2] = sum_x v[y][x] e^{-2pi i k2 x/200}, radix-2 over x
    {
        int p0 = lane, p1 = lane + 32;
        int pc0 = min(p0, 49), pc1 = min(p1, 49);
        for (int tile = warp; tile < 26; tile += NW){
            int k2b = tile * 2;
            u64 EC[2][2], ES[2][2], OC[2][2], OS[2][2];
#pragma unroll
            for (int j = 0; j < 2; j++)
#pragma unroll
                for (int m = 0; m < 2; m++){ EC[j][m]=0; ES[j][m]=0; OC[j][m]=0; OS[j][m]=0; }
            int idx[2], step[2];
#pragma unroll
            for (int j = 0; j < 2; j++){ step[j] = (2*(k2b + j)) % 200; idx[j] = 0; }
            for (int u = 0; u < 50; u++){
                const u64* rE = (const u64*)(s_imgT + (2*u)*102);
                const u64* rO = (const u64*)(s_imgT + (2*u + 1)*102);
                u64 VE0 = rE[pc0], VE1 = rE[pc1];
                u64 VO0 = rO[pc0], VO1 = rO[pc1];
#pragma unroll
                for (int j = 0; j < 2; j++){
                    ulonglong2 w = s_twd[idx[j]];
                    EC[j][0] = ffma2(VE0, w.x, EC[j][0]);
                    ES[j][0] = ffma2(VE0, w.y, ES[j][0]);
                    EC[j][1] = ffma2(VE1, w.x, EC[j][1]);
                    ES[j][1] = ffma2(VE1, w.y, ES[j][1]);
                    OC[j][0] = ffma2(VO0, w.x, OC[j][0]);
                    OS[j][0] = ffma2(VO0, w.y, OS[j][0]);
                    OC[j][1] = ffma2(VO1, w.x, OC[j][1]);
                    OS[j][1] = ffma2(VO1, w.y, OS[j][1]);
                    idx[j] += step[j]; if (idx[j] >= 200) idx[j] -= 200;
                }
            }
#pragma unroll
            for (int j = 0; j < 2; j++){
                int k2p = k2b + j;
                if (k2p > 50) continue;
                float c = up2(s_twd[k2p].x).x;
                float s = up2(s_twd[k2p].y).x;
#pragma unroll
                for (int m = 0; m < 2; m++){
                    int p = lane + 32*m;
                    if (p >= 50) continue;
                    float2 ec = up2(EC[j][m]), es = up2(ES[j][m]);
                    float2 oc = up2(OC[j][m]), os = up2(OS[j][m]);
                    // lane-pair component 0 (row 2p), component 1 (row 2p+1)
                    float t1a = c*oc.x - s*os.x, t2a = c*os.x + s*oc.x;
                    float t1b = c*oc.y - s*os.y, t2b = c*os.y + s*oc.y;
                    s_U[(2*p    )*103 + k2p]       = pk2(ec.x + t1a, -(es.x + t2a));
                    s_U[(2*p + 1)*103 + k2p]       = pk2(ec.y + t1b, -(es.y + t2b));
                    s_U[(2*p    )*103 + 100 - k2p] = pk2(ec.x - t1a,  es.x - t2a);
                    s_U[(2*p + 1)*103 + 100 - k2p] = pk2(ec.y - t1b,  es.y - t2b);
                }
            }
        }
    }
    __syncthreads();

    // ---- stage B: C[k1][k2] = sum_y U[y][k2] e^{-2pi i k1 y/200}, radix-2 over y
    {
        int kc[4];
#pragma unroll
        for (int m = 0; m < 4; m++) kc[m] = min(lane + 32*m, 100);
        for (int tile = warp; tile < 26; tile += NW){
            int k1b = tile * 2;
            u64 aE1[2][4], aE2[2][4], aO1[2][4], aO2[2][4];
#pragma unroll
            for (int j = 0; j < 2; j++)
#pragma unroll
                for (int m = 0; m < 4; m++){ aE1[j][m]=0; aE2[j][m]=0; aO1[j][m]=0; aO2[j][m]=0; }
            int idx[2], step[2];
#pragma unroll
            for (int j = 0; j < 2; j++){ step[j] = (2*(k1b + j)) % 200; idx[j] = 0; }
            for (int u = 0; u < 50; u++){
                const u64* rE = s_U + (2*u)*103;
                const u64* rO = s_U + (2*u + 1)*103;
                u64 DE0 = rE[kc[0]], DE1 = rE[kc[1]], DE2 = rE[kc[2]], DE3 = rE[kc[3]];
                u64 DO0 = rO[kc[0]], DO1 = rO[kc[1]], DO2 = rO[kc[2]], DO3 = rO[kc[3]];
#pragma unroll
                for (int j = 0; j < 2; j++){
                    ulonglong2 w = s_twd[idx[j]];
                    aE1[j][0] = ffma2(DE0, w.x, aE1[j][0]);
                    aE2[j][0] = ffma2(DE0, w.y, aE2[j][0]);
                    aE1[j][1] = ffma2(DE1, w.x, aE1[j][1]);
                    aE2[j][1] = ffma2(DE1, w.y, aE2[j][1]);
                    aE1[j][2] = ffma2(DE2, w.x, aE1[j][2]);
                    aE2[j][2] = ffma2(DE2, w.y, aE2[j][2]);
                    aE1[j][3] = ffma2(DE3, w.x, aE1[j][3]);
                    aE2[j][3] = ffma2(DE3, w.y, aE2[j][3]);
                    aO1[j][0] = ffma2(DO0, w.x, aO1[j][0]);
                    aO2[j][0] = ffma2(DO0, w.y, aO2[j][0]);
                    aO1[j][1] = ffma2(DO1, w.x, aO1[j][1]);
                    aO2[j][1] = ffma2(DO1, w.y, aO2[j][1]);
                    aO1[j][2] = ffma2(DO2, w.x, aO1[j][2]);
                    aO2[j][2] = ffma2(DO2, w.y, aO2[j][2]);
                    aO1[j][3] = ffma2(DO3, w.x, aO1[j][3]);
                    aO2[j][3] = ffma2(DO3, w.y, aO2[j][3]);
                    idx[j] += step[j]; if (idx[j] >= 200) idx[j] -= 200;
                }
            }
#pragma unroll
            for (int j = 0; j < 2; j++){
                int k1p = k1b + j;
                if (k1p > 50) continue;
                float wc = up2(s_twd[k1p].x).x;
                float ws = up2(s_twd[k1p].y).x;
                bool mir = (k1p >= 1 && k1p <= 49);
#pragma unroll
                for (int m = 0; m < 4; m++){
                    int k2 = lane + 32*m;
                    if (k2 > 100) continue;
                    float2 pE = up2(aE1[j][m]), qE = up2(aE2[j][m]);
                    float2 pO = up2(aO1[j][m]), qO = up2(aO2[j][m]);
                    float2 E1 = make_float2(pE.x + qE.y, pE.y - qE.x);
                    float2 E2 = make_float2(pE.x - qE.y, pE.y + qE.x);
                    float2 O1 = make_float2(pO.x + qO.y, pO.y - qO.x);
                    float2 O2 = make_float2(pO.x - qO.y, pO.y + qO.x);
                    float2 T1 = make_float2( wc*O1.x + ws*O1.y,   wc*O1.y - ws*O1.x);
                    float2 T2 = make_float2(-(wc*O2.x - ws*O2.y), -(wc*O2.y + ws*O2.x));
                    float2 C[4];
                    int    ko[4];
                    C[0] = make_float2(E1.x + T1.x, E1.y + T1.y); ko[0] = k1p;
                    C[1] = make_float2(E1.x - T1.x, E1.y - T1.y); ko[1] = k1p + 100;
                    C[2] = make_float2(E2.x + T2.x, E2.y + T2.y); ko[2] = 100 - k1p;
                    C[3] = make_float2(E2.x - T2.x, E2.y - T2.y); ko[3] = 200 - k1p;
                    int nout = mir ? 4 : 2;
#pragma unroll
                    for (int t = 0; t < 4; t++){
                        if (t >= nout) break;
                        int o = ko[t]*101 + k2;
                        if (Gt){
                            float2 g = Gt[o];
                            float2 v = make_float2(C[t].x*g.x - C[t].y*g.y,
                                                   C[t].x*g.y + C[t].y*g.x);
                            if (accum_ch){ float2 pv = gout[o]; v.x += pv.x; v.y += pv.y; }
                            gout[o] = v;
                        } else {
                            gout[o] = C[t];
                        }
                    }
                }
            }
        }
    }
}

// rec mode: grid=4, block q handles one (b,ch) image from d_feat, raw spectrum to d_rf
__global__ void __launch_bounds__(THR, 1) k_fwd_rec(){
    extern __shared__ char sm[];
    ulonglong2* s_twd  = (ulonglong2*)sm;
    float*      s_imgT = (float*)(sm + 3200);
    u64*        s_U    = (u64*)(sm + 3200 + 40800);
    int tid = threadIdx.x, lane = tid & 31, warp = tid >> 5;
    int q = blockIdx.x;
    for (int i = tid; i < SS; i += THR) s_twd[i] = d_twd[i];
    const float* src = d_feat + q*NPIX;
    for (int i = tid; i < NPIX; i += THR){
        int yy = i / 100, xx = i - yy*100;
        s_imgT[xx*102 + yy] = src[i];
    }
    __syncthreads();
    fwd_pass(s_twd, s_imgT, s_U, d_rf + q*SPEC, 0, 0, lane, warp);
}

// lig mode: grid=NIMG, per-block rotation fused, combine with d_G into d_SF
__global__ void __launch_bounds__(THR, 1) k_fwd_lig(){
    extern __shared__ char sm[];
    ulonglong2* s_twd  = (ulonglong2*)sm;
    float*      s_imgT = (float*)(sm + 3200);
    u64*        s_U    = (u64*)(sm + 3200 + 40800);
    int tid = threadIdx.x, lane = tid & 31, warp = tid >> 5;
    int img = blockIdx.x;
    int b = img / RR, r = img % RR;
    float2 cs = d_rtrig[r];
    for (int i = tid; i < SS; i += THR) s_twd[i] = d_twd[i];
    for (int ch = 0; ch < 2; ch++){
        const float* base = d_feat + ((2 + b)*2 + ch)*NPIX;
        for (int i = tid; i < NPIX; i += THR){
            int yy = i / 100, xx = i - yy*100;
            s_imgT[xx*102 + yy] = rot_pixel(base, cs.x, cs.y, yy, xx);
        }
        __syncthreads();
        fwd_pass(s_twd, s_imgT, s_U, d_SF + img*SPEC, d_G + (b*2 + ch)*SPEC, ch,
                 lane, warp);
        __syncthreads();
    }
}

// ---------------- combine coefficients ----------------
__global__ void k_gcoef(const float* __restrict__ bW, const float* __restrict__ c1,
                        const float* __restrict__ c2, const float* __restrict__ bu){
    int idx = blockIdx.x*blockDim.x + threadIdx.x;
    if (idx >= NB*SPEC) return;
    int b = idx / SPEC, i = idx % SPEC;
    float2 rb = d_rf[(b*2 + 0)*SPEC + i];
    float2 rB = d_rf[(b*2 + 1)*SPEC + i];
    float2 crb = make_float2(rb.x, -rb.y);
    float2 crB = make_float2(rB.x, -rB.y);
    float wb = bW[0], wc1 = c1[0], wc2 = c2[0], wk = bu[0];
    d_G[(b*2 + 0)*SPEC + i] = make_float2(wb*crb.x + wc2*crB.x,  wb*crb.y + wc2*crB.y);
    d_G[(b*2 + 1)*SPEC + i] = make_float2(wc1*crb.x - wk*crB.x,  wc1*crb.y - wk*crB.y);
}

// ---------------- inverse stage 1 over k1, radix-2 + y-pairing (unchanged from R12) ----------
__device__ __forceinline__ void ifft1_phase(const u64* __restrict__ s_S,
    const ulonglong2* __restrict__ s_twd, int img, int warp, int lane, int ph){
    int yb = warp * 4;
    int k2m[2], k2c[2];
#pragma unroll
    for (int m = 0; m < 2; m++){
        k2m[m] = ph*64 + lane + 32*m;
        k2c[m] = min(k2m[m], 100);
    }
    u64 aE1[4][2], aE2[4][2], aO1[4][2], aO2[4][2];
#pragma unroll
    for (int j = 0; j < 4; j++)
#pragma unroll
        for (int m = 0; m < 2; m++){ aE1[j][m]=0; aE2[j][m]=0; aO1[j][m]=0; aO2[j][m]=0; }
    int idx[4], step[4];
#pragma unroll
    for (int j = 0; j < 4; j++){ step[j] = (2*(yb + j)) % 200; idx[j] = 0; }
    for (int mm = 0; mm < 100; mm++){
        const u64* rE = s_S + (2*mm)*101;
        const u64* rO = s_S + (2*mm + 1)*101;
        u64 DE0 = rE[k2c[0]], DE1 = rE[k2c[1]];
        u64 DO0 = rO[k2c[0]], DO1 = rO[k2c[1]];
#pragma unroll
        for (int j = 0; j < 4; j++){
            ulonglong2 w = s_twd[idx[j]];
            aE1[j][0] = ffma2(DE0, w.x, aE1[j][0]);
            aE2[j][0] = ffma2(DE0, w.y, aE2[j][0]);
            aE1[j][1] = ffma2(DE1, w.x, aE1[j][1]);
            aE2[j][1] = ffma2(DE1, w.y, aE2[j][1]);
            aO1[j][0] = ffma2(DO0, w.x, aO1[j][0]);
            aO2[j][0] = ffma2(DO0, w.y, aO2[j][0]);
            aO1[j][1] = ffma2(DO1, w.x, aO1[j][1]);
            aO2[j][1] = ffma2(DO1, w.y, aO2[j][1]);
            idx[j] += step[j]; if (idx[j] >= 200) idx[j] -= 200;
        }
    }
    float2* base = d_Binv + img*SPEC;
#pragma unroll
    for (int j = 0; j < 4; j++){
        int yp = yb + j;
        if (yp > 50) continue;
        float c1 = up2(s_twd[yp].x).x;
        float s1 = up2(s_twd[yp].y).x;
#pragma unroll
        for (int m = 0; m < 2; m++){
            int k2 = k2m[m];
            if (k2 > 100) continue;
            float2 a1 = up2(aE1[j][m]), a2 = up2(aE2[j][m]);
            float2 E1 = make_float2(a1.x - a2.y, a2.x + a1.y);
            float2 E2 = make_float2(a1.x + a2.y, a1.y - a2.x);
            float2 o1 = up2(aO1[j][m]), o2 = up2(aO2[j][m]);
            float2 O1 = make_float2(o1.x - o2.y, o2.x + o1.y);
            float2 O2 = make_float2(o1.x + o2.y, o1.y - o2.x);
            float2 T1 = make_float2(c1*O1.x - s1*O1.y,  c1*O1.y + s1*O1.x);
            float2 T2 = make_float2(-c1*O2.x - s1*O2.y, -c1*O2.y + s1*O2.x);
            float sc = (k2 == 0 || k2 == 100) ? 2.5e-5f : 5.0e-5f;
            base[yp*101 + k2]        = make_float2((E1.x + T1.x)*sc, (E1.y + T1.y)*sc);
            base[(yp + 100)*101 + k2] = make_float2((E1.x - T1.x)*sc, (E1.y - T1.y)*sc);
            base[(100 - yp)*101 + k2] = make_float2((E2.x + T2.x)*sc, (E2.y + T2.y)*sc);
            if (yp >= 1)
                base[(200 - yp)*101 + k2] = make_float2((E2.x - T2.x)*sc, (E2.y - T2.y)*sc);
        }
    }
}

__global__ void __launch_bounds__(THR, 1) k_ifft1(){
    extern __shared__ char sm[];
    ulonglong2* s_twd = (ulonglong2*)sm;
    u64*        s_S   = (u64*)(sm + 3200);
    int tid = threadIdx.x, lane = tid & 31, warp = tid >> 5;
    int img = blockIdx.x;
    const u64* src = (const u64*)(d_SF + img*SPEC);
    for (int i = tid; i < SS; i += THR) s_twd[i] = d_twd[i];
    for (int i = tid; i < SPEC; i += THR) s_S[i] = src[i];
    __syncthreads();
    ifft1_phase(s_S, s_twd, img, warp, lane, 0);
    ifft1_phase(s_S, s_twd, img, warp, lane, 1);
}

// ---------------- inverse stage 2 over k2, radix-2 + x quad-pairing (unchanged) ----------
template<int MCNT>
__device__ __forceinline__ void ifft2r_tile(const u64* __restrict__ s_B,
    const u64* __restrict__ s_twp, const ulonglong2* __restrict__ s_twd,
    int xt, int ybase, int lane, float& lm, int r, int gtr, int ty, int tx, int b){
    int xb = xt * 4;
    int ym[MCNT], yc[MCNT]; bool vy[MCNT];
#pragma unroll
    for (int m = 0; m < MCNT; m++){
        ym[m] = ybase + lane + 32*m;
        vy[m] = ym[m] < 200;
        yc[m] = min(ym[m], 199);
    }
    u64 aE[4][MCNT], aO1[4][MCNT], aO2[4][MCNT];
#pragma unroll
    for (int j = 0; j < 4; j++)
#pragma unroll
        for (int m = 0; m < MCNT; m++){ aE[j][m]=0; aO1[j][m]=0; aO2[j][m]=0; }
    int idx[4], step[4];
#pragma unroll
    for (int j = 0; j < 4; j++){ step[j] = (2*(xb + j)) % 200; idx[j] = 0; }
    for (int mm = 0; mm < 50; mm++){
        const u64* rE = s_B + (2*mm)*200;
        const u64* rO = s_B + (2*mm + 1)*200;
        u64 BE[MCNT], BO[MCNT];
#pragma unroll
        for (int m = 0; m < MCNT; m++){ BE[m] = rE[yc[m]]; BO[m] = rO[yc[m]]; }
#pragma unroll
        for (int j = 0; j < 4; j++){
            u64 wp = s_twp[idx[j]];
            ulonglong2 wd = s_twd[idx[j]];
#pragma unroll
            for (int m = 0; m < MCNT; m++){
                aE[j][m]  = ffma2(BE[m], wp,   aE[j][m]);
                aO1[j][m] = ffma2(BO[m], wd.x, aO1[j][m]);
                aO2[j][m] = ffma2(BO[m], wd.y, aO2[j][m]);
            }
            idx[j] += step[j]; if (idx[j] >= 200) idx[j] -= 200;
        }
    }
    {
        const u64* rE = s_B + 100*200;
        u64 BE[MCNT];
#pragma unroll
        for (int m = 0; m < MCNT; m++) BE[m] = rE[yc[m]];
#pragma unroll
        for (int j = 0; j < 4; j++){
            u64 wp = s_twp[idx[j]];
#pragma unroll
            for (int m = 0; m < MCNT; m++) aE[j][m] = ffma2(BE[m], wp, aE[j][m]);
        }
    }
#pragma unroll
    for (int j = 0; j < 4; j++){
        int xp = xb + j;
        if (xp > 50) continue;
        float2 w1 = up2(s_twp[xp]);
#pragma unroll
        for (int m = 0; m < MCNT; m++){
            if (!vy[m]) continue;
            float2 ae = up2(aE[j][m]);
            float vE1 = ae.x - ae.y;
            float vE2 = ae.x + ae.y;
            float2 a1 = up2(aO1[j][m]), a2 = up2(aO2[j][m]);
            float POr = a1.x - a2.y, POi = a2.x + a1.y;
            float P2r = a1.x + a2.y, P2i = a1.y - a2.x;
            float t1 =  w1.x*POr - w1.y*POi;
            float t2 = -w1.x*P2r - w1.y*P2i;
            float v1 = vE1 + t1;
            float v2 = vE1 - t1;
            float v3 = vE2 + t2;
            float v4 = vE2 - t2;
            lm = fmaxf(lm, fmaxf(v1, v2));
            lm = fmaxf(lm, v3);
            if (xp >= 1) lm = fmaxf(lm, v4);
            if (r == gtr && ym[m] == ty){
                if (xp == tx)               d_pos[b] = v1;
                if (xp + 100 == tx)         d_pos[b] = v2;
                if (100 - xp == tx)         d_pos[b] = v3;
                if (xp >= 1 && 200 - xp == tx) d_pos[b] = v4;
            }
        }
    }
}

__global__ void __launch_bounds__(THR, 1) k_ifft2(const int* __restrict__ gt_rot,
                                                  const int* __restrict__ gt_txy){
    extern __shared__ char sm[];
    u64*        s_twp = (u64*)sm;
    ulonglong2* s_twd = (ulonglong2*)(sm + 1600);
    u64*        s_B   = (u64*)(sm + 4800);
    __shared__ float red[512];
    int tid = threadIdx.x, lane = tid & 31, warp = tid >> 5;
    int img = blockIdx.x;
    int b = img / RR, r = img % RR;
    const u64* src = (const u64*)(d_Binv + img*SPEC);
    for (int i = tid; i < SS; i += THR){ s_twp[i] = d_twp[i]; s_twd[i] = d_twd[i]; }
    for (int i = tid; i < SPEC; i += THR){
        int y = i / 101, k2 = i - y*101;
        s_B[k2*200 + y] = src[i];
    }
    __syncthreads();

    int gtr = gt_rot[b];
    int ty = gt_txy[2*b], tx = gt_txy[2*b + 1];
    float lm = -FLT_MAX;

    ifft2r_tile<4>(s_B, s_twp, s_twd, warp, 0,   lane, lm, r, gtr, ty, tx, b);
    ifft2r_tile<3>(s_B, s_twp, s_twd, warp, 128, lane, lm, r, gtr, ty, tx, b);

    red[tid] = lm;
    if (tid < 512 - THR) red[THR + tid] = -FLT_MAX;
    __syncthreads();
    for (int s = 256; s > 0; s >>= 1){
        if (tid < s) red[tid] = fmaxf(red[tid], red[tid + s]);
        __syncthreads();
    }
    if (tid == 0) d_blockmax[img] = red[0];
}

// ---------------- final reduction + loss ----------------
__global__ void k_final(float* __restrict__ out){
    __shared__ float r0[512], r1[512];
    int tid = threadIdx.x;
    float m0 = -FLT_MAX, m1 = -FLT_MAX;
    if (tid < RR){ m0 = d_blockmax[tid]; m1 = d_blockmax[RR + tid]; }
    r0[tid] = m0; r1[tid] = m1;
    __syncthreads();
    for (int s = 256; s > 0; s >>= 1){
        if (tid < s){ r0[tid] = fmaxf(r0[tid], r0[tid+s]); r1[tid] = fmaxf(r1[tid], r1[tid+s]); }
        __syncthreads();
    }
    if (tid == 0){
        float p0 = d_pos[0], p1 = d_pos[1];
        float b0 = r0[0], b1 = r1[0];
        out[0] = 0.5f * ((p0 + p0*p0) + (p1 + p1*p1));
        out[1] = 0.5f * ((-b0 + b0*b0) + (-b1 + b1*b1));
    }
}

// ---------------- launch ----------------
extern "C" void kernel_launch(void* const* d_in, const int* in_sizes, int n_in,
                              void* d_out, int out_size){
    const float* rec = (const float*)d_in[0];
    const float* lig = (const float*)d_in[1];
    const float* w1  = (const float*)d_in[2];
    const float* w2  = (const float*)d_in[3];
    const float* bW  = (const float*)d_in[4];
    const float* c1  = (const float*)d_in[5];
    const float* c2  = (const float*)d_in[6];
    const float* bu  = (const float*)d_in[7];
    const int*   gtr = (const int*)d_in[8];
    const int*   gtx = (const int*)d_in[9];
    float* out = (float*)d_out;

    const int FWD_SMEM = 3200 + 40800 + 82400;     // 126400
    const int I1_SMEM  = 3200 + SPEC*8;            // 164800
    const int I2_SMEM  = 4800 + SPEC*8;            // 166400
    cudaFuncSetAttribute(k_fwd_rec, cudaFuncAttributeMaxDynamicSharedMemorySize, FWD_SMEM);
    cudaFuncSetAttribute(k_fwd_lig, cudaFuncAttributeMaxDynamicSharedMemorySize, FWD_SMEM);
    cudaFuncSetAttribute(k_ifft1,   cudaFuncAttributeMaxDynamicSharedMemorySize, I1_SMEM);
    cudaFuncSetAttribute(k_ifft2,   cudaFuncAttributeMaxDynamicSharedMemorySize, I2_SMEM);

    k_init<<<1, 512>>>();
    k_conv1<<<(4*NPIX + 255)/256, 256>>>(rec, lig, w1);
    k_conv2<<<(4*NPIX + 255)/256, 256>>>(w2);
    k_fwd_rec<<<4, THR, FWD_SMEM>>>();
    k_gcoef<<<(NB*SPEC + 255)/256, 256>>>(bW, c1, c2, bu);
    k_fwd_lig<<<NIMG, THR, FWD_SMEM>>>();
    k_ifft1<<<NIMG, THR, I1_SMEM>>>();
    k_ifft2<<<NIMG, THR, I2_SMEM>>>(gtr, gtx);
    k_final<<<1, 512>>>(out);
}

// round 14
// speedup vs baseline: 3.3914x; 1.2492x over previous
#include <cuda_runtime.h>
#include <math.h>
#include <cfloat>

#ifndef M_PI
#define M_PI 3.14159265358979323846
#endif

typedef unsigned long long u64;

#define NPIX 10000      // 100*100
#define SIDE 100
#define SS   200
#define KH   101        // rfft half-width
#define RR   360
#define NB   2
#define NIMG (NB*RR)    // 720
#define SPEC (SS*KH)    // 20200
#define EPSF 1e-12f
#define THR  416
#define NW   13

// ---------------- static device scratch ----------------
__device__ float  d_h1[4*9*NPIX];
__device__ float  d_feat[4*2*NPIX];
__device__ float2 d_rf[4*SPEC];            // [q][k1*101 + k2]
__device__ float2 d_G[4*SPEC];             // [q][k1*101 + k2]
__device__ float2 d_SF[NIMG*SPEC];         // [img][k1*101 + k2]
__device__ float2 d_Binv[NIMG*SPEC];       // [img][y*101 + k2]
__device__ float  d_blockmax[NIMG];
__device__ float  d_pos[NB];
__device__ float2 d_rtrig[RR];
__device__ ulonglong2 d_twd[SS];           // ((c,c),(s,s)), c=cos(2pi t/200), s=sin
__device__ u64        d_twp[SS];           // (c, s)

// ---------------- packed f32x2 helpers ----------------
__device__ __forceinline__ u64 pk2(float a, float b){
    u64 r; asm("mov.b64 %0, {%1, %2};" : "=l"(r) : "f"(a), "f"(b)); return r;
}
__device__ __forceinline__ float2 up2(u64 v){
    float2 r; asm("mov.b64 {%0, %1}, %2;" : "=f"(r.x), "=f"(r.y) : "l"(v)); return r;
}
__device__ __forceinline__ u64 ffma2(u64 a, u64 b, u64 c){
    u64 d; asm("fma.rn.f32x2 %0, %1, %2, %3;" : "=l"(d) : "l"(a), "l"(b), "l"(c)); return d;
}
__device__ __forceinline__ float2 cmulf(float2 a, float2 b){
    return make_float2(a.x*b.x - a.y*b.y, a.x*b.y + a.y*b.x);
}
__device__ __forceinline__ float2 caddf(float2 a, float2 b){ return make_float2(a.x+b.x, a.y+b.y); }
__device__ __forceinline__ float2 csubf(float2 a, float2 b){ return make_float2(a.x-b.x, a.y-b.y); }

// ---------------- init tables ----------------
__global__ void k_init(){
    int t = threadIdx.x;
    if (t < SS){
        double th = 2.0 * M_PI * (double)t / 200.0;
        float c = (float)cos(th), s = (float)sin(th);
        d_twd[t] = make_ulonglong2(pk2(c, c), pk2(s, s));
        d_twp[t] = pk2(c, s);
    }
    if (t < RR){
        double th = -M_PI + (double)t * (2.0 * M_PI / 360.0);
        d_rtrig[t] = make_float2((float)cos(th), (float)sin(th));
    }
}

// ---------------- conv1 + field norm ----------------
__global__ void k_conv1(const float* __restrict__ rec, const float* __restrict__ lig,
                        const float* __restrict__ w1){
    int idx = blockIdx.x*blockDim.x + threadIdx.x;
    if (idx >= 4*NPIX) return;
    int t = idx / NPIX, p = idx % NPIX;
    int y = p / SIDE, x = p % SIDE;
    const float* src = (t < 2) ? rec + t*NPIX : lig + (t-2)*NPIX;
    float acc[9];
#pragma unroll
    for (int o = 0; o < 9; o++) acc[o] = 0.f;
    for (int dy = 0; dy < 5; dy++){
        int yy = y + dy - 2; if (yy < 0 || yy >= SIDE) continue;
        for (int dx = 0; dx < 5; dx++){
            int xx = x + dx - 2; if (xx < 0 || xx >= SIDE) continue;
            float v = src[yy*SIDE + xx];
#pragma unroll
            for (int o = 0; o < 9; o++) acc[o] = fmaf(w1[o*25 + dy*5 + dx], v, acc[o]);
        }
    }
    float out[9];
    { float n = sqrtf(acc[0]*acc[0] + EPSF); out[0] = acc[0] * (n/(n+EPSF)); }
#pragma unroll
    for (int g = 0; g < 4; g++){
        int a = 1 + 2*g;
        float n = sqrtf(acc[a]*acc[a] + acc[a+1]*acc[a+1] + EPSF);
        float s = n/(n+EPSF);
        out[a] = acc[a]*s; out[a+1] = acc[a+1]*s;
    }
#pragma unroll
    for (int o = 0; o < 9; o++) d_h1[(t*9 + o)*NPIX + p] = out[o];
}

// ---------------- conv2 + field norm + features ----------------
__global__ void k_conv2(const float* __restrict__ w2){
    int idx = blockIdx.x*blockDim.x + threadIdx.x;
    if (idx >= 4*NPIX) return;
    int t = idx / NPIX, p = idx % NPIX;
    int y = p / SIDE, x = p % SIDE;
    float h[3] = {0.f, 0.f, 0.f};
    for (int ic = 0; ic < 9; ic++){
        const float* base = d_h1 + (t*9 + ic)*NPIX;
        for (int dy = 0; dy < 5; dy++){
            int yy = y + dy - 2; if (yy < 0 || yy >= SIDE) continue;
            for (int dx = 0; dx < 5; dx++){
                int xx = x + dx - 2; if (xx < 0 || xx >= SIDE) continue;
                float v = base[yy*SIDE + xx];
#pragma unroll
                for (int oc = 0; oc < 3; oc++)
                    h[oc] = fmaf(w2[(oc*9 + ic)*25 + dy*5 + dx], v, h[oc]);
            }
        }
    }
    float n0 = sqrtf(h[0]*h[0] + EPSF);
    float o0 = h[0] * (n0/(n0+EPSF));
    float n1 = sqrtf(h[1]*h[1] + h[2]*h[2] + EPSF);
    float s  = n1/(n1+EPSF);
    float o1 = h[1]*s, o2 = h[2]*s;
    d_feat[(t*2 + 0)*NPIX + p] = fabsf(o0);
    d_feat[(t*2 + 1)*NPIX + p] = sqrtf(o1*o1 + o2*o2 + EPSF);
}

// ---------------- bilinear rotation of one pixel ----------------
__device__ __forceinline__ float rot_pixel(const float* __restrict__ base,
                                           float ct, float st, int i, int j){
    const float c = 49.5f;
    float xs = (float)j - c, ys = (float)i - c;
    float xq =  ct*xs + st*ys + c;
    float yq = -st*xs + ct*ys + c;
    float x0f = floorf(xq), y0f = floorf(yq);
    float wx = xq - x0f, wy = yq - y0f;
    int x0 = (int)x0f, y0 = (int)y0f;
    float w00 = (1.f-wy)*(1.f-wx), w01 = (1.f-wy)*wx;
    float w10 = wy*(1.f-wx),       w11 = wy*wx;
    bool vx0 = (x0 >= 0 && x0 < SIDE), vx1 = (x0+1 >= 0 && x0+1 < SIDE);
    bool vy0 = (y0 >= 0 && y0 < SIDE), vy1 = (y0+1 >= 0 && y0+1 < SIDE);
    int cx0 = min(max(x0, 0), SIDE-1),   cx1 = min(max(x0+1, 0), SIDE-1);
    int cy0 = min(max(y0, 0), SIDE-1),   cy1 = min(max(y0+1, 0), SIDE-1);
    float g00 = (vy0 && vx0) ? base[cy0*SIDE + cx0] : 0.f;
    float g01 = (vy0 && vx1) ? base[cy0*SIDE + cx1] : 0.f;
    float g10 = (vy1 && vx0) ? base[cy1*SIDE + cx0] : 0.f;
    float g11 = (vy1 && vx1) ? base[cy1*SIDE + cx1] : 0.f;
    return g00*w00 + g01*w01 + g10*w10 + g11*w11;
}

// ---------------- forward rfft2: stage A radix-2 (R13), stage B radix-4 ----------------
// s_imgT [x][y] pitch 102 -> s_U [y][k2] pitch 103 -> spectrum out.
__device__ __forceinline__ void fwd_pass(const ulonglong2* __restrict__ s_twd,
                                         const float* __restrict__ s_imgT,
                                         u64* __restrict__ s_U,
                                         float2* __restrict__ gout,
                                         const float2* __restrict__ Gt,   // null: raw store
                                         int accum_ch,                    // 0: store, 1: accumulate
                                         int lane, int warp){
    // ---- stage A: U[y][k2] = sum_x v[y][x] e^{-2pi i k2 x/200}, radix-2 over x
    {
        int p0 = lane, p1 = lane + 32;
        int pc0 = min(p0, 49), pc1 = min(p1, 49);
        for (int tile = warp; tile < 26; tile += NW){
            int k2b = tile * 2;
            u64 EC[2][2], ES[2][2], OC[2][2], OS[2][2];
#pragma unroll
            for (int j = 0; j < 2; j++)
#pragma unroll
                for (int m = 0; m < 2; m++){ EC[j][m]=0; ES[j][m]=0; OC[j][m]=0; OS[j][m]=0; }
            int idx[2], step[2];
#pragma unroll
            for (int j = 0; j < 2; j++){ step[j] = (2*(k2b + j)) % 200; idx[j] = 0; }
            for (int u = 0; u < 50; u++){
                const u64* rE = (const u64*)(s_imgT + (2*u)*102);
                const u64* rO = (const u64*)(s_imgT + (2*u + 1)*102);
                u64 VE0 = rE[pc0], VE1 = rE[pc1];
                u64 VO0 = rO[pc0], VO1 = rO[pc1];
#pragma unroll
                for (int j = 0; j < 2; j++){
                    ulonglong2 w = s_twd[idx[j]];
                    EC[j][0] = ffma2(VE0, w.x, EC[j][0]);
                    ES[j][0] = ffma2(VE0, w.y, ES[j][0]);
                    EC[j][1] = ffma2(VE1, w.x, EC[j][1]);
                    ES[j][1] = ffma2(VE1, w.y, ES[j][1]);
                    OC[j][0] = ffma2(VO0, w.x, OC[j][0]);
                    OS[j][0] = ffma2(VO0, w.y, OS[j][0]);
                    OC[j][1] = ffma2(VO1, w.x, OC[j][1]);
                    OS[j][1] = ffma2(VO1, w.y, OS[j][1]);
                    idx[j] += step[j]; if (idx[j] >= 200) idx[j] -= 200;
                }
            }
#pragma unroll
            for (int j = 0; j < 2; j++){
                int k2p = k2b + j;
                if (k2p > 50) continue;
                float c = up2(s_twd[k2p].x).x;
                float s = up2(s_twd[k2p].y).x;
#pragma unroll
                for (int m = 0; m < 2; m++){
                    int p = lane + 32*m;
                    if (p >= 50) continue;
                    float2 ec = up2(EC[j][m]), es = up2(ES[j][m]);
                    float2 oc = up2(OC[j][m]), os = up2(OS[j][m]);
                    float t1a = c*oc.x - s*os.x, t2a = c*os.x + s*oc.x;
                    float t1b = c*oc.y - s*os.y, t2b = c*os.y + s*oc.y;
                    s_U[(2*p    )*103 + k2p]       = pk2(ec.x + t1a, -(es.x + t2a));
                    s_U[(2*p + 1)*103 + k2p]       = pk2(ec.y + t1b, -(es.y + t2b));
                    s_U[(2*p    )*103 + 100 - k2p] = pk2(ec.x - t1a,  es.x - t2a);
                    s_U[(2*p + 1)*103 + 100 - k2p] = pk2(ec.y - t1b,  es.y - t2b);
                }
            }
        }
    }
    __syncthreads();

    // ---- stage B: C[k1][k2] = sum_y U[y][k2] e^{-2pi i k1 y/200}, radix-4 over y
    // Sub-DFTs G_q (rows y=4u+q, q=0..3), period 50 in k1.
    // E = G0 + ubar*G2, O = G1 + ubar*G3, C(k1) = E + wbar*O, C(k1+100) = E - wbar*O.
    {
        int kpp0 = warp * 2;    // k1'' = kpp0 + j, j=0..1 (0..25)
        for (int ph = 0; ph < 2; ph++){
            int k2m[2], k2c[2];
#pragma unroll
            for (int m = 0; m < 2; m++){
                k2m[m] = ph*64 + lane + 32*m;
                k2c[m] = min(k2m[m], 100);
            }
            u64 aC[4][2][2], aS[4][2][2];   // [q][j][m]
#pragma unroll
            for (int q = 0; q < 4; q++)
#pragma unroll
                for (int j = 0; j < 2; j++)
#pragma unroll
                    for (int m = 0; m < 2; m++){ aC[q][j][m] = 0; aS[q][j][m] = 0; }
            int idx[2], step[2];
#pragma unroll
            for (int j = 0; j < 2; j++){ step[j] = (4*(kpp0 + j)) % 200; idx[j] = 0; }
            int off = 0;
            for (int u = 0; u < 25; u++){
                u64 D[4][2];
#pragma unroll
                for (int q = 0; q < 4; q++){
                    D[q][0] = s_U[off + q*103 + k2c[0]];
                    D[q][1] = s_U[off + q*103 + k2c[1]];
                }
#pragma unroll
                for (int j = 0; j < 2; j++){
                    ulonglong2 w = s_twd[idx[j]];
#pragma unroll
                    for (int q = 0; q < 4; q++){
                        aC[q][j][0] = ffma2(D[q][0], w.x, aC[q][j][0]);
                        aS[q][j][0] = ffma2(D[q][0], w.y, aS[q][j][0]);
                        aC[q][j][1] = ffma2(D[q][1], w.x, aC[q][j][1]);
                        aS[q][j][1] = ffma2(D[q][1], w.y, aS[q][j][1]);
                    }
                    idx[j] += step[j]; if (idx[j] >= 200) idx[j] -= 200;
                }
                off += 4*103;
            }
#pragma unroll
            for (int j = 0; j < 2; j++){
                int kpp = kpp0 + j;                 // 0..25
                float C = up2(s_twd[kpp].x).x;
                float S = up2(s_twd[kpp].y).x;
                float cu = up2(s_twd[2*kpp].x).x;
                float su = up2(s_twd[2*kpp].y).x;
                float2 ub1 = make_float2(cu, -su);
                float2 ub2 = make_float2(cu,  su);
                bool edge = (kpp >= 1 && kpp <= 24);
#pragma unroll
                for (int m = 0; m < 2; m++){
                    int k2 = k2m[m];
                    if (k2 > 100) continue;
                    float2 X1[4], X2[4];
#pragma unroll
                    for (int q = 0; q < 4; q++){
                        float2 c = up2(aC[q][j][m]), s = up2(aS[q][j][m]);
                        X1[q] = make_float2(c.x + s.y, c.y - s.x);   // e^{-i} at kpp
                        X2[q] = make_float2(c.x - s.y, c.y + s.x);   // at 50-kpp
                    }
                    auto emit = [&](int k1o, float2 Cv){
                        int o = k1o*101 + k2;
                        if (Gt){
                            float2 g = Gt[o];
                            float2 v = make_float2(Cv.x*g.x - Cv.y*g.y,
                                                   Cv.x*g.y + Cv.y*g.x);
                            if (accum_ch){ float2 pv = gout[o]; v.x += pv.x; v.y += pv.y; }
                            gout[o] = v;
                        } else {
                            gout[o] = Cv;
                        }
                    };
                    {   // branch 1: k1' = kpp ; branch 2: k1' = 50+kpp
                        float2 t2 = cmulf(ub1, X1[2]);
                        float2 t3 = cmulf(ub1, X1[3]);
                        float2 E1 = caddf(X1[0], t2), E1m = csubf(X1[0], t2);
                        float2 O1 = caddf(X1[1], t3), O1m = csubf(X1[1], t3);
                        float2 w1 = make_float2(C, -S);
                        float2 tt = cmulf(w1, O1);
                        emit(kpp,        caddf(E1, tt));
                        emit(kpp + 100,  csubf(E1, tt));
                        float2 w2 = make_float2(-S, -C);
                        float2 uu = cmulf(w2, O1m);
                        emit(50 + kpp,   caddf(E1m, uu));
                        emit(150 + kpp,  csubf(E1m, uu));
                    }
                    if (edge){ // branch 3: k1' = 50-kpp ; branch 4: k1' = 100-kpp
                        float2 t2 = cmulf(ub2, X2[2]);
                        float2 t3 = cmulf(ub2, X2[3]);
                        float2 E2p = caddf(X2[0], t2), E2m = csubf(X2[0], t2);
                        float2 O2p = caddf(X2[1], t3), O2m = csubf(X2[1], t3);
                        float2 w3 = make_float2(S, -C);
                        float2 tt = cmulf(w3, O2m);
                        emit(50 - kpp,   caddf(E2m, tt));
                        emit(150 - kpp,  csubf(E2m, tt));
                        float2 w4 = make_float2(-C, -S);
                        float2 uu = cmulf(w4, O2p);
                        emit(100 - kpp,  caddf(E2p, uu));
                        emit(200 - kpp,  csubf(E2p, uu));
                    }
                }
            }
        }
    }
}

// rec mode: grid=4, block q handles one (b,ch) image from d_feat, raw spectrum to d_rf
__global__ void __launch_bounds__(THR, 1) k_fwd_rec(){
    extern __shared__ char sm[];
    ulonglong2* s_twd  = (ulonglong2*)sm;
    float*      s_imgT = (float*)(sm + 3200);
    u64*        s_U    = (u64*)(sm + 3200 + 40800);
    int tid = threadIdx.x, lane = tid & 31, warp = tid >> 5;
    int q = blockIdx.x;
    for (int i = tid; i < SS; i += THR) s_twd[i] = d_twd[i];
    const float* src = d_feat + q*NPIX;
    for (int i = tid; i < NPIX; i += THR){
        int yy = i / 100, xx = i - yy*100;
        s_imgT[xx*102 + yy] = src[i];
    }
    __syncthreads();
    fwd_pass(s_twd, s_imgT, s_U, d_rf + q*SPEC, 0, 0, lane, warp);
}

// lig mode: grid=NIMG, per-block rotation fused, combine with d_G into d_SF
__global__ void __launch_bounds__(THR, 1) k_fwd_lig(){
    extern __shared__ char sm[];
    ulonglong2* s_twd  = (ulonglong2*)sm;
    float*      s_imgT = (float*)(sm + 3200);
    u64*        s_U    = (u64*)(sm + 3200 + 40800);
    int tid = threadIdx.x, lane = tid & 31, warp = tid >> 5;
    int img = blockIdx.x;
    int b = img / RR, r = img % RR;
    float2 cs = d_rtrig[r];
    for (int i = tid; i < SS; i += THR) s_twd[i] = d_twd[i];
    for (int ch = 0; ch < 2; ch++){
        const float* base = d_feat + ((2 + b)*2 + ch)*NPIX;
        for (int i = tid; i < NPIX; i += THR){
            int yy = i / 100, xx = i - yy*100;
            s_imgT[xx*102 + yy] = rot_pixel(base, cs.x, cs.y, yy, xx);
        }
        __syncthreads();
        fwd_pass(s_twd, s_imgT, s_U, d_SF + img*SPEC, d_G + (b*2 + ch)*SPEC, ch,
                 lane, warp);
        __syncthreads();
    }
}

// ---------------- combine coefficients ----------------
__global__ void k_gcoef(const float* __restrict__ bW, const float* __restrict__ c1,
                        const float* __restrict__ c2, const float* __restrict__ bu){
    int idx = blockIdx.x*blockDim.x + threadIdx.x;
    if (idx >= NB*SPEC) return;
    int b = idx / SPEC, i = idx % SPEC;
    float2 rb = d_rf[(b*2 + 0)*SPEC + i];
    float2 rB = d_rf[(b*2 + 1)*SPEC + i];
    float2 crb = make_float2(rb.x, -rb.y);
    float2 crB = make_float2(rB.x, -rB.y);
    float wb = bW[0], wc1 = c1[0], wc2 = c2[0], wk = bu[0];
    d_G[(b*2 + 0)*SPEC + i] = make_float2(wb*crb.x + wc2*crB.x,  wb*crb.y + wc2*crB.y);
    d_G[(b*2 + 1)*SPEC + i] = make_float2(wc1*crb.x - wk*crB.x,  wc1*crb.y - wk*crB.y);
}

// ---------------- inverse stage 1 over k1, radix-4 + pairing ----------------
// B[y][k2] = sc * sum_k1 SF[k1][k2] e^{+2pi i k1 y/200}; rows k1 = 4u+q.
// E = G0 + u*G2, O = G1 + u*G3 (u = e^{+2pi i y/100}); B(y) = E + w^y O, B(y+100) = E - w^y O.
__device__ __forceinline__ void ifft1_l2(const u64* __restrict__ s_S,
    const ulonglong2* __restrict__ s_twd, int img, int warp, int lane, int ph){
    int ypp0 = warp * 2;                 // y'' = ypp0 + j
    int k2m[2], k2c[2];
#pragma unroll
    for (int m = 0; m < 2; m++){
        k2m[m] = ph*64 + lane + 32*m;
        k2c[m] = min(k2m[m], 100);
    }
    u64 aC[4][2][2], aS[4][2][2];
#pragma unroll
    for (int q = 0; q < 4; q++)
#pragma unroll
        for (int j = 0; j < 2; j++)
#pragma unroll
            for (int m = 0; m < 2; m++){ aC[q][j][m] = 0; aS[q][j][m] = 0; }
    int idx[2], step[2];
#pragma unroll
    for (int j = 0; j < 2; j++){ step[j] = (4*(ypp0 + j)) % 200; idx[j] = 0; }
    int off = 0;
    for (int u = 0; u < 50; u++){
        u64 D[4][2];
#pragma unroll
        for (int q = 0; q < 4; q++){
            D[q][0] = s_S[off + q*101 + k2c[0]];
            D[q][1] = s_S[off + q*101 + k2c[1]];
        }
#pragma unroll
        for (int j = 0; j < 2; j++){
            ulonglong2 w = s_twd[idx[j]];
#pragma unroll
            for (int q = 0; q < 4; q++){
                aC[q][j][0] = ffma2(D[q][0], w.x, aC[q][j][0]);
                aS[q][j][0] = ffma2(D[q][0], w.y, aS[q][j][0]);
                aC[q][j][1] = ffma2(D[q][1], w.x, aC[q][j][1]);
                aS[q][j][1] = ffma2(D[q][1], w.y, aS[q][j][1]);
            }
            idx[j] += step[j]; if (idx[j] >= 200) idx[j] -= 200;
        }
        off += 4*101;
    }
    float2* base = d_Binv + img*SPEC;
#pragma unroll
    for (int j = 0; j < 2; j++){
        int ypp = ypp0 + j;                 // 0..25
        float C = up2(s_twd[ypp].x).x;
        float S = up2(s_twd[ypp].y).x;
        float cu = up2(s_twd[2*ypp].x).x;
        float su = up2(s_twd[2*ypp].y).x;
        float2 u1 = make_float2(cu,  su);
        float2 u2 = make_float2(cu, -su);
        bool edge = (ypp >= 1 && ypp <= 24);
#pragma unroll
        for (int m = 0; m < 2; m++){
            int k2 = k2m[m];
            if (k2 > 100) continue;
            float sc = (k2 == 0 || k2 == 100) ? 2.5e-5f : 5.0e-5f;
            float2 X1[4], X2[4];
#pragma unroll
            for (int q = 0; q < 4; q++){
                float2 c = up2(aC[q][j][m]), s = up2(aS[q][j][m]);
                X1[q] = make_float2(c.x - s.y, s.x + c.y);   // e^{+i} at ypp
                X2[q] = make_float2(c.x + s.y, c.y - s.x);   // at 50-ypp
            }
            auto st = [&](int y, float2 v){
                base[y*101 + k2] = make_float2(v.x*sc, v.y*sc);
            };
            {   // y' = ypp and y' = 50+ypp
                float2 t2 = cmulf(u1, X1[2]);
                float2 t3 = cmulf(u1, X1[3]);
                float2 E1 = caddf(X1[0], t2), E1m = csubf(X1[0], t2);
                float2 O1 = caddf(X1[1], t3), O1m = csubf(X1[1], t3);
                float2 w1 = make_float2(C, S);
                float2 tt = cmulf(w1, O1);
                st(ypp,        caddf(E1, tt));
                st(ypp + 100,  csubf(E1, tt));
                float2 w2 = make_float2(-S, C);
                float2 uu = cmulf(w2, O1m);
                st(50 + ypp,   caddf(E1m, uu));
                st(150 + ypp,  csubf(E1m, uu));
            }
            if (edge){ // y' = 50-ypp and y' = 100-ypp
                float2 t2 = cmulf(u2, X2[2]);
                float2 t3 = cmulf(u2, X2[3]);
                float2 E2p = caddf(X2[0], t2), E2m = csubf(X2[0], t2);
                float2 O2p = caddf(X2[1], t3), O2m = csubf(X2[1], t3);
                float2 w3 = make_float2(S, C);
                float2 tt = cmulf(w3, O2m);
                st(50 - ypp,   caddf(E2m, tt));
                st(150 - ypp,  csubf(E2m, tt));
                float2 w4 = make_float2(-C, S);
                float2 uu = cmulf(w4, O2p);
                st(100 - ypp,  caddf(E2p, uu));
                st(200 - ypp,  csubf(E2p, uu));
            }
        }
    }
}

__global__ void __launch_bounds__(THR, 1) k_ifft1(){
    extern __shared__ char sm[];
    ulonglong2* s_twd = (ulonglong2*)sm;
    u64*        s_S   = (u64*)(sm + 3200);
    int tid = threadIdx.x, lane = tid & 31, warp = tid >> 5;
    int img = blockIdx.x;
    const u64* src = (const u64*)(d_SF + img*SPEC);
    for (int i = tid; i < SS; i += THR) s_twd[i] = d_twd[i];
    for (int i = tid; i < SPEC; i += THR) s_S[i] = src[i];
    __syncthreads();
    ifft1_l2(s_S, s_twd, img, warp, lane, 0);
    ifft1_l2(s_S, s_twd, img, warp, lane, 1);
}

// ---------------- inverse stage 2 over k2, radix-2 + x quad-pairing (R13) ----------
template<int MCNT>
__device__ __forceinline__ void ifft2r_tile(const u64* __restrict__ s_B,
    const u64* __restrict__ s_twp, const ulonglong2* __restrict__ s_twd,
    int xt, int ybase, int lane, float& lm, int r, int gtr, int ty, int tx, int b){
    int xb = xt * 4;
    int ym[MCNT], yc[MCNT]; bool vy[MCNT];
#pragma unroll
    for (int m = 0; m < MCNT; m++){
        ym[m] = ybase + lane + 32*m;
        vy[m] = ym[m] < 200;
        yc[m] = min(ym[m], 199);
    }
    u64 aE[4][MCNT], aO1[4][MCNT], aO2[4][MCNT];
#pragma unroll
    for (int j = 0; j < 4; j++)
#pragma unroll
        for (int m = 0; m < MCNT; m++){ aE[j][m]=0; aO1[j][m]=0; aO2[j][m]=0; }
    int idx[4], step[4];
#pragma unroll
    for (int j = 0; j < 4; j++){ step[j] = (2*(xb + j)) % 200; idx[j] = 0; }
    for (int mm = 0; mm < 50; mm++){
        const u64* rE = s_B + (2*mm)*200;
        const u64* rO = s_B + (2*mm + 1)*200;
        u64 BE[MCNT], BO[MCNT];
#pragma unroll
        for (int m = 0; m < MCNT; m++){ BE[m] = rE[yc[m]]; BO[m] = rO[yc[m]]; }
#pragma unroll
        for (int j = 0; j < 4; j++){
            u64 wp = s_twp[idx[j]];
            ulonglong2 wd = s_twd[idx[j]];
#pragma unroll
            for (int m = 0; m < MCNT; m++){
                aE[j][m]  = ffma2(BE[m], wp,   aE[j][m]);
                aO1[j][m] = ffma2(BO[m], wd.x, aO1[j][m]);
                aO2[j][m] = ffma2(BO[m], wd.y, aO2[j][m]);
            }
            idx[j] += step[j]; if (idx[j] >= 200) idx[j] -= 200;
        }
    }
    {
        const u64* rE = s_B + 100*200;
        u64 BE[MCNT];
#pragma unroll
        for (int m = 0; m < MCNT; m++) BE[m] = rE[yc[m]];
#pragma unroll
        for (int j = 0; j < 4; j++){
            u64 wp = s_twp[idx[j]];
#pragma unroll
            for (int m = 0; m < MCNT; m++) aE[j][m] = ffma2(BE[m], wp, aE[j][m]);
        }
    }
#pragma unroll
    for (int j = 0; j < 4; j++){
        int xp = xb + j;
        if (xp > 50) continue;
        float2 w1 = up2(s_twp[xp]);
#pragma unroll
        for (int m = 0; m < MCNT; m++){
            if (!vy[m]) continue;
            float2 ae = up2(aE[j][m]);
            float vE1 = ae.x - ae.y;
            float vE2 = ae.x + ae.y;
            float2 a1 = up2(aO1[j][m]), a2 = up2(aO2[j][m]);
            float POr = a1.x - a2.y, POi = a2.x + a1.y;
            float P2r = a1.x + a2.y, P2i = a1.y - a2.x;
            float t1 =  w1.x*POr - w1.y*POi;
            float t2 = -w1.x*P2r - w1.y*P2i;
            float v1 = vE1 + t1;
            float v2 = vE1 - t1;
            float v3 = vE2 + t2;
            float v4 = vE2 - t2;
            lm = fmaxf(lm, fmaxf(v1, v2));
            lm = fmaxf(lm, v3);
            if (xp >= 1) lm = fmaxf(lm, v4);
            if (r == gtr && ym[m] == ty){
                if (xp == tx)               d_pos[b] = v1;
                if (xp + 100 == tx)         d_pos[b] = v2;
                if (100 - xp == tx)         d_pos[b] = v3;
                if (xp >= 1 && 200 - xp == tx) d_pos[b] = v4;
            }
        }
    }
}

__global__ void __launch_bounds__(THR, 1) k_ifft2(const int* __restrict__ gt_rot,
                                                  const int* __restrict__ gt_txy){
    extern __shared__ char sm[];
    u64*        s_twp = (u64*)sm;
    ulonglong2* s_twd = (ulonglong2*)(sm + 1600);
    u64*        s_B   = (u64*)(sm + 4800);
    __shared__ float red[512];
    int tid = threadIdx.x, lane = tid & 31, warp = tid >> 5;
    int img = blockIdx.x;
    int b = img / RR, r = img % RR;
    const u64* src = (const u64*)(d_Binv + img*SPEC);
    for (int i = tid; i < SS; i += THR){ s_twp[i] = d_twp[i]; s_twd[i] = d_twd[i]; }
    for (int i = tid; i < SPEC; i += THR){
        int y = i / 101, k2 = i - y*101;
        s_B[k2*200 + y] = src[i];
    }
    __syncthreads();

    int gtr = gt_rot[b];
    int ty = gt_txy[2*b], tx = gt_txy[2*b + 1];
    float lm = -FLT_MAX;

    ifft2r_tile<4>(s_B, s_twp, s_twd, warp, 0,   lane, lm, r, gtr, ty, tx, b);
    ifft2r_tile<3>(s_B, s_twp, s_twd, warp, 128, lane, lm, r, gtr, ty, tx, b);

    red[tid] = lm;
    if (tid < 512 - THR) red[THR + tid] = -FLT_MAX;
    __syncthreads();
    for (int s = 256; s > 0; s >>= 1){
        if (tid < s) red[tid] = fmaxf(red[tid], red[tid + s]);
        __syncthreads();
    }
    if (tid == 0) d_blockmax[img] = red[0];
}

// ---------------- final reduction + loss ----------------
__global__ void k_final(float* __restrict__ out){
    __shared__ float r0[512], r1[512];
    int tid = threadIdx.x;
    float m0 = -FLT_MAX, m1 = -FLT_MAX;
    if (tid < RR){ m0 = d_blockmax[tid]; m1 = d_blockmax[RR + tid]; }
    r0[tid] = m0; r1[tid] = m1;
    __syncthreads();
    for (int s = 256; s > 0; s >>= 1){
        if (tid < s){ r0[tid] = fmaxf(r0[tid], r0[tid+s]); r1[tid] = fmaxf(r1[tid], r1[tid+s]); }
        __syncthreads();
    }
    if (tid == 0){
        float p0 = d_pos[0], p1 = d_pos[1];
        float b0 = r0[0], b1 = r1[0];
        out[0] = 0.5f * ((p0 + p0*p0) + (p1 + p1*p1));
        out[1] = 0.5f * ((-b0 + b0*b0) + (-b1 + b1*b1));
    }
}

// ---------------- launch ----------------
extern "C" void kernel_launch(void* const* d_in, const int* in_sizes, int n_in,
                              void* d_out, int out_size){
    const float* rec = (const float*)d_in[0];
    const float* lig = (const float*)d_in[1];
    const float* w1  = (const float*)d_in[2];
    const float* w2  = (const float*)d_in[3];
    const float* bW  = (const float*)d_in[4];
    const float* c1  = (const float*)d_in[5];
    const float* c2  = (const float*)d_in[6];
    const float* bu  = (const float*)d_in[7];
    const int*   gtr = (const int*)d_in[8];
    const int*   gtx = (const int*)d_in[9];
    float* out = (float*)d_out;

    const int FWD_SMEM = 3200 + 40800 + 82400;     // 126400
    const int I1_SMEM  = 3200 + SPEC*8;            // 164800
    const int I2_SMEM  = 4800 + SPEC*8;            // 166400
    cudaFuncSetAttribute(k_fwd_rec, cudaFuncAttributeMaxDynamicSharedMemorySize, FWD_SMEM);
    cudaFuncSetAttribute(k_fwd_lig, cudaFuncAttributeMaxDynamicSharedMemorySize, FWD_SMEM);
    cudaFuncSetAttribute(k_ifft1,   cudaFuncAttributeMaxDynamicSharedMemorySize, I1_SMEM);
    cudaFuncSetAttribute(k_ifft2,   cudaFuncAttributeMaxDynamicSharedMemorySize, I2_SMEM);

    k_init<<<1, 512>>>();
    k_conv1<<<(4*NPIX + 255)/256, 256>>>(rec, lig, w1);
    k_conv2<<<(4*NPIX + 255)/256, 256>>>(w2);
    k_fwd_rec<<<4, THR, FWD_SMEM>>>();
    k_gcoef<<<(NB*SPEC + 255)/256, 256>>>(bW, c1, c2, bu);
    k_fwd_lig<<<NIMG, THR, FWD_SMEM>>>();
    k_ifft1<<<NIMG, THR, I1_SMEM>>>();
    k_ifft2<<<NIMG, THR, I2_SMEM>>>(gtr, gtx);
    k_final<<<1, 512>>>(out);
}

// round 15
// speedup vs baseline: 4.0609x; 1.1974x over previous
#include <cuda_runtime.h>
#include <math.h>
#include <cfloat>

#ifndef M_PI
#define M_PI 3.14159265358979323846
#endif

typedef unsigned long long u64;

#define NPIX 10000      // 100*100
#define SIDE 100
#define SS   200
#define KH   101        // rfft half-width
#define RR   360
#define NB   2
#define NIMG (NB*RR)    // 720
#define SPEC (SS*KH)    // 20200
#define EPSF 1e-12f
#define THR  416
#define NW   13

// ---------------- static device scratch ----------------
__device__ float  d_h1[4*9*NPIX];
__device__ float  d_feat[4*2*NPIX];
__device__ float2 d_rf[4*SPEC];            // [q][k1*101 + k2]
__device__ float2 d_G[4*SPEC];             // [q][k1*101 + k2]
__device__ float2 d_SF[NIMG*SPEC];         // [img][k1*101 + k2]
__device__ float2 d_Binv[NIMG*SPEC];       // [img][y*101 + k2]
__device__ float  d_blockmax[NIMG];
__device__ float  d_pos[NB];
__device__ float2 d_rtrig[RR];
__device__ ulonglong2 d_twd[SS];           // ((c,c),(s,s)), c=cos(2pi t/200), s=sin
__device__ u64        d_twp[SS];           // (c, s)

// ---------------- packed f32x2 helpers ----------------
__device__ __forceinline__ u64 pk2(float a, float b){
    u64 r; asm("mov.b64 %0, {%1, %2};" : "=l"(r) : "f"(a), "f"(b)); return r;
}
__device__ __forceinline__ float2 up2(u64 v){
    float2 r; asm("mov.b64 {%0, %1}, %2;" : "=f"(r.x), "=f"(r.y) : "l"(v)); return r;
}
__device__ __forceinline__ u64 ffma2(u64 a, u64 b, u64 c){
    u64 d; asm("fma.rn.f32x2 %0, %1, %2, %3;" : "=l"(d) : "l"(a), "l"(b), "l"(c)); return d;
}
__device__ __forceinline__ float2 cmulf(float2 a, float2 b){
    return make_float2(a.x*b.x - a.y*b.y, a.x*b.y + a.y*b.x);
}
__device__ __forceinline__ float2 caddf(float2 a, float2 b){ return make_float2(a.x+b.x, a.y+b.y); }
__device__ __forceinline__ float2 csubf(float2 a, float2 b){ return make_float2(a.x-b.x, a.y-b.y); }

// ---------------- init tables ----------------
__global__ void k_init(){
    int t = threadIdx.x;
    if (t < SS){
        double th = 2.0 * M_PI * (double)t / 200.0;
        float c = (float)cos(th), s = (float)sin(th);
        d_twd[t] = make_ulonglong2(pk2(c, c), pk2(s, s));
        d_twp[t] = pk2(c, s);
    }
    if (t < RR){
        double th = -M_PI + (double)t * (2.0 * M_PI / 360.0);
        d_rtrig[t] = make_float2((float)cos(th), (float)sin(th));
    }
}

// ---------------- conv1 + field norm ----------------
__global__ void k_conv1(const float* __restrict__ rec, const float* __restrict__ lig,
                        const float* __restrict__ w1){
    int idx = blockIdx.x*blockDim.x + threadIdx.x;
    if (idx >= 4*NPIX) return;
    int t = idx / NPIX, p = idx % NPIX;
    int y = p / SIDE, x = p % SIDE;
    const float* src = (t < 2) ? rec + t*NPIX : lig + (t-2)*NPIX;
    float acc[9];
#pragma unroll
    for (int o = 0; o < 9; o++) acc[o] = 0.f;
    for (int dy = 0; dy < 5; dy++){
        int yy = y + dy - 2; if (yy < 0 || yy >= SIDE) continue;
        for (int dx = 0; dx < 5; dx++){
            int xx = x + dx - 2; if (xx < 0 || xx >= SIDE) continue;
            float v = src[yy*SIDE + xx];
#pragma unroll
            for (int o = 0; o < 9; o++) acc[o] = fmaf(w1[o*25 + dy*5 + dx], v, acc[o]);
        }
    }
    float out[9];
    { float n = sqrtf(acc[0]*acc[0] + EPSF); out[0] = acc[0] * (n/(n+EPSF)); }
#pragma unroll
    for (int g = 0; g < 4; g++){
        int a = 1 + 2*g;
        float n = sqrtf(acc[a]*acc[a] + acc[a+1]*acc[a+1] + EPSF);
        float s = n/(n+EPSF);
        out[a] = acc[a]*s; out[a+1] = acc[a+1]*s;
    }
#pragma unroll
    for (int o = 0; o < 9; o++) d_h1[(t*9 + o)*NPIX + p] = out[o];
}

// ---------------- conv2 + field norm + features ----------------
__global__ void k_conv2(const float* __restrict__ w2){
    int idx = blockIdx.x*blockDim.x + threadIdx.x;
    if (idx >= 4*NPIX) return;
    int t = idx / NPIX, p = idx % NPIX;
    int y = p / SIDE, x = p % SIDE;
    float h[3] = {0.f, 0.f, 0.f};
    for (int ic = 0; ic < 9; ic++){
        const float* base = d_h1 + (t*9 + ic)*NPIX;
        for (int dy = 0; dy < 5; dy++){
            int yy = y + dy - 2; if (yy < 0 || yy >= SIDE) continue;
            for (int dx = 0; dx < 5; dx++){
                int xx = x + dx - 2; if (xx < 0 || xx >= SIDE) continue;
                float v = base[yy*SIDE + xx];
#pragma unroll
                for (int oc = 0; oc < 3; oc++)
                    h[oc] = fmaf(w2[(oc*9 + ic)*25 + dy*5 + dx], v, h[oc]);
            }
        }
    }
    float n0 = sqrtf(h[0]*h[0] + EPSF);
    float o0 = h[0] * (n0/(n0+EPSF));
    float n1 = sqrtf(h[1]*h[1] + h[2]*h[2] + EPSF);
    float s  = n1/(n1+EPSF);
    float o1 = h[1]*s, o2 = h[2]*s;
    d_feat[(t*2 + 0)*NPIX + p] = fabsf(o0);
    d_feat[(t*2 + 1)*NPIX + p] = sqrtf(o1*o1 + o2*o2 + EPSF);
}

// ---------------- bilinear rotation of one pixel ----------------
__device__ __forceinline__ float rot_pixel(const float* __restrict__ base,
                                           float ct, float st, int i, int j){
    const float c = 49.5f;
    float xs = (float)j - c, ys = (float)i - c;
    float xq =  ct*xs + st*ys + c;
    float yq = -st*xs + ct*ys + c;
    float x0f = floorf(xq), y0f = floorf(yq);
    float wx = xq - x0f, wy = yq - y0f;
    int x0 = (int)x0f, y0 = (int)y0f;
    float w00 = (1.f-wy)*(1.f-wx), w01 = (1.f-wy)*wx;
    float w10 = wy*(1.f-wx),       w11 = wy*wx;
    bool vx0 = (x0 >= 0 && x0 < SIDE), vx1 = (x0+1 >= 0 && x0+1 < SIDE);
    bool vy0 = (y0 >= 0 && y0 < SIDE), vy1 = (y0+1 >= 0 && y0+1 < SIDE);
    int cx0 = min(max(x0, 0), SIDE-1),   cx1 = min(max(x0+1, 0), SIDE-1);
    int cy0 = min(max(y0, 0), SIDE-1),   cy1 = min(max(y0+1, 0), SIDE-1);
    float g00 = (vy0 && vx0) ? base[cy0*SIDE + cx0] : 0.f;
    float g01 = (vy0 && vx1) ? base[cy0*SIDE + cx1] : 0.f;
    float g10 = (vy1 && vx0) ? base[cy1*SIDE + cx0] : 0.f;
    float g11 = (vy1 && vx1) ? base[cy1*SIDE + cx1] : 0.f;
    return g00*w00 + g01*w01 + g10*w10 + g11*w11;
}

// ---------------- forward rfft2: radix-4 in BOTH stages ----------------
// s_imgT [x][y] pitch 102 -> s_U [y][k2] pitch 103 -> spectrum out.
__device__ __forceinline__ void fwd_pass(const ulonglong2* __restrict__ s_twd,
                                         const float* __restrict__ s_imgT,
                                         u64* __restrict__ s_U,
                                         float2* __restrict__ gout,
                                         const float2* __restrict__ Gt,   // null: raw store
                                         int accum_ch,                    // 0: store, 1: accumulate
                                         int lane, int warp){
    // ---- stage A: U[y][k2] = sum_x v[y][x] e^{-2pi i k2 x/200}, radix-4 over x
    // x = 4u+q; G_q period-50 sub-DFT of real rows; butterfly covers {k2',50-k2',50+k2',100-k2'}
    {
        int pc0 = min(lane, 49), pc1 = min(lane + 32, 49);
        int kpp0 = warp * 2;
        u64 aC[4][2][2], aS[4][2][2];   // [q][j][m]
#pragma unroll
        for (int q = 0; q < 4; q++)
#pragma unroll
            for (int j = 0; j < 2; j++)
#pragma unroll
                for (int m = 0; m < 2; m++){ aC[q][j][m] = 0; aS[q][j][m] = 0; }
        int idx[2], step[2];
#pragma unroll
        for (int j = 0; j < 2; j++){ step[j] = 4*(kpp0 + j); idx[j] = 0; }
        for (int u = 0; u < 25; u++){
            u64 V[4][2];
#pragma unroll
            for (int q = 0; q < 4; q++){
                const u64* rp = (const u64*)(s_imgT + (4*u + q)*102);
                V[q][0] = rp[pc0]; V[q][1] = rp[pc1];
            }
#pragma unroll
            for (int j = 0; j < 2; j++){
                ulonglong2 w = s_twd[idx[j]];
#pragma unroll
                for (int q = 0; q < 4; q++){
                    aC[q][j][0] = ffma2(V[q][0], w.x, aC[q][j][0]);
                    aS[q][j][0] = ffma2(V[q][0], w.y, aS[q][j][0]);
                    aC[q][j][1] = ffma2(V[q][1], w.x, aC[q][j][1]);
                    aS[q][j][1] = ffma2(V[q][1], w.y, aS[q][j][1]);
                }
                idx[j] += step[j]; if (idx[j] >= 200) idx[j] -= 200;
            }
        }
#pragma unroll
        for (int j = 0; j < 2; j++){
            int kpp = kpp0 + j;
            float c1 = up2(s_twd[kpp].x).x,   s1 = up2(s_twd[kpp].y).x;
            float c2 = up2(s_twd[2*kpp].x).x, s2 = up2(s_twd[2*kpp].y).x;
            float c3 = up2(s_twd[3*kpp].x).x, s3 = up2(s_twd[3*kpp].y).x;
            bool e3 = (kpp >= 1 && kpp <= 24);
            bool e4 = (kpp <= 24);
#pragma unroll
            for (int m = 0; m < 2; m++){
                int p = lane + 32*m;
                if (p >= 50) continue;
                float2 C0 = up2(aC[0][j][m]), S0 = up2(aS[0][j][m]);
                float2 C1 = up2(aC[1][j][m]), S1 = up2(aS[1][j][m]);
                float2 C2 = up2(aC[2][j][m]), S2 = up2(aS[2][j][m]);
                float2 C3 = up2(aC[3][j][m]), S3 = up2(aS[3][j][m]);
#pragma unroll
                for (int t = 0; t < 2; t++){
                    float g0c = t ? C0.y : C0.x, g0s = t ? S0.y : S0.x;
                    float g1c = t ? C1.y : C1.x, g1s = t ? S1.y : S1.x;
                    float g2c = t ? C2.y : C2.x, g2s = t ? S2.y : S2.x;
                    float g3c = t ? C3.y : C3.x, g3s = t ? S3.y : S3.x;
                    // A_q = conj(w_q) * (gqc, -gqs)
                    float A0r = g0c,                A0i = -g0s;
                    float A1r = c1*g1c - s1*g1s,    A1i = -(c1*g1s + s1*g1c);
                    float A2r = c2*g2c - s2*g2s,    A2i = -(c2*g2s + s2*g2c);
                    float A3r = c3*g3c - s3*g3s,    A3i = -(c3*g3s + s3*g3c);
                    float Pr = A0r + A2r, Pi = A0i + A2i;
                    float Mr = A0r - A2r, Mi = A0i - A2i;
                    float Qr = A1r + A3r, Qi = A1i + A3i;
                    float Rr = A1r - A3r, Ri = A1i - A3i;
                    u64* row = s_U + (2*p + t)*103;
                    row[kpp]      = pk2(Pr + Qr, Pi + Qi);           // U(kpp)
                    row[kpp + 50] = pk2(Mr + Ri, Mi - Rr);           // U(kpp+50) = M - iR
                    if (e3) row[50 - kpp]  = pk2(Mr - Ri, -(Mi + Rr));   // conj(M + iR)
                    if (e4) row[100 - kpp] = pk2(Pr - Qr, -(Pi - Qi));   // conj(P - Q)
                }
            }
        }
    }
    __syncthreads();

    // ---- stage B: C[k1][k2] = sum_y U[y][k2] e^{-2pi i k1 y/200}, radix-4 over y (R14)
    {
        int kpp0 = warp * 2;
        for (int ph = 0; ph < 2; ph++){
            int k2m[2], k2c[2];
#pragma unroll
            for (int m = 0; m < 2; m++){
                k2m[m] = ph*64 + lane + 32*m;
                k2c[m] = min(k2m[m], 100);
            }
            u64 aC[4][2][2], aS[4][2][2];
#pragma unroll
            for (int q = 0; q < 4; q++)
#pragma unroll
                for (int j = 0; j < 2; j++)
#pragma unroll
                    for (int m = 0; m < 2; m++){ aC[q][j][m] = 0; aS[q][j][m] = 0; }
            int idx[2], step[2];
#pragma unroll
            for (int j = 0; j < 2; j++){ step[j] = (4*(kpp0 + j)) % 200; idx[j] = 0; }
            int off = 0;
            for (int u = 0; u < 25; u++){
                u64 D[4][2];
#pragma unroll
                for (int q = 0; q < 4; q++){
                    D[q][0] = s_U[off + q*103 + k2c[0]];
                    D[q][1] = s_U[off + q*103 + k2c[1]];
                }
#pragma unroll
                for (int j = 0; j < 2; j++){
                    ulonglong2 w = s_twd[idx[j]];
#pragma unroll
                    for (int q = 0; q < 4; q++){
                        aC[q][j][0] = ffma2(D[q][0], w.x, aC[q][j][0]);
                        aS[q][j][0] = ffma2(D[q][0], w.y, aS[q][j][0]);
                        aC[q][j][1] = ffma2(D[q][1], w.x, aC[q][j][1]);
                        aS[q][j][1] = ffma2(D[q][1], w.y, aS[q][j][1]);
                    }
                    idx[j] += step[j]; if (idx[j] >= 200) idx[j] -= 200;
                }
                off += 4*103;
            }
#pragma unroll
            for (int j = 0; j < 2; j++){
                int kpp = kpp0 + j;                 // 0..25
                float C = up2(s_twd[kpp].x).x;
                float S = up2(s_twd[kpp].y).x;
                float cu = up2(s_twd[2*kpp].x).x;
                float su = up2(s_twd[2*kpp].y).x;
                float2 ub1 = make_float2(cu, -su);
                float2 ub2 = make_float2(cu,  su);
                bool edge = (kpp >= 1 && kpp <= 24);
#pragma unroll
                for (int m = 0; m < 2; m++){
                    int k2 = k2m[m];
                    if (k2 > 100) continue;
                    float2 X1[4], X2[4];
#pragma unroll
                    for (int q = 0; q < 4; q++){
                        float2 c = up2(aC[q][j][m]), s = up2(aS[q][j][m]);
                        X1[q] = make_float2(c.x + s.y, c.y - s.x);   // e^{-i} at kpp
                        X2[q] = make_float2(c.x - s.y, c.y + s.x);   // at 50-kpp
                    }
                    auto emit = [&](int k1o, float2 Cv){
                        int o = k1o*101 + k2;
                        if (Gt){
                            float2 g = Gt[o];
                            float2 v = make_float2(Cv.x*g.x - Cv.y*g.y,
                                                   Cv.x*g.y + Cv.y*g.x);
                            if (accum_ch){ float2 pv = gout[o]; v.x += pv.x; v.y += pv.y; }
                            gout[o] = v;
                        } else {
                            gout[o] = Cv;
                        }
                    };
                    {   // branch 1: k1' = kpp ; branch 2: k1' = 50+kpp
                        float2 t2 = cmulf(ub1, X1[2]);
                        float2 t3 = cmulf(ub1, X1[3]);
                        float2 E1 = caddf(X1[0], t2), E1m = csubf(X1[0], t2);
                        float2 O1 = caddf(X1[1], t3), O1m = csubf(X1[1], t3);
                        float2 w1 = make_float2(C, -S);
                        float2 tt = cmulf(w1, O1);
                        emit(kpp,        caddf(E1, tt));
                        emit(kpp + 100,  csubf(E1, tt));
                        float2 w2 = make_float2(-S, -C);
                        float2 uu = cmulf(w2, O1m);
                        emit(50 + kpp,   caddf(E1m, uu));
                        emit(150 + kpp,  csubf(E1m, uu));
                    }
                    if (edge){ // branch 3: k1' = 50-kpp ; branch 4: k1' = 100-kpp
                        float2 t2 = cmulf(ub2, X2[2]);
                        float2 t3 = cmulf(ub2, X2[3]);
                        float2 E2p = caddf(X2[0], t2), E2m = csubf(X2[0], t2);
                        float2 O2p = caddf(X2[1], t3), O2m = csubf(X2[1], t3);
                        float2 w3 = make_float2(S, -C);
                        float2 tt = cmulf(w3, O2m);
                        emit(50 - kpp,   caddf(E2m, tt));
                        emit(150 - kpp,  csubf(E2m, tt));
                        float2 w4 = make_float2(-C, -S);
                        float2 uu = cmulf(w4, O2p);
                        emit(100 - kpp,  caddf(E2p, uu));
                        emit(200 - kpp,  csubf(E2p, uu));
                    }
                }
            }
        }
    }
}

// rec mode: grid=4, block q handles one (b,ch) image from d_feat, raw spectrum to d_rf
__global__ void __launch_bounds__(THR, 1) k_fwd_rec(){
    extern __shared__ char sm[];
    ulonglong2* s_twd  = (ulonglong2*)sm;
    float*      s_imgT = (float*)(sm + 3200);
    u64*        s_U    = (u64*)(sm + 3200 + 40800);
    int tid = threadIdx.x, lane = tid & 31, warp = tid >> 5;
    int q = blockIdx.x;
    for (int i = tid; i < SS; i += THR) s_twd[i] = d_twd[i];
    const float* src = d_feat + q*NPIX;
    for (int i = tid; i < NPIX; i += THR){
        int yy = i / 100, xx = i - yy*100;
        s_imgT[xx*102 + yy] = src[i];
    }
    __syncthreads();
    fwd_pass(s_twd, s_imgT, s_U, d_rf + q*SPEC, 0, 0, lane, warp);
}

// lig mode: grid=NIMG, per-block rotation fused, combine with d_G into d_SF
__global__ void __launch_bounds__(THR, 1) k_fwd_lig(){
    extern __shared__ char sm[];
    ulonglong2* s_twd  = (ulonglong2*)sm;
    float*      s_imgT = (float*)(sm + 3200);
    u64*        s_U    = (u64*)(sm + 3200 + 40800);
    int tid = threadIdx.x, lane = tid & 31, warp = tid >> 5;
    int img = blockIdx.x;
    int b = img / RR, r = img % RR;
    float2 cs = d_rtrig[r];
    for (int i = tid; i < SS; i += THR) s_twd[i] = d_twd[i];
    for (int ch = 0; ch < 2; ch++){
        const float* base = d_feat + ((2 + b)*2 + ch)*NPIX;
        for (int i = tid; i < NPIX; i += THR){
            int yy = i / 100, xx = i - yy*100;
            s_imgT[xx*102 + yy] = rot_pixel(base, cs.x, cs.y, yy, xx);
        }
        __syncthreads();
        fwd_pass(s_twd, s_imgT, s_U, d_SF + img*SPEC, d_G + (b*2 + ch)*SPEC, ch,
                 lane, warp);
        __syncthreads();
    }
}

// ---------------- combine coefficients ----------------
__global__ void k_gcoef(const float* __restrict__ bW, const float* __restrict__ c1,
                        const float* __restrict__ c2, const float* __restrict__ bu){
    int idx = blockIdx.x*blockDim.x + threadIdx.x;
    if (idx >= NB*SPEC) return;
    int b = idx / SPEC, i = idx % SPEC;
    float2 rb = d_rf[(b*2 + 0)*SPEC + i];
    float2 rB = d_rf[(b*2 + 1)*SPEC + i];
    float2 crb = make_float2(rb.x, -rb.y);
    float2 crB = make_float2(rB.x, -rB.y);
    float wb = bW[0], wc1 = c1[0], wc2 = c2[0], wk = bu[0];
    d_G[(b*2 + 0)*SPEC + i] = make_float2(wb*crb.x + wc2*crB.x,  wb*crb.y + wc2*crB.y);
    d_G[(b*2 + 1)*SPEC + i] = make_float2(wc1*crb.x - wk*crB.x,  wc1*crb.y - wk*crB.y);
}

// ---------------- inverse stage 1 over k1, radix-4 + pairing (R14) ----------------
__device__ __forceinline__ void ifft1_l2(const u64* __restrict__ s_S,
    const ulonglong2* __restrict__ s_twd, int img, int warp, int lane, int ph){
    int ypp0 = warp * 2;
    int k2m[2], k2c[2];
#pragma unroll
    for (int m = 0; m < 2; m++){
        k2m[m] = ph*64 + lane + 32*m;
        k2c[m] = min(k2m[m], 100);
    }
    u64 aC[4][2][2], aS[4][2][2];
#pragma unroll
    for (int q = 0; q < 4; q++)
#pragma unroll
        for (int j = 0; j < 2; j++)
#pragma unroll
            for (int m = 0; m < 2; m++){ aC[q][j][m] = 0; aS[q][j][m] = 0; }
    int idx[2], step[2];
#pragma unroll
    for (int j = 0; j < 2; j++){ step[j] = (4*(ypp0 + j)) % 200; idx[j] = 0; }
    int off = 0;
    for (int u = 0; u < 50; u++){
        u64 D[4][2];
#pragma unroll
        for (int q = 0; q < 4; q++){
            D[q][0] = s_S[off + q*101 + k2c[0]];
            D[q][1] = s_S[off + q*101 + k2c[1]];
        }
#pragma unroll
        for (int j = 0; j < 2; j++){
            ulonglong2 w = s_twd[idx[j]];
#pragma unroll
            for (int q = 0; q < 4; q++){
                aC[q][j][0] = ffma2(D[q][0], w.x, aC[q][j][0]);
                aS[q][j][0] = ffma2(D[q][0], w.y, aS[q][j][0]);
                aC[q][j][1] = ffma2(D[q][1], w.x, aC[q][j][1]);
                aS[q][j][1] = ffma2(D[q][1], w.y, aS[q][j][1]);
            }
            idx[j] += step[j]; if (idx[j] >= 200) idx[j] -= 200;
        }
        off += 4*101;
    }
    float2* base = d_Binv + img*SPEC;
#pragma unroll
    for (int j = 0; j < 2; j++){
        int ypp = ypp0 + j;                 // 0..25
        float C = up2(s_twd[ypp].x).x;
        float S = up2(s_twd[ypp].y).x;
        float cu = up2(s_twd[2*ypp].x).x;
        float su = up2(s_twd[2*ypp].y).x;
        float2 u1 = make_float2(cu,  su);
        float2 u2 = make_float2(cu, -su);
        bool edge = (ypp >= 1 && ypp <= 24);
#pragma unroll
        for (int m = 0; m < 2; m++){
            int k2 = k2m[m];
            if (k2 > 100) continue;
            float sc = (k2 == 0 || k2 == 100) ? 2.5e-5f : 5.0e-5f;
            float2 X1[4], X2[4];
#pragma unroll
            for (int q = 0; q < 4; q++){
                float2 c = up2(aC[q][j][m]), s = up2(aS[q][j][m]);
                X1[q] = make_float2(c.x - s.y, s.x + c.y);   // e^{+i} at ypp
                X2[q] = make_float2(c.x + s.y, c.y - s.x);   // at 50-ypp
            }
            auto st = [&](int y, float2 v){
                base[y*101 + k2] = make_float2(v.x*sc, v.y*sc);
            };
            {   // y' = ypp and y' = 50+ypp
                float2 t2 = cmulf(u1, X1[2]);
                float2 t3 = cmulf(u1, X1[3]);
                float2 E1 = caddf(X1[0], t2), E1m = csubf(X1[0], t2);
                float2 O1 = caddf(X1[1], t3), O1m = csubf(X1[1], t3);
                float2 w1 = make_float2(C, S);
                float2 tt = cmulf(w1, O1);
                st(ypp,        caddf(E1, tt));
                st(ypp + 100,  csubf(E1, tt));
                float2 w2 = make_float2(-S, C);
                float2 uu = cmulf(w2, O1m);
                st(50 + ypp,   caddf(E1m, uu));
                st(150 + ypp,  csubf(E1m, uu));
            }
            if (edge){ // y' = 50-ypp and y' = 100-ypp
                float2 t2 = cmulf(u2, X2[2]);
                float2 t3 = cmulf(u2, X2[3]);
                float2 E2p = caddf(X2[0], t2), E2m = csubf(X2[0], t2);
                float2 O2p = caddf(X2[1], t3), O2m = csubf(X2[1], t3);
                float2 w3 = make_float2(S, C);
                float2 tt = cmulf(w3, O2m);
                st(50 - ypp,   caddf(E2m, tt));
                st(150 - ypp,  csubf(E2m, tt));
                float2 w4 = make_float2(-C, S);
                float2 uu = cmulf(w4, O2p);
                st(100 - ypp,  caddf(E2p, uu));
                st(200 - ypp,  csubf(E2p, uu));
            }
        }
    }
}

__global__ void __launch_bounds__(THR, 1) k_ifft1(){
    extern __shared__ char sm[];
    ulonglong2* s_twd = (ulonglong2*)sm;
    u64*        s_S   = (u64*)(sm + 3200);
    int tid = threadIdx.x, lane = tid & 31, warp = tid >> 5;
    int img = blockIdx.x;
    const u64* src = (const u64*)(d_SF + img*SPEC);
    for (int i = tid; i < SS; i += THR) s_twd[i] = d_twd[i];
    for (int i = tid; i < SPEC; i += THR) s_S[i] = src[i];
    __syncthreads();
    ifft1_l2(s_S, s_twd, img, warp, lane, 0);
    ifft1_l2(s_S, s_twd, img, warp, lane, 1);
}

// ---------------- inverse stage 2: radix-4 over k2 + x octet-pairing ----------------
// out(x) = Re(sum_k2 B[k2] w^{k2 x}), w = e^{+2pi i/200}; k2 = 4m+q, tail k2=100.
// q0 packed-real (1 ffma2); q1..3 complex (2 ffma2). Per x' in 0..25:
// 8 positions {x'+50j} and mirrors {50j-x'} from the same accumulators.
template<int MCNT>
__device__ __forceinline__ void ifft2r4_tile(const u64* __restrict__ s_B,
    const u64* __restrict__ s_twp, const ulonglong2* __restrict__ s_twd,
    int warp, int ybase, int lane, float& lm, int r, int gtr, int ty, int tx, int b){
    int xp0 = warp * 2;
    int ym[MCNT], yc[MCNT]; bool vy[MCNT];
#pragma unroll
    for (int m = 0; m < MCNT; m++){
        ym[m] = ybase + lane + 32*m;
        vy[m] = ym[m] < 200;
        yc[m] = min(ym[m], 199);
    }
    u64 aE[2][MCNT], a11[2][MCNT], a12[2][MCNT], a21[2][MCNT], a22[2][MCNT], a31[2][MCNT], a32[2][MCNT];
#pragma unroll
    for (int j = 0; j < 2; j++)
#pragma unroll
        for (int m = 0; m < MCNT; m++){
            aE[j][m]=0; a11[j][m]=0; a12[j][m]=0; a21[j][m]=0; a22[j][m]=0; a31[j][m]=0; a32[j][m]=0;
        }
    int idx[2], step[2];
#pragma unroll
    for (int j = 0; j < 2; j++){ step[j] = 4*(xp0 + j); idx[j] = 0; }
    for (int mm = 0; mm < 25; mm++){
        const u64* r0 = s_B + (4*mm    )*200;
        const u64* r1 = s_B + (4*mm + 1)*200;
        const u64* r2 = s_B + (4*mm + 2)*200;
        const u64* r3 = s_B + (4*mm + 3)*200;
        u64 B0[MCNT], B1[MCNT], B2[MCNT], B3[MCNT];
#pragma unroll
        for (int m = 0; m < MCNT; m++){
            B0[m] = r0[yc[m]]; B1[m] = r1[yc[m]];
            B2[m] = r2[yc[m]]; B3[m] = r3[yc[m]];
        }
#pragma unroll
        for (int j = 0; j < 2; j++){
            u64 wp = s_twp[idx[j]];
            ulonglong2 wd = s_twd[idx[j]];
#pragma unroll
            for (int m = 0; m < MCNT; m++){
                aE[j][m]  = ffma2(B0[m], wp,   aE[j][m]);
                a11[j][m] = ffma2(B1[m], wd.x, a11[j][m]);
                a12[j][m] = ffma2(B1[m], wd.y, a12[j][m]);
                a21[j][m] = ffma2(B2[m], wd.x, a21[j][m]);
                a22[j][m] = ffma2(B2[m], wd.y, a22[j][m]);
                a31[j][m] = ffma2(B3[m], wd.x, a31[j][m]);
                a32[j][m] = ffma2(B3[m], wd.y, a32[j][m]);
            }
            idx[j] += step[j]; if (idx[j] >= 200) idx[j] -= 200;
        }
    }
    u64 Bt[MCNT];
    {
        const u64* rt = s_B + 100*200;
#pragma unroll
        for (int m = 0; m < MCNT; m++) Bt[m] = rt[yc[m]];
    }
#pragma unroll
    for (int j = 0; j < 2; j++){
        int xp = xp0 + j;
        float2 w1 = up2(s_twp[xp]);
        float2 w2 = up2(s_twp[2*xp]);
        float2 w3 = up2(s_twp[3*xp]);
        bool mir = (xp >= 1 && xp <= 24);
#pragma unroll
        for (int m = 0; m < MCNT; m++){
            if (!vy[m]) continue;
            float2 e = up2(aE[j][m]);
            float R0p = e.x - e.y, R0m = e.x + e.y;
            float2 p11 = up2(a11[j][m]), p12 = up2(a12[j][m]);
            float S1pr = p11.x - p12.y, S1pi = p12.x + p11.y;
            float S1mr = p11.x + p12.y, S1mi = p11.y - p12.x;
            float2 p21 = up2(a21[j][m]), p22 = up2(a22[j][m]);
            float S2pr = p21.x - p22.y, S2pi = p22.x + p21.y;
            float S2mr = p21.x + p22.y, S2mi = p21.y - p22.x;
            float2 p31 = up2(a31[j][m]), p32 = up2(a32[j][m]);
            float S3pr = p31.x - p32.y, S3pi = p32.x + p31.y;
            float S3mr = p31.x + p32.y, S3mi = p31.y - p32.x;
            float V1pr = w1.x*S1pr - w1.y*S1pi, V1pi = w1.x*S1pi + w1.y*S1pr;
            float V1mr = w1.x*S1mr + w1.y*S1mi, V1mi = w1.x*S1mi - w1.y*S1mr;
            float V2pr = w2.x*S2pr - w2.y*S2pi;
            float V2mr = w2.x*S2mr + w2.y*S2mi;
            float V3pr = w3.x*S3pr - w3.y*S3pi, V3pi = w3.x*S3pi + w3.y*S3pr;
            float V3mr = w3.x*S3mr + w3.y*S3mi, V3mi = w3.x*S3mi - w3.y*S3mr;
            float tb = up2(Bt[m]).x;
            float T = (xp & 1) ? -tb : tb;
            float o0 = R0p + V2pr + V1pr + V3pr + T;      // x = xp
            float o1 = R0p - V2pr - V1pi + V3pi + T;      // xp + 50
            float o2 = R0p + V2pr - V1pr - V3pr + T;      // xp + 100
            float o3 = R0p - V2pr + V1pi - V3pi + T;      // xp + 150
            lm = fmaxf(lm, fmaxf(fmaxf(o0, o1), fmaxf(o2, o3)));
            if (r == gtr && ym[m] == ty){
                if (xp == tx)         d_pos[b] = o0;
                if (xp +  50 == tx)   d_pos[b] = o1;
                if (xp + 100 == tx)   d_pos[b] = o2;
                if (xp + 150 == tx)   d_pos[b] = o3;
            }
            if (mir){
                float u1v = R0m - V2mr - V1mi + V3mi + T;  //  50 - xp
                float u2v = R0m + V2mr - V1mr - V3mr + T;  // 100 - xp
                float u3v = R0m - V2mr + V1mi - V3mi + T;  // 150 - xp
                float u0v = R0m + V2mr + V1mr + V3mr + T;  // 200 - xp
                lm = fmaxf(lm, fmaxf(fmaxf(u0v, u1v), fmaxf(u2v, u3v)));
                if (r == gtr && ym[m] == ty){
                    if ( 50 - xp == tx) d_pos[b] = u1v;
                    if (100 - xp == tx) d_pos[b] = u2v;
                    if (150 - xp == tx) d_pos[b] = u3v;
                    if (200 - xp == tx) d_pos[b] = u0v;
                }
            }
        }
    }
}

__global__ void __launch_bounds__(THR, 1) k_ifft2(const int* __restrict__ gt_rot,
                                                  const int* __restrict__ gt_txy){
    extern __shared__ char sm[];
    u64*        s_twp = (u64*)sm;
    ulonglong2* s_twd = (ulonglong2*)(sm + 1600);
    u64*        s_B   = (u64*)(sm + 4800);
    __shared__ float red[512];
    int tid = threadIdx.x, lane = tid & 31, warp = tid >> 5;
    int img = blockIdx.x;
    int b = img / RR, r = img % RR;
    const u64* src = (const u64*)(d_Binv + img*SPEC);
    for (int i = tid; i < SS; i += THR){ s_twp[i] = d_twp[i]; s_twd[i] = d_twd[i]; }
    for (int i = tid; i < SPEC; i += THR){
        int y = i / 101, k2 = i - y*101;
        s_B[k2*200 + y] = src[i];
    }
    __syncthreads();

    int gtr = gt_rot[b];
    int ty = gt_txy[2*b], tx = gt_txy[2*b + 1];
    float lm = -FLT_MAX;

    ifft2r4_tile<2>(s_B, s_twp, s_twd, warp, 0,   lane, lm, r, gtr, ty, tx, b);
    ifft2r4_tile<2>(s_B, s_twp, s_twd, warp, 64,  lane, lm, r, gtr, ty, tx, b);
    ifft2r4_tile<2>(s_B, s_twp, s_twd, warp, 128, lane, lm, r, gtr, ty, tx, b);
    ifft2r4_tile<1>(s_B, s_twp, s_twd, warp, 192, lane, lm, r, gtr, ty, tx, b);

    red[tid] = lm;
    if (tid < 512 - THR) red[THR + tid] = -FLT_MAX;
    __syncthreads();
    for (int s = 256; s > 0; s >>= 1){
        if (tid < s) red[tid] = fmaxf(red[tid], red[tid + s]);
        __syncthreads();
    }
    if (tid == 0) d_blockmax[img] = red[0];
}

// ---------------- final reduction + loss ----------------
__global__ void k_final(float* __restrict__ out){
    __shared__ float r0[512], r1[512];
    int tid = threadIdx.x;
    float m0 = -FLT_MAX, m1 = -FLT_MAX;
    if (tid < RR){ m0 = d_blockmax[tid]; m1 = d_blockmax[RR + tid]; }
    r0[tid] = m0; r1[tid] = m1;
    __syncthreads();
    for (int s = 256; s > 0; s >>= 1){
        if (tid < s){ r0[tid] = fmaxf(r0[tid], r0[tid+s]); r1[tid] = fmaxf(r1[tid], r1[tid+s]); }
        __syncthreads();
    }
    if (tid == 0){
        float p0 = d_pos[0], p1 = d_pos[1];
        float b0 = r0[0], b1 = r1[0];
        out[0] = 0.5f * ((p0 + p0*p0) + (p1 + p1*p1));
        out[1] = 0.5f * ((-b0 + b0*b0) + (-b1 + b1*b1));
    }
}

// ---------------- launch ----------------
extern "C" void kernel_launch(void* const* d_in, const int* in_sizes, int n_in,
                              void* d_out, int out_size){
    const float* rec = (const float*)d_in[0];
    const float* lig = (const float*)d_in[1];
    const float* w1  = (const float*)d_in[2];
    const float* w2  = (const float*)d_in[3];
    const float* bW  = (const float*)d_in[4];
    const float* c1  = (const float*)d_in[5];
    const float* c2  = (const float*)d_in[6];
    const float* bu  = (const float*)d_in[7];
    const int*   gtr = (const int*)d_in[8];
    const int*   gtx = (const int*)d_in[9];
    float* out = (float*)d_out;

    const int FWD_SMEM = 3200 + 40800 + 82400;     // 126400
    const int I1_SMEM  = 3200 + SPEC*8;            // 164800
    const int I2_SMEM  = 4800 + SPEC*8;            // 166400
    cudaFuncSetAttribute(k_fwd_rec, cudaFuncAttributeMaxDynamicSharedMemorySize, FWD_SMEM);
    cudaFuncSetAttribute(k_fwd_lig, cudaFuncAttributeMaxDynamicSharedMemorySize, FWD_SMEM);
    cudaFuncSetAttribute(k_ifft1,   cudaFuncAttributeMaxDynamicSharedMemorySize, I1_SMEM);
    cudaFuncSetAttribute(k_ifft2,   cudaFuncAttributeMaxDynamicSharedMemorySize, I2_SMEM);

    k_init<<<1, 512>>>();
    k_conv1<<<(4*NPIX + 255)/256, 256>>>(rec, lig, w1);
    k_conv2<<<(4*NPIX + 255)/256, 256>>>(w2);
    k_fwd_rec<<<4, THR, FWD_SMEM>>>();
    k_gcoef<<<(NB*SPEC + 255)/256, 256>>>(bW, c1, c2, bu);
    k_fwd_lig<<<NIMG, THR, FWD_SMEM>>>();
    k_ifft1<<<NIMG, THR, I1_SMEM>>>();
    k_ifft2<<<NIMG, THR, I2_SMEM>>>(gtr, gtx);
    k_final<<<1, 512>>>(out);
}

// round 16
// speedup vs baseline: 4.2147x; 1.0379x over previous
#include <cuda_runtime.h>
#include <math.h>
#include <cfloat>

#ifndef M_PI
#define M_PI 3.14159265358979323846
#endif

typedef unsigned long long u64;

#define NPIX 10000      // 100*100
#define SIDE 100
#define SS   200
#define KH   101        // rfft half-width
#define RR   360
#define NB   2
#define NIMG (NB*RR)    // 720
#define SPEC (SS*KH)    // 20200
#define EPSF 1e-12f
#define THR  416
#define NW   13

// ---------------- static device scratch ----------------
__device__ float  d_h1[4*9*NPIX];
__device__ float  d_feat[4*2*NPIX];
__device__ float2 d_rf[4*SPEC];            // [q][k1*101 + k2]
__device__ float2 d_G[4*SPEC];             // [q][k1*101 + k2]
__device__ float2 d_SF[NIMG*SPEC];         // per-img scratch (L2-hot in fused pipe)
__device__ float2 d_Binv[NIMG*SPEC];       // per-img scratch (L2-hot in fused pipe)
__device__ float  d_blockmax[NIMG];
__device__ float  d_pos[NB];
__device__ float2 d_rtrig[RR];
__device__ ulonglong2 d_twd[SS];           // ((c,c),(s,s)), c=cos(2pi t/200), s=sin
__device__ u64        d_twp[SS];           // (c, s)

// ---------------- packed f32x2 helpers ----------------
__device__ __forceinline__ u64 pk2(float a, float b){
    u64 r; asm("mov.b64 %0, {%1, %2};" : "=l"(r) : "f"(a), "f"(b)); return r;
}
__device__ __forceinline__ float2 up2(u64 v){
    float2 r; asm("mov.b64 {%0, %1}, %2;" : "=f"(r.x), "=f"(r.y) : "l"(v)); return r;
}
__device__ __forceinline__ u64 ffma2(u64 a, u64 b, u64 c){
    u64 d; asm("fma.rn.f32x2 %0, %1, %2, %3;" : "=l"(d) : "l"(a), "l"(b), "l"(c)); return d;
}
__device__ __forceinline__ float2 cmulf(float2 a, float2 b){
    return make_float2(a.x*b.x - a.y*b.y, a.x*b.y + a.y*b.x);
}
__device__ __forceinline__ float2 caddf(float2 a, float2 b){ return make_float2(a.x+b.x, a.y+b.y); }
__device__ __forceinline__ float2 csubf(float2 a, float2 b){ return make_float2(a.x-b.x, a.y-b.y); }

// ---------------- init tables ----------------
__global__ void k_init(){
    int t = threadIdx.x;
    if (t < SS){
        double th = 2.0 * M_PI * (double)t / 200.0;
        float c = (float)cos(th), s = (float)sin(th);
        d_twd[t] = make_ulonglong2(pk2(c, c), pk2(s, s));
        d_twp[t] = pk2(c, s);
    }
    if (t < RR){
        double th = -M_PI + (double)t * (2.0 * M_PI / 360.0);
        d_rtrig[t] = make_float2((float)cos(th), (float)sin(th));
    }
}

// ---------------- conv1 + field norm ----------------
__global__ void k_conv1(const float* __restrict__ rec, const float* __restrict__ lig,
                        const float* __restrict__ w1){
    int idx = blockIdx.x*blockDim.x + threadIdx.x;
    if (idx >= 4*NPIX) return;
    int t = idx / NPIX, p = idx % NPIX;
    int y = p / SIDE, x = p % SIDE;
    const float* src = (t < 2) ? rec + t*NPIX : lig + (t-2)*NPIX;
    float acc[9];
#pragma unroll
    for (int o = 0; o < 9; o++) acc[o] = 0.f;
    for (int dy = 0; dy < 5; dy++){
        int yy = y + dy - 2; if (yy < 0 || yy >= SIDE) continue;
        for (int dx = 0; dx < 5; dx++){
            int xx = x + dx - 2; if (xx < 0 || xx >= SIDE) continue;
            float v = src[yy*SIDE + xx];
#pragma unroll
            for (int o = 0; o < 9; o++) acc[o] = fmaf(w1[o*25 + dy*5 + dx], v, acc[o]);
        }
    }
    float out[9];
    { float n = sqrtf(acc[0]*acc[0] + EPSF); out[0] = acc[0] * (n/(n+EPSF)); }
#pragma unroll
    for (int g = 0; g < 4; g++){
        int a = 1 + 2*g;
        float n = sqrtf(acc[a]*acc[a] + acc[a+1]*acc[a+1] + EPSF);
        float s = n/(n+EPSF);
        out[a] = acc[a]*s; out[a+1] = acc[a+1]*s;
    }
#pragma unroll
    for (int o = 0; o < 9; o++) d_h1[(t*9 + o)*NPIX + p] = out[o];
}

// ---------------- conv2 + field norm + features ----------------
__global__ void k_conv2(const float* __restrict__ w2){
    int idx = blockIdx.x*blockDim.x + threadIdx.x;
    if (idx >= 4*NPIX) return;
    int t = idx / NPIX, p = idx % NPIX;
    int y = p / SIDE, x = p % SIDE;
    float h[3] = {0.f, 0.f, 0.f};
    for (int ic = 0; ic < 9; ic++){
        const float* base = d_h1 + (t*9 + ic)*NPIX;
        for (int dy = 0; dy < 5; dy++){
            int yy = y + dy - 2; if (yy < 0 || yy >= SIDE) continue;
            for (int dx = 0; dx < 5; dx++){
                int xx = x + dx - 2; if (xx < 0 || xx >= SIDE) continue;
                float v = base[yy*SIDE + xx];
#pragma unroll
                for (int oc = 0; oc < 3; oc++)
                    h[oc] = fmaf(w2[(oc*9 + ic)*25 + dy*5 + dx], v, h[oc]);
            }
        }
    }
    float n0 = sqrtf(h[0]*h[0] + EPSF);
    float o0 = h[0] * (n0/(n0+EPSF));
    float n1 = sqrtf(h[1]*h[1] + h[2]*h[2] + EPSF);
    float s  = n1/(n1+EPSF);
    float o1 = h[1]*s, o2 = h[2]*s;
    d_feat[(t*2 + 0)*NPIX + p] = fabsf(o0);
    d_feat[(t*2 + 1)*NPIX + p] = sqrtf(o1*o1 + o2*o2 + EPSF);
}

// ---------------- bilinear rotation of one pixel ----------------
__device__ __forceinline__ float rot_pixel(const float* __restrict__ base,
                                           float ct, float st, int i, int j){
    const float c = 49.5f;
    float xs = (float)j - c, ys = (float)i - c;
    float xq =  ct*xs + st*ys + c;
    float yq = -st*xs + ct*ys + c;
    float x0f = floorf(xq), y0f = floorf(yq);
    float wx = xq - x0f, wy = yq - y0f;
    int x0 = (int)x0f, y0 = (int)y0f;
    float w00 = (1.f-wy)*(1.f-wx), w01 = (1.f-wy)*wx;
    float w10 = wy*(1.f-wx),       w11 = wy*wx;
    bool vx0 = (x0 >= 0 && x0 < SIDE), vx1 = (x0+1 >= 0 && x0+1 < SIDE);
    bool vy0 = (y0 >= 0 && y0 < SIDE), vy1 = (y0+1 >= 0 && y0+1 < SIDE);
    int cx0 = min(max(x0, 0), SIDE-1),   cx1 = min(max(x0+1, 0), SIDE-1);
    int cy0 = min(max(y0, 0), SIDE-1),   cy1 = min(max(y0+1, 0), SIDE-1);
    float g00 = (vy0 && vx0) ? base[cy0*SIDE + cx0] : 0.f;
    float g01 = (vy0 && vx1) ? base[cy0*SIDE + cx1] : 0.f;
    float g10 = (vy1 && vx0) ? base[cy1*SIDE + cx0] : 0.f;
    float g11 = (vy1 && vx1) ? base[cy1*SIDE + cx1] : 0.f;
    return g00*w00 + g01*w01 + g10*w10 + g11*w11;
}

// ---------------- forward rfft2: radix-4 in BOTH stages (verbatim R15) ----------------
__device__ __forceinline__ void fwd_pass(const ulonglong2* __restrict__ s_twd,
                                         const float* __restrict__ s_imgT,
                                         u64* __restrict__ s_U,
                                         float2* __restrict__ gout,
                                         const float2* __restrict__ Gt,   // null: raw store
                                         int accum_ch,                    // 0: store, 1: accumulate
                                         int lane, int warp){
    // ---- stage A: radix-4 over x
    {
        int pc0 = min(lane, 49), pc1 = min(lane + 32, 49);
        int kpp0 = warp * 2;
        u64 aC[4][2][2], aS[4][2][2];   // [q][j][m]
#pragma unroll
        for (int q = 0; q < 4; q++)
#pragma unroll
            for (int j = 0; j < 2; j++)
#pragma unroll
                for (int m = 0; m < 2; m++){ aC[q][j][m] = 0; aS[q][j][m] = 0; }
        int idx[2], step[2];
#pragma unroll
        for (int j = 0; j < 2; j++){ step[j] = 4*(kpp0 + j); idx[j] = 0; }
        for (int u = 0; u < 25; u++){
            u64 V[4][2];
#pragma unroll
            for (int q = 0; q < 4; q++){
                const u64* rp = (const u64*)(s_imgT + (4*u + q)*102);
                V[q][0] = rp[pc0]; V[q][1] = rp[pc1];
            }
#pragma unroll
            for (int j = 0; j < 2; j++){
                ulonglong2 w = s_twd[idx[j]];
#pragma unroll
                for (int q = 0; q < 4; q++){
                    aC[q][j][0] = ffma2(V[q][0], w.x, aC[q][j][0]);
                    aS[q][j][0] = ffma2(V[q][0], w.y, aS[q][j][0]);
                    aC[q][j][1] = ffma2(V[q][1], w.x, aC[q][j][1]);
                    aS[q][j][1] = ffma2(V[q][1], w.y, aS[q][j][1]);
                }
                idx[j] += step[j]; if (idx[j] >= 200) idx[j] -= 200;
            }
        }
#pragma unroll
        for (int j = 0; j < 2; j++){
            int kpp = kpp0 + j;
            float c1 = up2(s_twd[kpp].x).x,   s1 = up2(s_twd[kpp].y).x;
            float c2 = up2(s_twd[2*kpp].x).x, s2 = up2(s_twd[2*kpp].y).x;
            float c3 = up2(s_twd[3*kpp].x).x, s3 = up2(s_twd[3*kpp].y).x;
            bool e3 = (kpp >= 1 && kpp <= 24);
            bool e4 = (kpp <= 24);
#pragma unroll
            for (int m = 0; m < 2; m++){
                int p = lane + 32*m;
                if (p >= 50) continue;
                float2 C0 = up2(aC[0][j][m]), S0 = up2(aS[0][j][m]);
                float2 C1 = up2(aC[1][j][m]), S1 = up2(aS[1][j][m]);
                float2 C2 = up2(aC[2][j][m]), S2 = up2(aS[2][j][m]);
                float2 C3 = up2(aC[3][j][m]), S3 = up2(aS[3][j][m]);
#pragma unroll
                for (int t = 0; t < 2; t++){
                    float g0c = t ? C0.y : C0.x, g0s = t ? S0.y : S0.x;
                    float g1c = t ? C1.y : C1.x, g1s = t ? S1.y : S1.x;
                    float g2c = t ? C2.y : C2.x, g2s = t ? S2.y : S2.x;
                    float g3c = t ? C3.y : C3.x, g3s = t ? S3.y : S3.x;
                    float A0r = g0c,                A0i = -g0s;
                    float A1r = c1*g1c - s1*g1s,    A1i = -(c1*g1s + s1*g1c);
                    float A2r = c2*g2c - s2*g2s,    A2i = -(c2*g2s + s2*g2c);
                    float A3r = c3*g3c - s3*g3s,    A3i = -(c3*g3s + s3*g3c);
                    float Pr = A0r + A2r, Pi = A0i + A2i;
                    float Mr = A0r - A2r, Mi = A0i - A2i;
                    float Qr = A1r + A3r, Qi = A1i + A3i;
                    float Rr = A1r - A3r, Ri = A1i - A3i;
                    u64* row = s_U + (2*p + t)*103;
                    row[kpp]      = pk2(Pr + Qr, Pi + Qi);
                    row[kpp + 50] = pk2(Mr + Ri, Mi - Rr);
                    if (e3) row[50 - kpp]  = pk2(Mr - Ri, -(Mi + Rr));
                    if (e4) row[100 - kpp] = pk2(Pr - Qr, -(Pi - Qi));
                }
            }
        }
    }
    __syncthreads();

    // ---- stage B: radix-4 over y
    {
        int kpp0 = warp * 2;
        for (int ph = 0; ph < 2; ph++){
            int k2m[2], k2c[2];
#pragma unroll
            for (int m = 0; m < 2; m++){
                k2m[m] = ph*64 + lane + 32*m;
                k2c[m] = min(k2m[m], 100);
            }
            u64 aC[4][2][2], aS[4][2][2];
#pragma unroll
            for (int q = 0; q < 4; q++)
#pragma unroll
                for (int j = 0; j < 2; j++)
#pragma unroll
                    for (int m = 0; m < 2; m++){ aC[q][j][m] = 0; aS[q][j][m] = 0; }
            int idx[2], step[2];
#pragma unroll
            for (int j = 0; j < 2; j++){ step[j] = (4*(kpp0 + j)) % 200; idx[j] = 0; }
            int off = 0;
            for (int u = 0; u < 25; u++){
                u64 D[4][2];
#pragma unroll
                for (int q = 0; q < 4; q++){
                    D[q][0] = s_U[off + q*103 + k2c[0]];
                    D[q][1] = s_U[off + q*103 + k2c[1]];
                }
#pragma unroll
                for (int j = 0; j < 2; j++){
                    ulonglong2 w = s_twd[idx[j]];
#pragma unroll
                    for (int q = 0; q < 4; q++){
                        aC[q][j][0] = ffma2(D[q][0], w.x, aC[q][j][0]);
                        aS[q][j][0] = ffma2(D[q][0], w.y, aS[q][j][0]);
                        aC[q][j][1] = ffma2(D[q][1], w.x, aC[q][j][1]);
                        aS[q][j][1] = ffma2(D[q][1], w.y, aS[q][j][1]);
                    }
                    idx[j] += step[j]; if (idx[j] >= 200) idx[j] -= 200;
                }
                off += 4*103;
            }
#pragma unroll
            for (int j = 0; j < 2; j++){
                int kpp = kpp0 + j;                 // 0..25
                float C = up2(s_twd[kpp].x).x;
                float S = up2(s_twd[kpp].y).x;
                float cu = up2(s_twd[2*kpp].x).x;
                float su = up2(s_twd[2*kpp].y).x;
                float2 ub1 = make_float2(cu, -su);
                float2 ub2 = make_float2(cu,  su);
                bool edge = (kpp >= 1 && kpp <= 24);
#pragma unroll
                for (int m = 0; m < 2; m++){
                    int k2 = k2m[m];
                    if (k2 > 100) continue;
                    float2 X1[4], X2[4];
#pragma unroll
                    for (int q = 0; q < 4; q++){
                        float2 c = up2(aC[q][j][m]), s = up2(aS[q][j][m]);
                        X1[q] = make_float2(c.x + s.y, c.y - s.x);
                        X2[q] = make_float2(c.x - s.y, c.y + s.x);
                    }
                    auto emit = [&](int k1o, float2 Cv){
                        int o = k1o*101 + k2;
                        if (Gt){
                            float2 g = Gt[o];
                            float2 v = make_float2(Cv.x*g.x - Cv.y*g.y,
                                                   Cv.x*g.y + Cv.y*g.x);
                            if (accum_ch){ float2 pv = gout[o]; v.x += pv.x; v.y += pv.y; }
                            gout[o] = v;
                        } else {
                            gout[o] = Cv;
                        }
                    };
                    {
                        float2 t2 = cmulf(ub1, X1[2]);
                        float2 t3 = cmulf(ub1, X1[3]);
                        float2 E1 = caddf(X1[0], t2), E1m = csubf(X1[0], t2);
                        float2 O1 = caddf(X1[1], t3), O1m = csubf(X1[1], t3);
                        float2 w1 = make_float2(C, -S);
                        float2 tt = cmulf(w1, O1);
                        emit(kpp,        caddf(E1, tt));
                        emit(kpp + 100,  csubf(E1, tt));
                        float2 w2 = make_float2(-S, -C);
                        float2 uu = cmulf(w2, O1m);
                        emit(50 + kpp,   caddf(E1m, uu));
                        emit(150 + kpp,  csubf(E1m, uu));
                    }
                    if (edge){
                        float2 t2 = cmulf(ub2, X2[2]);
                        float2 t3 = cmulf(ub2, X2[3]);
                        float2 E2p = caddf(X2[0], t2), E2m = csubf(X2[0], t2);
                        float2 O2p = caddf(X2[1], t3), O2m = csubf(X2[1], t3);
                        float2 w3 = make_float2(S, -C);
                        float2 tt = cmulf(w3, O2m);
                        emit(50 - kpp,   caddf(E2m, tt));
                        emit(150 - kpp,  csubf(E2m, tt));
                        float2 w4 = make_float2(-C, -S);
                        float2 uu = cmulf(w4, O2p);
                        emit(100 - kpp,  caddf(E2p, uu));
                        emit(200 - kpp,  csubf(E2p, uu));
                    }
                }
            }
        }
    }
}

// ---------------- inverse stage 1 over k1, radix-4 + pairing (verbatim R15) ----------------
__device__ __forceinline__ void ifft1_l2(const u64* __restrict__ s_S,
    const ulonglong2* __restrict__ s_twd, int img, int warp, int lane, int ph){
    int ypp0 = warp * 2;
    int k2m[2], k2c[2];
#pragma unroll
    for (int m = 0; m < 2; m++){
        k2m[m] = ph*64 + lane + 32*m;
        k2c[m] = min(k2m[m], 100);
    }
    u64 aC[4][2][2], aS[4][2][2];
#pragma unroll
    for (int q = 0; q < 4; q++)
#pragma unroll
        for (int j = 0; j < 2; j++)
#pragma unroll
            for (int m = 0; m < 2; m++){ aC[q][j][m] = 0; aS[q][j][m] = 0; }
    int idx[2], step[2];
#pragma unroll
    for (int j = 0; j < 2; j++){ step[j] = (4*(ypp0 + j)) % 200; idx[j] = 0; }
    int off = 0;
    for (int u = 0; u < 50; u++){
        u64 D[4][2];
#pragma unroll
        for (int q = 0; q < 4; q++){
            D[q][0] = s_S[off + q*101 + k2c[0]];
            D[q][1] = s_S[off + q*101 + k2c[1]];
        }
#pragma unroll
        for (int j = 0; j < 2; j++){
            ulonglong2 w = s_twd[idx[j]];
#pragma unroll
            for (int q = 0; q < 4; q++){
                aC[q][j][0] = ffma2(D[q][0], w.x, aC[q][j][0]);
                aS[q][j][0] = ffma2(D[q][0], w.y, aS[q][j][0]);
                aC[q][j][1] = ffma2(D[q][1], w.x, aC[q][j][1]);
                aS[q][j][1] = ffma2(D[q][1], w.y, aS[q][j][1]);
            }
            idx[j] += step[j]; if (idx[j] >= 200) idx[j] -= 200;
        }
        off += 4*101;
    }
    float2* base = d_Binv + img*SPEC;
#pragma unroll
    for (int j = 0; j < 2; j++){
        int ypp = ypp0 + j;                 // 0..25
        float C = up2(s_twd[ypp].x).x;
        float S = up2(s_twd[ypp].y).x;
        float cu = up2(s_twd[2*ypp].x).x;
        float su = up2(s_twd[2*ypp].y).x;
        float2 u1 = make_float2(cu,  su);
        float2 u2 = make_float2(cu, -su);
        bool edge = (ypp >= 1 && ypp <= 24);
#pragma unroll
        for (int m = 0; m < 2; m++){
            int k2 = k2m[m];
            if (k2 > 100) continue;
            float sc = (k2 == 0 || k2 == 100) ? 2.5e-5f : 5.0e-5f;
            float2 X1[4], X2[4];
#pragma unroll
            for (int q = 0; q < 4; q++){
                float2 c = up2(aC[q][j][m]), s = up2(aS[q][j][m]);
                X1[q] = make_float2(c.x - s.y, s.x + c.y);
                X2[q] = make_float2(c.x + s.y, c.y - s.x);
            }
            auto st = [&](int y, float2 v){
                base[y*101 + k2] = make_float2(v.x*sc, v.y*sc);
            };
            {
                float2 t2 = cmulf(u1, X1[2]);
                float2 t3 = cmulf(u1, X1[3]);
                float2 E1 = caddf(X1[0], t2), E1m = csubf(X1[0], t2);
                float2 O1 = caddf(X1[1], t3), O1m = csubf(X1[1], t3);
                float2 w1 = make_float2(C, S);
                float2 tt = cmulf(w1, O1);
                st(ypp,        caddf(E1, tt));
                st(ypp + 100,  csubf(E1, tt));
                float2 w2 = make_float2(-S, C);
                float2 uu = cmulf(w2, O1m);
                st(50 + ypp,   caddf(E1m, uu));
                st(150 + ypp,  csubf(E1m, uu));
            }
            if (edge){
                float2 t2 = cmulf(u2, X2[2]);
                float2 t3 = cmulf(u2, X2[3]);
                float2 E2p = caddf(X2[0], t2), E2m = csubf(X2[0], t2);
                float2 O2p = caddf(X2[1], t3), O2m = csubf(X2[1], t3);
                float2 w3 = make_float2(S, C);
                float2 tt = cmulf(w3, O2m);
                st(50 - ypp,   caddf(E2m, tt));
                st(150 - ypp,  csubf(E2m, tt));
                float2 w4 = make_float2(-C, S);
                float2 uu = cmulf(w4, O2p);
                st(100 - ypp,  caddf(E2p, uu));
                st(200 - ypp,  csubf(E2p, uu));
            }
        }
    }
}

// ---------------- inverse stage 2: radix-4 over k2 + x octet-pairing (verbatim R15) ----------
template<int MCNT>
__device__ __forceinline__ void ifft2r4_tile(const u64* __restrict__ s_B,
    const u64* __restrict__ s_twp, const ulonglong2* __restrict__ s_twd,
    int warp, int ybase, int lane, float& lm, int r, int gtr, int ty, int tx, int b){
    int xp0 = warp * 2;
    int ym[MCNT], yc[MCNT]; bool vy[MCNT];
#pragma unroll
    for (int m = 0; m < MCNT; m++){
        ym[m] = ybase + lane + 32*m;
        vy[m] = ym[m] < 200;
        yc[m] = min(ym[m], 199);
    }
    u64 aE[2][MCNT], a11[2][MCNT], a12[2][MCNT], a21[2][MCNT], a22[2][MCNT], a31[2][MCNT], a32[2][MCNT];
#pragma unroll
    for (int j = 0; j < 2; j++)
#pragma unroll
        for (int m = 0; m < MCNT; m++){
            aE[j][m]=0; a11[j][m]=0; a12[j][m]=0; a21[j][m]=0; a22[j][m]=0; a31[j][m]=0; a32[j][m]=0;
        }
    int idx[2], step[2];
#pragma unroll
    for (int j = 0; j < 2; j++){ step[j] = 4*(xp0 + j); idx[j] = 0; }
    for (int mm = 0; mm < 25; mm++){
        const u64* r0 = s_B + (4*mm    )*200;
        const u64* r1 = s_B + (4*mm + 1)*200;
        const u64* r2 = s_B + (4*mm + 2)*200;
        const u64* r3 = s_B + (4*mm + 3)*200;
        u64 B0[MCNT], B1[MCNT], B2[MCNT], B3[MCNT];
#pragma unroll
        for (int m = 0; m < MCNT; m++){
            B0[m] = r0[yc[m]]; B1[m] = r1[yc[m]];
            B2[m] = r2[yc[m]]; B3[m] = r3[yc[m]];
        }
#pragma unroll
        for (int j = 0; j < 2; j++){
            u64 wp = s_twp[idx[j]];
            ulonglong2 wd = s_twd[idx[j]];
#pragma unroll
            for (int m = 0; m < MCNT; m++){
                aE[j][m]  = ffma2(B0[m], wp,   aE[j][m]);
                a11[j][m] = ffma2(B1[m], wd.x, a11[j][m]);
                a12[j][m] = ffma2(B1[m], wd.y, a12[j][m]);
                a21[j][m] = ffma2(B2[m], wd.x, a21[j][m]);
                a22[j][m] = ffma2(B2[m], wd.y, a22[j][m]);
                a31[j][m] = ffma2(B3[m], wd.x, a31[j][m]);
                a32[j][m] = ffma2(B3[m], wd.y, a32[j][m]);
            }
            idx[j] += step[j]; if (idx[j] >= 200) idx[j] -= 200;
        }
    }
    u64 Bt[MCNT];
    {
        const u64* rt = s_B + 100*200;
#pragma unroll
        for (int m = 0; m < MCNT; m++) Bt[m] = rt[yc[m]];
    }
#pragma unroll
    for (int j = 0; j < 2; j++){
        int xp = xp0 + j;
        float2 w1 = up2(s_twp[xp]);
        float2 w2 = up2(s_twp[2*xp]);
        float2 w3 = up2(s_twp[3*xp]);
        bool mir = (xp >= 1 && xp <= 24);
#pragma unroll
        for (int m = 0; m < MCNT; m++){
            if (!vy[m]) continue;
            float2 e = up2(aE[j][m]);
            float R0p = e.x - e.y, R0m = e.x + e.y;
            float2 p11 = up2(a11[j][m]), p12 = up2(a12[j][m]);
            float S1pr = p11.x - p12.y, S1pi = p12.x + p11.y;
            float S1mr = p11.x + p12.y, S1mi = p11.y - p12.x;
            float2 p21 = up2(a21[j][m]), p22 = up2(a22[j][m]);
            float S2pr = p21.x - p22.y, S2pi = p22.x + p21.y;
            float S2mr = p21.x + p22.y, S2mi = p21.y - p22.x;
            float2 p31 = up2(a31[j][m]), p32 = up2(a32[j][m]);
            float S3pr = p31.x - p32.y, S3pi = p32.x + p31.y;
            float S3mr = p31.x + p32.y, S3mi = p31.y - p32.x;
            float V1pr = w1.x*S1pr - w1.y*S1pi, V1pi = w1.x*S1pi + w1.y*S1pr;
            float V1mr = w1.x*S1mr + w1.y*S1mi, V1mi = w1.x*S1mi - w1.y*S1mr;
            float V2pr = w2.x*S2pr - w2.y*S2pi;
            float V2mr = w2.x*S2mr + w2.y*S2mi;
            float V3pr = w3.x*S3pr - w3.y*S3pi, V3pi = w3.x*S3pi + w3.y*S3pr;
            float V3mr = w3.x*S3mr + w3.y*S3mi, V3mi = w3.x*S3mi - w3.y*S3mr;
            float tb = up2(Bt[m]).x;
            float T = (xp & 1) ? -tb : tb;
            float o0 = R0p + V2pr + V1pr + V3pr + T;
            float o1 = R0p - V2pr - V1pi + V3pi + T;
            float o2 = R0p + V2pr - V1pr - V3pr + T;
            float o3 = R0p - V2pr + V1pi - V3pi + T;
            lm = fmaxf(lm, fmaxf(fmaxf(o0, o1), fmaxf(o2, o3)));
            if (r == gtr && ym[m] == ty){
                if (xp == tx)         d_pos[b] = o0;
                if (xp +  50 == tx)   d_pos[b] = o1;
                if (xp + 100 == tx)   d_pos[b] = o2;
                if (xp + 150 == tx)   d_pos[b] = o3;
            }
            if (mir){
                float u1v = R0m - V2mr - V1mi + V3mi + T;
                float u2v = R0m + V2mr - V1mr - V3mr + T;
                float u3v = R0m - V2mr + V1mi - V3mi + T;
                float u0v = R0m + V2mr + V1mr + V3mr + T;
                lm = fmaxf(lm, fmaxf(fmaxf(u0v, u1v), fmaxf(u2v, u3v)));
                if (r == gtr && ym[m] == ty){
                    if ( 50 - xp == tx) d_pos[b] = u1v;
                    if (100 - xp == tx) d_pos[b] = u2v;
                    if (150 - xp == tx) d_pos[b] = u3v;
                    if (200 - xp == tx) d_pos[b] = u0v;
                }
            }
        }
    }
}

// ---------------- rec forward: grid=4, raw spectrum to d_rf ----------------
__global__ void __launch_bounds__(THR, 1) k_fwd_rec(){
    extern __shared__ char sm[];
    ulonglong2* s_twd  = (ulonglong2*)sm;
    float*      s_imgT = (float*)(sm + 3200);
    u64*        s_U    = (u64*)(sm + 3200 + 40800);
    int tid = threadIdx.x, lane = tid & 31, warp = tid >> 5;
    int q = blockIdx.x;
    for (int i = tid; i < SS; i += THR) s_twd[i] = d_twd[i];
    const float* src = d_feat + q*NPIX;
    for (int i = tid; i < NPIX; i += THR){
        int yy = i / 100, xx = i - yy*100;
        s_imgT[xx*102 + yy] = src[i];
    }
    __syncthreads();
    fwd_pass(s_twd, s_imgT, s_U, d_rf + q*SPEC, 0, 0, lane, warp);
}

// ---------------- combine coefficients ----------------
__global__ void k_gcoef(const float* __restrict__ bW, const float* __restrict__ c1,
                        const float* __restrict__ c2, const float* __restrict__ bu){
    int idx = blockIdx.x*blockDim.x + threadIdx.x;
    if (idx >= NB*SPEC) return;
    int b = idx / SPEC, i = idx % SPEC;
    float2 rb = d_rf[(b*2 + 0)*SPEC + i];
    float2 rB = d_rf[(b*2 + 1)*SPEC + i];
    float2 crb = make_float2(rb.x, -rb.y);
    float2 crB = make_float2(rB.x, -rB.y);
    float wb = bW[0], wc1 = c1[0], wc2 = c2[0], wk = bu[0];
    d_G[(b*2 + 0)*SPEC + i] = make_float2(wb*crb.x + wc2*crB.x,  wb*crb.y + wc2*crB.y);
    d_G[(b*2 + 1)*SPEC + i] = make_float2(wc1*crb.x - wk*crB.x,  wc1*crb.y - wk*crB.y);
}

// ---------------- FUSED pipeline: rotation+fwd -> ifft1 -> ifft2+max+gather ----------------
// One block per (b, r) image. d_SF / d_Binv become block-private L2-hot scratch.
// smem overlay: [0,3200) twd | [3200,4800) twp | [4800,166400) big region
//   fwd:   imgT@4800 (40800) + s_U@45600 (82400)
//   ifft1: s_S@4800 (161600)   (overwrites imgT/s_U after sync)
//   ifft2: s_B@4800 (161600)   (overwrites s_S after sync)
__global__ void __launch_bounds__(THR, 1) k_pipe(const int* __restrict__ gt_rot,
                                                 const int* __restrict__ gt_txy){
    extern __shared__ char sm[];
    ulonglong2* s_twd  = (ulonglong2*)sm;
    u64*        s_twp  = (u64*)(sm + 3200);
    float*      s_imgT = (float*)(sm + 4800);
    u64*        s_U    = (u64*)(sm + 45600);
    u64*        s_S    = (u64*)(sm + 4800);
    u64*        s_B    = (u64*)(sm + 4800);
    __shared__ float red[512];
    int tid = threadIdx.x, lane = tid & 31, warp = tid >> 5;
    int img = blockIdx.x;
    int b = img / RR, r = img % RR;
    float2 cs = d_rtrig[r];
    for (int i = tid; i < SS; i += THR){ s_twd[i] = d_twd[i]; s_twp[i] = d_twp[i]; }

    // ---- forward rfft2 (rotation fused), both channels, combine into d_SF
    for (int ch = 0; ch < 2; ch++){
        const float* base = d_feat + ((2 + b)*2 + ch)*NPIX;
        for (int i = tid; i < NPIX; i += THR){
            int yy = i / 100, xx = i - yy*100;
            s_imgT[xx*102 + yy] = rot_pixel(base, cs.x, cs.y, yy, xx);
        }
        __syncthreads();
        fwd_pass(s_twd, s_imgT, s_U, d_SF + img*SPEC, d_G + (b*2 + ch)*SPEC, ch,
                 lane, warp);
        __syncthreads();
    }

    // ---- inverse stage 1 (SF -> Binv), SF now L2-hot (written by this block)
    {
        const u64* src = (const u64*)(d_SF + img*SPEC);
        for (int i = tid; i < SPEC; i += THR) s_S[i] = src[i];
        __syncthreads();
        ifft1_l2(s_S, s_twd, img, warp, lane, 0);
        ifft1_l2(s_S, s_twd, img, warp, lane, 1);
    }
    __syncthreads();

    // ---- inverse stage 2 + max-reduce + gather
    {
        const u64* src = (const u64*)(d_Binv + img*SPEC);
        for (int i = tid; i < SPEC; i += THR){
            int y = i / 101, k2 = i - y*101;
            s_B[k2*200 + y] = src[i];
        }
        __syncthreads();

        int gtr = gt_rot[b];
        int ty = gt_txy[2*b], tx = gt_txy[2*b + 1];
        float lm = -FLT_MAX;

        ifft2r4_tile<2>(s_B, s_twp, s_twd, warp, 0,   lane, lm, r, gtr, ty, tx, b);
        ifft2r4_tile<2>(s_B, s_twp, s_twd, warp, 64,  lane, lm, r, gtr, ty, tx, b);
        ifft2r4_tile<2>(s_B, s_twp, s_twd, warp, 128, lane, lm, r, gtr, ty, tx, b);
        ifft2r4_tile<1>(s_B, s_twp, s_twd, warp, 192, lane, lm, r, gtr, ty, tx, b);

        red[tid] = lm;
        if (tid < 512 - THR) red[THR + tid] = -FLT_MAX;
        __syncthreads();
        for (int s = 256; s > 0; s >>= 1){
            if (tid < s) red[tid] = fmaxf(red[tid], red[tid + s]);
            __syncthreads();
        }
        if (tid == 0) d_blockmax[img] = red[0];
    }
}

// ---------------- final reduction + loss ----------------
__global__ void k_final(float* __restrict__ out){
    __shared__ float r0[512], r1[512];
    int tid = threadIdx.x;
    float m0 = -FLT_MAX, m1 = -FLT_MAX;
    if (tid < RR){ m0 = d_blockmax[tid]; m1 = d_blockmax[RR + tid]; }
    r0[tid] = m0; r1[tid] = m1;
    __syncthreads();
    for (int s = 256; s > 0; s >>= 1){
        if (tid < s){ r0[tid] = fmaxf(r0[tid], r0[tid+s]); r1[tid] = fmaxf(r1[tid], r1[tid+s]); }
        __syncthreads();
    }
    if (tid == 0){
        float p0 = d_pos[0], p1 = d_pos[1];
        float b0 = r0[0], b1 = r1[0];
        out[0] = 0.5f * ((p0 + p0*p0) + (p1 + p1*p1));
        out[1] = 0.5f * ((-b0 + b0*b0) + (-b1 + b1*b1));
    }
}

// ---------------- launch ----------------
extern "C" void kernel_launch(void* const* d_in, const int* in_sizes, int n_in,
                              void* d_out, int out_size){
    const float* rec = (const float*)d_in[0];
    const float* lig = (const float*)d_in[1];
    const float* w1  = (const float*)d_in[2];
    const float* w2  = (const float*)d_in[3];
    const float* bW  = (const float*)d_in[4];
    const float* c1  = (const float*)d_in[5];
    const float* c2  = (const float*)d_in[6];
    const float* bu  = (const float*)d_in[7];
    const int*   gtr = (const int*)d_in[8];
    const int*   gtx = (const int*)d_in[9];
    float* out = (float*)d_out;

    const int REC_SMEM  = 3200 + 40800 + 82400;    // 126400
    const int PIPE_SMEM = 4800 + SPEC*8;           // 166400
    cudaFuncSetAttribute(k_fwd_rec, cudaFuncAttributeMaxDynamicSharedMemorySize, REC_SMEM);
    cudaFuncSetAttribute(k_pipe,    cudaFuncAttributeMaxDynamicSharedMemorySize, PIPE_SMEM);

    k_init<<<1, 512>>>();
    k_conv1<<<(4*NPIX + 255)/256, 256>>>(rec, lig, w1);
    k_conv2<<<(4*NPIX + 255)/256, 256>>>(w2);
    k_fwd_rec<<<4, THR, REC_SMEM>>>();
    k_gcoef<<<(NB*SPEC + 255)/256, 256>>>(bW, c1, c2, bu);
    k_pipe<<<NIMG, THR, PIPE_SMEM>>>(gtr, gtx);
    k_final<<<1, 512>>>(out);
}